// round 11
// baseline (speedup 1.0000x reference)
#include <cuda_runtime.h>
#include <cuda_fp16.h>
#include <math.h>
#include <stdint.h>

#define CF   1984
#define NB   8
#define NN   1024    // h*w = 32*32
#define NCLS 1000

// ---------------- scratch (static device globals; no allocation) ----------------
__device__ __half g_tn_hi[NB * NN * CF];
__device__ __half g_tn_lo[NB * NN * CF];
__device__ __half g_rn_hi[NB * NN * CF];
__device__ __half g_A_hi[NB * NN * NN];
__device__ __half g_A_lo[NB * NN * NN];
__device__ __half g_frabT_hi[NB * 128 * NN];
__device__ float g_frab1[NB * 64 * 64 * 64];
__device__ float g_fa[NB * NN * 128];
__device__ float g_mpp[8 * NB * CF];
__device__ float g_mp[NB * CF];
__device__ float g_d1p[8 * NB * 512];
__device__ float g_g1[NB * 512];
__device__ float g_logits[NB * NCLS];

// ============================ helpers ============================
__device__ __forceinline__ uint32_t smem_u32(const void* p) {
    uint32_t a;
    asm("{ .reg .u64 t; cvta.to.shared.u64 t, %1; cvt.u32.u64 %0, t; }" : "=r"(a) : "l"(p));
    return a;
}
__device__ __forceinline__ void cp_async16(uint32_t dst, const void* src) {
    asm volatile("cp.async.cg.shared.global [%0], [%1], 16;" :: "r"(dst), "l"(src));
}
#define CP_COMMIT() asm volatile("cp.async.commit_group;" ::: "memory")
#define CP_WAIT(n)  asm volatile("cp.async.wait_group %0;" :: "n"(n) : "memory")

__device__ __forceinline__ void ldsm_x4(uint32_t* r, uint32_t addr) {
    asm volatile("ldmatrix.sync.aligned.m8n8.x4.shared.b16 {%0,%1,%2,%3}, [%4];"
                 : "=r"(r[0]), "=r"(r[1]), "=r"(r[2]), "=r"(r[3]) : "r"(addr));
}
__device__ __forceinline__ void mma16816(float* d, const uint32_t* a, const uint32_t* b) {
    asm volatile(
        "mma.sync.aligned.m16n8k16.row.col.f32.f16.f16.f32 "
        "{%0,%1,%2,%3}, {%4,%5,%6,%7}, {%8,%9}, {%0,%1,%2,%3};"
        : "+f"(d[0]), "+f"(d[1]), "+f"(d[2]), "+f"(d[3])
        : "r"(a[0]), "r"(a[1]), "r"(a[2]), "r"(a[3]), "r"(b[0]), "r"(b[1]));
}

// ---------------- normalize + fp16 hi/lo split (half2 stores) ----------------
__global__ void normalize_split_hl(const float* __restrict__ in,
                                   __half* __restrict__ hi, __half* __restrict__ lo) {
    int row = blockIdx.x;
    const float* src = in + (size_t)row * CF;
    __half* dh = hi + (size_t)row * CF;
    __half* dl = lo + (size_t)row * CF;
    float2 v[4];
    float ss = 0.f;
#pragma unroll
    for (int i = 0; i < 4; i++) {
        int c2 = (threadIdx.x + i * 256) * 2;
        if (c2 < CF) { v[i] = *(const float2*)(src + c2); ss += v[i].x * v[i].x + v[i].y * v[i].y; }
        else v[i] = make_float2(0.f, 0.f);
    }
    __shared__ float red[256];
    red[threadIdx.x] = ss; __syncthreads();
    for (int s = 128; s > 0; s >>= 1) {
        if (threadIdx.x < s) red[threadIdx.x] += red[threadIdx.x + s];
        __syncthreads();
    }
    float inv = 1.f / (sqrtf(red[0]) + 1e-6f);
#pragma unroll
    for (int i = 0; i < 4; i++) {
        int c2 = (threadIdx.x + i * 256) * 2;
        if (c2 < CF) {
            float x0 = v[i].x * inv, x1 = v[i].y * inv;
            __half h0 = __float2half_rn(x0), h1 = __float2half_rn(x1);
            *(__half2*)(dh + c2) = __halves2half2(h0, h1);
            *(__half2*)(dl + c2) = __halves2half2(
                __float2half_rn(x0 - __half2float(h0)), __float2half_rn(x1 - __half2float(h1)));
        }
    }
}
__global__ void normalize_split_h(const float* __restrict__ in, __half* __restrict__ hi) {
    int row = blockIdx.x;
    const float* src = in + (size_t)row * CF;
    __half* dh = hi + (size_t)row * CF;
    float2 v[4];
    float ss = 0.f;
#pragma unroll
    for (int i = 0; i < 4; i++) {
        int c2 = (threadIdx.x + i * 256) * 2;
        if (c2 < CF) { v[i] = *(const float2*)(src + c2); ss += v[i].x * v[i].x + v[i].y * v[i].y; }
        else v[i] = make_float2(0.f, 0.f);
    }
    __shared__ float red[256];
    red[threadIdx.x] = ss; __syncthreads();
    for (int s = 128; s > 0; s >>= 1) {
        if (threadIdx.x < s) red[threadIdx.x] += red[threadIdx.x + s];
        __syncthreads();
    }
    float inv = 1.f / (sqrtf(red[0]) + 1e-6f);
#pragma unroll
    for (int i = 0; i < 4; i++) {
        int c2 = (threadIdx.x + i * 256) * 2;
        if (c2 < CF)
            *(__half2*)(dh + c2) = __halves2half2(
                __float2half_rn(v[i].x * inv), __float2half_rn(v[i].y * inv));
    }
}

// =====================================================================
// gemm_nt_mma: C = Ah*Bh^T + Al*Bh^T  (2-term fp16 split)  [HMMA rate-bound]
// =====================================================================
#define KCH    32
#define NCH    (CF / KCH)        // 62
#define RSTR   80
#define TILE_BYTES (128 * RSTR)
#define STG_BYTES  (3 * TILE_BYTES)
#define PIPE3  3
#define GEMM_SMEM (PIPE3 * STG_BYTES)    // 92160

__global__ __launch_bounds__(256, 2) void gemm_nt_mma(
    const __half* __restrict__ Ahi, const __half* __restrict__ Alo,
    const __half* __restrict__ Bhi, float* __restrict__ Cg)
{
    extern __shared__ __align__(128) char smem[];
    uint32_t sbase = smem_u32(smem);
    int tid = threadIdx.x;
    int wid = tid >> 5, lane = tid & 31;
    int warp_m = wid & 1;
    int warp_n = wid >> 1;

    int b = blockIdx.z;
    int row0 = blockIdx.y * 128;
    int col0 = blockIdx.x * 128;

    const __half* srcs[3] = {
        Ahi + ((size_t)b * NN + row0) * CF,
        Alo + ((size_t)b * NN + row0) * CF,
        Bhi + ((size_t)b * NN + col0) * CF };
    float* C = Cg + (size_t)b * NN * NN;

    float acc[4][4][4];
#pragma unroll
    for (int i = 0; i < 4; i++)
#pragma unroll
        for (int j = 0; j < 4; j++)
#pragma unroll
            for (int k = 0; k < 4; k++) acc[i][j][k] = 0.f;

    auto prefetch = [&](int c) {
        int kk = c * KCH;
        uint32_t stg = sbase + (c % PIPE3) * STG_BYTES;
#pragma unroll
        for (int it = 0; it < 6; it++) {
            int idx = it * 256 + tid;
            int t = idx >> 9;
            int w = idx & 511;
            int r = w >> 2, seg = w & 3;
            cp_async16(stg + (uint32_t)(t * TILE_BYTES + r * RSTR + seg * 16),
                       srcs[t] + (size_t)r * CF + kk + seg * 8);
        }
    };

    prefetch(0); CP_COMMIT();
    prefetch(1); CP_COMMIT();

    int a_row = (lane & 7) + ((lane >> 3) & 1) * 8;
    int a_k8  = (lane >> 4) * 8;
    int bg    = lane >> 3;
    int b_nat = bg >> 1;
    int b_k8  = (bg & 1) * 8;

    for (int c = 0; c < NCH; c++) {
        CP_WAIT(1);
        __syncthreads();
        if (c + 2 < NCH) { prefetch(c + 2); CP_COMMIT(); }

        uint32_t stg = sbase + (c % PIPE3) * STG_BYTES;
        uint32_t sAh = stg, sAl = stg + TILE_BYTES, sBh = stg + 2 * TILE_BYTES;
#pragma unroll
        for (int k16 = 0; k16 < 2; k16++) {
            int kb = k16 * 16;
            uint32_t afh[4][4], afl[4][4];
#pragma unroll
            for (int am = 0; am < 4; am++) {
                uint32_t off = (uint32_t)((warp_m * 64 + am * 16 + a_row) * RSTR + (kb + a_k8) * 2);
                ldsm_x4(afh[am], sAh + off);
                ldsm_x4(afl[am], sAl + off);
            }
            uint32_t bfh[4][2];
#pragma unroll
            for (int bp = 0; bp < 2; bp++) {
                uint32_t boff = (uint32_t)((warp_n * 32 + (bp * 2 + b_nat) * 8 + (lane & 7)) * RSTR
                                           + (kb + b_k8) * 2);
                uint32_t r4[4];
                ldsm_x4(r4, sBh + boff);
                bfh[bp * 2 + 0][0] = r4[0]; bfh[bp * 2 + 0][1] = r4[1];
                bfh[bp * 2 + 1][0] = r4[2]; bfh[bp * 2 + 1][1] = r4[3];
            }
#pragma unroll
            for (int am = 0; am < 4; am++)
#pragma unroll
                for (int an = 0; an < 4; an++) {
                    mma16816(acc[am][an], afh[am], bfh[an]);
                    mma16816(acc[am][an], afl[am], bfh[an]);
                }
        }
    }

    int tr = lane >> 2, tc = (lane & 3) * 2;
#pragma unroll
    for (int am = 0; am < 4; am++)
#pragma unroll
        for (int an = 0; an < 4; an++) {
            int r = row0 + warp_m * 64 + am * 16 + tr;
            int cc = col0 + warp_n * 32 + an * 8 + tc;
            *(float2*)(C + (size_t)r * NN + cc) = make_float2(acc[am][an][0], acc[am][an][1]);
            *(float2*)(C + (size_t)(r + 8) * NN + cc) = make_float2(acc[am][an][2], acc[am][an][3]);
        }
}

// ---------------- row softmax, split-fp16 half2 output ----------------
__global__ void softmax_split_rows(const float* __restrict__ Cmat,
                                   __half* __restrict__ Ahi, __half* __restrict__ Alo) {
    int row = blockIdx.x;
    const float* src = Cmat + (size_t)row * NN;
    __half* dh = Ahi + (size_t)row * NN;
    __half* dl = Alo + (size_t)row * NN;
    int tid = threadIdx.x;
    float2 v[2];
    float m = -1e30f;
#pragma unroll
    for (int i = 0; i < 2; i++) {
        int c2 = (tid + i * 256) * 2;
        v[i] = *(const float2*)(src + c2);
        m = fmaxf(m, fmaxf(v[i].x, v[i].y));
    }
    __shared__ float red[256];
    red[tid] = m; __syncthreads();
    for (int s = 128; s > 0; s >>= 1) { if (tid < s) red[tid] = fmaxf(red[tid], red[tid + s]); __syncthreads(); }
    m = red[0]; __syncthreads();
    float ssum = 0.f;
#pragma unroll
    for (int i = 0; i < 2; i++) {
        v[i].x = __expf(v[i].x - m); v[i].y = __expf(v[i].y - m);
        ssum += v[i].x + v[i].y;
    }
    red[tid] = ssum; __syncthreads();
    for (int s = 128; s > 0; s >>= 1) { if (tid < s) red[tid] += red[tid + s]; __syncthreads(); }
    float inv = 1.f / red[0];
#pragma unroll
    for (int i = 0; i < 2; i++) {
        int c2 = (tid + i * 256) * 2;
        float x0 = v[i].x * inv, x1 = v[i].y * inv;
        __half h0 = __float2half_rn(x0), h1 = __float2half_rn(x1);
        *(__half2*)(dh + c2) = __halves2half2(h0, h1);
        *(__half2*)(dl + c2) = __halves2half2(
            __float2half_rn(x0 - __half2float(h0)), __float2half_rn(x1 - __half2float(h1)));
    }
}

// =====================================================================
// gemm_nn_mma: f_a = (Ah+Al) @ Bh^T
// =====================================================================
#define NKCH   (NN / KCH)
#define AT_BYTES (64 * RSTR)
#define BT_BYTES (128 * RSTR)
#define STG2_BYTES (2 * AT_BYTES + BT_BYTES)
#define PIPE4  4
#define GEMM2_SMEM (PIPE4 * STG2_BYTES)

__global__ __launch_bounds__(256) void gemm_nn_mma(
    const __half* __restrict__ Ahi, const __half* __restrict__ Alo,
    const __half* __restrict__ Bhi, float* __restrict__ Fg)
{
    extern __shared__ __align__(128) char smem[];
    uint32_t sbase = smem_u32(smem);
    int tid = threadIdx.x;
    int wid = tid >> 5, lane = tid & 31;
    int warp_m = wid & 1;
    int warp_n = wid >> 1;

    int b = blockIdx.y;
    int mrow0 = blockIdx.x * 64;

    const __half* Ah = Ahi + ((size_t)b * NN + mrow0) * NN;
    const __half* Al = Alo + ((size_t)b * NN + mrow0) * NN;
    const __half* Bh = Bhi + (size_t)b * 128 * NN;
    float* F = Fg + (size_t)b * NN * 128;

    float acc[2][4][4];
#pragma unroll
    for (int i = 0; i < 2; i++)
#pragma unroll
        for (int j = 0; j < 4; j++)
#pragma unroll
            for (int k = 0; k < 4; k++) acc[i][j][k] = 0.f;

    auto prefetch = [&](int c) {
        int kk = c * KCH;
        uint32_t stg = sbase + (c % PIPE4) * STG2_BYTES;
#pragma unroll
        for (int it = 0; it < 4; it++) {
            int idx = it * 256 + tid;
            if (idx < 512) {
                int pl = idx >> 8, w = idx & 255;
                int r = w >> 2, seg = w & 3;
                const __half* s = pl ? Al : Ah;
                cp_async16(stg + (uint32_t)(pl * AT_BYTES + r * RSTR + seg * 16),
                           s + (size_t)r * NN + kk + seg * 8);
            } else {
                int w = idx - 512;
                int r = w >> 2, seg = w & 3;
                cp_async16(stg + (uint32_t)(2 * AT_BYTES + r * RSTR + seg * 16),
                           Bh + (size_t)r * NN + kk + seg * 8);
            }
        }
    };

    prefetch(0); CP_COMMIT();
    prefetch(1); CP_COMMIT();

    int a_row = (lane & 7) + ((lane >> 3) & 1) * 8;
    int a_k8  = (lane >> 4) * 8;
    int bg    = lane >> 3;
    int b_nat = bg >> 1;
    int b_k8  = (bg & 1) * 8;

    for (int c = 0; c < NKCH; c++) {
        if (c + 2 < NKCH) prefetch(c + 2);
        CP_COMMIT();
        CP_WAIT(2);
        __syncthreads();

        uint32_t stg = sbase + (c % PIPE4) * STG2_BYTES;
        uint32_t sAh = stg, sAl = stg + AT_BYTES, sBh = stg + 2 * AT_BYTES;
#pragma unroll
        for (int k16 = 0; k16 < 2; k16++) {
            int kb = k16 * 16;
            uint32_t afh[2][4], afl[2][4];
#pragma unroll
            for (int am = 0; am < 2; am++) {
                uint32_t off = (uint32_t)((warp_m * 32 + am * 16 + a_row) * RSTR + (kb + a_k8) * 2);
                ldsm_x4(afh[am], sAh + off);
                ldsm_x4(afl[am], sAl + off);
            }
            uint32_t bfh[4][2];
#pragma unroll
            for (int bp = 0; bp < 2; bp++) {
                uint32_t boff = (uint32_t)((warp_n * 32 + (bp * 2 + b_nat) * 8 + (lane & 7)) * RSTR
                                           + (kb + b_k8) * 2);
                uint32_t r4[4];
                ldsm_x4(r4, sBh + boff);
                bfh[bp * 2 + 0][0] = r4[0]; bfh[bp * 2 + 0][1] = r4[1];
                bfh[bp * 2 + 1][0] = r4[2]; bfh[bp * 2 + 1][1] = r4[3];
            }
#pragma unroll
            for (int am = 0; am < 2; am++)
#pragma unroll
                for (int an = 0; an < 4; an++) {
                    mma16816(acc[am][an], afh[am], bfh[an]);
                    mma16816(acc[am][an], afl[am], bfh[an]);
                }
        }
    }

    int tr = lane >> 2, tc = (lane & 3) * 2;
#pragma unroll
    for (int am = 0; am < 2; am++)
#pragma unroll
        for (int an = 0; an < 4; an++) {
            int r = mrow0 + warp_m * 32 + am * 16 + tr;
            int cc = warp_n * 32 + an * 8 + tc;
            *(float2*)(F + (size_t)r * 128 + cc) = make_float2(acc[am][an][0], acc[am][an][1]);
            *(float2*)(F + (size_t)(r + 8) * 128 + cc) = make_float2(acc[am][an][2], acc[am][an][3]);
        }
}

// ------- conv1: small CIN=2, per-batch (unchanged; cheap) -------
template <int TILE, int STRIDE, int CIN>
__global__ void conv2d_relu_t(
    const float* __restrict__ in, const float* __restrict__ w,
    const float* __restrict__ bias, float* __restrict__ out,
    int Hin, int Win, int Hout, int Wout, int Cout, int pad)
{
    constexpr int SPANX = (TILE - 1) * STRIDE + 3;
    extern __shared__ float sm[];
    int b = blockIdx.z;
    int oy = blockIdx.y;
    int ox0 = blockIdx.x * TILE;
    int co = threadIdx.x;

    int iy0 = oy * STRIDE - pad;
    int ix0 = ox0 * STRIDE - pad;
    constexpr int TOT = 3 * SPANX * CIN;
    for (int i = threadIdx.x; i < TOT; i += blockDim.x) {
        int ci = i % CIN; int rest = i / CIN;
        int xx = rest % SPANX; int r = rest / SPANX;
        int iy = iy0 + r, ix = ix0 + xx;
        float v = 0.f;
        if (iy >= 0 && iy < Hin && ix >= 0 && ix < Win)
            v = in[(((size_t)b * Hin + iy) * Win + ix) * CIN + ci];
        sm[(r * SPANX + xx) * CIN + ci] = v;
    }
    __syncthreads();

    float acc[TILE];
    float bv = bias[co];
#pragma unroll
    for (int p = 0; p < TILE; p++) acc[p] = bv;

#pragma unroll
    for (int r = 0; r < 3; r++)
#pragma unroll
        for (int kx = 0; kx < 3; kx++) {
#pragma unroll
            for (int ci = 0; ci < CIN; ci++) {
                float wv = w[(size_t)((r * 3 + kx) * CIN + ci) * Cout + co];
                const float* srow = &sm[(r * SPANX + kx) * CIN + ci];
#pragma unroll
                for (int p = 0; p < TILE; p++)
                    acc[p] += srow[(size_t)p * STRIDE * CIN] * wv;
            }
        }
#pragma unroll
    for (int p = 0; p < TILE; p++) {
        int ox = ox0 + p;
        out[(((size_t)b * Hout + oy) * Wout + ox) * Cout + co] = fmaxf(acc[p], 0.f);
    }
}

// ------- batch-fused 3x3 conv + relu: one block = all 8 batches of a tile -------
// weights read once per block (8-16x less weight traffic than per-batch blocks)
template <int TILE, int STRIDE, int CIN, int CINCH, int COSPLIT>
__global__ void conv2d_relu_b(
    const float* __restrict__ in, const float* __restrict__ w,
    const float* __restrict__ bias, float* __restrict__ out,
    int Hin, int Win, int Hout, int Wout, int Cout, int pad)
{
    constexpr int SPANX = (TILE - 1) * STRIDE + 3;
    constexpr int NCHK = CIN / CINCH;
    extern __shared__ float sm[];       // [3][SPANX][NB][CINCH]
    int oy = blockIdx.y;
    int xt = blockIdx.x / COSPLIT, cs = blockIdx.x % COSPLIT;
    int ox0 = xt * TILE;
    int co = cs * blockDim.x + threadIdx.x;
    int iy0 = oy * STRIDE - pad, ix0 = ox0 * STRIDE - pad;

    float acc[NB][TILE];
    float bv = bias[co];
#pragma unroll
    for (int bt = 0; bt < NB; bt++)
#pragma unroll
        for (int p = 0; p < TILE; p++) acc[bt][p] = bv;

    for (int ch = 0; ch < NCHK; ch++) {
        if (ch) __syncthreads();
        constexpr int TOT = 3 * SPANX * NB * CINCH;
        for (int i = threadIdx.x; i < TOT; i += blockDim.x) {
            int ci = i % CINCH; int rest = i / CINCH;
            int bt = rest % NB; rest /= NB;
            int xx = rest % SPANX; int r = rest / SPANX;
            int iy = iy0 + r, ix = ix0 + xx;
            float v = 0.f;
            if (iy >= 0 && iy < Hin && ix >= 0 && ix < Win)
                v = in[(((size_t)bt * Hin + iy) * Win + ix) * CIN + ch * CINCH + ci];
            sm[((r * SPANX + xx) * NB + bt) * CINCH + ci] = v;
        }
        __syncthreads();
#pragma unroll
        for (int r = 0; r < 3; r++)
#pragma unroll
            for (int kx = 0; kx < 3; kx++) {
#pragma unroll 4
                for (int ci = 0; ci < CINCH; ci++) {
                    float wv = w[(size_t)((r * 3 + kx) * CIN + ch * CINCH + ci) * Cout + co];
#pragma unroll
                    for (int bt = 0; bt < NB; bt++) {
#pragma unroll
                        for (int p = 0; p < TILE; p++)
                            acc[bt][p] += sm[((r * SPANX + kx + p * STRIDE) * NB + bt) * CINCH + ci] * wv;
                    }
                }
            }
    }
#pragma unroll
    for (int bt = 0; bt < NB; bt++)
#pragma unroll
        for (int p = 0; p < TILE; p++)
            out[(((size_t)bt * Hout + oy) * Wout + ox0 + p) * Cout + co] = fmaxf(acc[bt][p], 0.f);
}

// ---- conv2 batch-fused: stride-2 3x3, 64->128, TRANSPOSED fp16 output ----
__global__ void conv2_t_fp16_b(
    const float* __restrict__ in, const float* __restrict__ w,
    const float* __restrict__ bias, __half* __restrict__ out_hi)
{
    constexpr int TILE = 4, STRIDE = 2, SPANX = 11, CIN = 64, CINCH = 32, COUT = 128;
    constexpr int NCHK = CIN / CINCH;
    extern __shared__ float sm[];       // [3][11][8][32] = 33792 B
    int oy = blockIdx.y;                // 0..31
    int ox0 = blockIdx.x * TILE;        // 8 x-tiles
    int co = threadIdx.x;               // 128
    int iy0 = oy * STRIDE, ix0 = ox0 * STRIDE;

    float acc[NB][TILE];
    float bv = bias[co];
#pragma unroll
    for (int bt = 0; bt < NB; bt++)
#pragma unroll
        for (int p = 0; p < TILE; p++) acc[bt][p] = bv;

    for (int ch = 0; ch < NCHK; ch++) {
        if (ch) __syncthreads();
        constexpr int TOT = 3 * SPANX * NB * CINCH;
        for (int i = threadIdx.x; i < TOT; i += COUT) {
            int ci = i % CINCH; int rest = i / CINCH;
            int bt = rest % NB; rest /= NB;
            int xx = rest % SPANX; int r = rest / SPANX;
            int iy = iy0 + r, ix = ix0 + xx;
            float v = 0.f;
            if (iy < 64 && ix < 64)
                v = in[(((size_t)bt * 64 + iy) * 64 + ix) * CIN + ch * CINCH + ci];
            sm[((r * SPANX + xx) * NB + bt) * CINCH + ci] = v;
        }
        __syncthreads();
#pragma unroll
        for (int r = 0; r < 3; r++)
#pragma unroll
            for (int kx = 0; kx < 3; kx++) {
#pragma unroll 4
                for (int ci = 0; ci < CINCH; ci++) {
                    float wv = w[(size_t)((r * 3 + kx) * CIN + ch * CINCH + ci) * COUT + co];
#pragma unroll
                    for (int bt = 0; bt < NB; bt++) {
#pragma unroll
                        for (int p = 0; p < TILE; p++)
                            acc[bt][p] += sm[((r * SPANX + kx + p * STRIDE) * NB + bt) * CINCH + ci] * wv;
                    }
                }
            }
    }
#pragma unroll
    for (int bt = 0; bt < NB; bt++) {
        __half* dh = out_hi + ((size_t)bt * COUT + co) * NN + oy * 32 + ox0;
#pragma unroll
        for (int p = 0; p < TILE; p++)
            dh[p] = __float2half_rn(fmaxf(acc[bt][p], 0.f));
    }
}

// ---------------- maxpool: 2-phase ----------------
__global__ void maxpool_p1(const float* __restrict__ t, float* __restrict__ mpp) {
    int b = blockIdx.z;
    int ns = blockIdx.y;
    int c = blockIdx.x * 256 + threadIdx.x;
    if (c >= CF) return;
    const float* src = t + ((size_t)b * NN + ns * 128) * CF + c;
    float m = -1e30f;
#pragma unroll 8
    for (int n = 0; n < 128; n++) m = fmaxf(m, src[(size_t)n * CF]);
    mpp[((size_t)ns * NB + b) * CF + c] = m;
}
__global__ void maxpool_p2(const float* __restrict__ mpp, float* __restrict__ mp) {
    int b = blockIdx.y;
    int c = blockIdx.x * 256 + threadIdx.x;
    if (c >= CF) return;
    float m = -1e30f;
#pragma unroll
    for (int ns = 0; ns < 8; ns++) m = fmaxf(m, mpp[((size_t)ns * NB + b) * CF + c]);
    mp[b * CF + c] = m;
}

// ---------------- dense1: K-split partials + reduce ----------------
__global__ void dense1_p1(const float* __restrict__ mp, const float* __restrict__ w,
                          float* __restrict__ d1p) {
    int ks = blockIdx.x;
    int b = blockIdx.y;
    int j = threadIdx.x;
    __shared__ float sm[248];
    for (int k = threadIdx.x; k < 248; k += 512) sm[k] = mp[b * CF + ks * 248 + k];
    __syncthreads();
    float s = 0.f;
#pragma unroll 8
    for (int k = 0; k < 248; k++) s += sm[k] * w[(size_t)(ks * 248 + k) * 512 + j];
    d1p[((size_t)ks * NB + b) * 512 + j] = s;
}
__global__ void dense1_p2(const float* __restrict__ d1p, const float* __restrict__ bias,
                          float* __restrict__ g1) {
    int b = blockIdx.x;
    int j = threadIdx.x;
    float s = bias[j];
#pragma unroll
    for (int ks = 0; ks < 8; ks++) s += d1p[((size_t)ks * NB + b) * 512 + j];
    g1[b * 512 + j] = fmaxf(s, 0.f);
}

// ---------------- dense2 logits (j-split) + softmax ----------------
__global__ void dense2_p1(const float* __restrict__ g1, const float* __restrict__ w,
                          const float* __restrict__ bias, float* __restrict__ logits) {
    int jb = blockIdx.x;
    int b = blockIdx.y;
    int j = jb * 128 + threadIdx.x;
    __shared__ float sg[512];
    for (int k = threadIdx.x; k < 512; k += 128) sg[k] = g1[b * 512 + k];
    __syncthreads();
    if (j >= NCLS) return;
    float s = bias[j];
#pragma unroll 8
    for (int k = 0; k < 512; k++) s += sg[k] * w[(size_t)k * NCLS + j];
    logits[b * NCLS + j] = s;
}
__global__ void softmax1000(const float* __restrict__ logits, float* __restrict__ out) {
    int b = blockIdx.x;
    const float* src = logits + b * NCLS;
    int tid = threadIdx.x;
    __shared__ float red[256];
    float m = -1e30f;
    for (int j = tid; j < NCLS; j += 256) m = fmaxf(m, src[j]);
    red[tid] = m; __syncthreads();
    for (int s = 128; s > 0; s >>= 1) { if (tid < s) red[tid] = fmaxf(red[tid], red[tid + s]); __syncthreads(); }
    m = red[0]; __syncthreads();
    float ssum = 0.f;
    for (int j = tid; j < NCLS; j += 256) ssum += __expf(src[j] - m);
    red[tid] = ssum; __syncthreads();
    for (int s = 128; s > 0; s >>= 1) { if (tid < s) red[tid] += red[tid + s]; __syncthreads(); }
    float inv = 1.f / red[0];
    for (int j = tid; j < NCLS; j += 256) out[b * NCLS + j] = __expf(src[j] - m) * inv;
}

// ---------------- launcher ----------------
extern "C" void kernel_launch(void* const* d_in, const int* in_sizes, int n_in,
                              void* d_out, int out_size) {
    const float* t_lum  = (const float*)d_in[0];
    const float* r_lum  = (const float*)d_in[1];
    const float* r_ab   = (const float*)d_in[2];
    const float* w_rab1 = (const float*)d_in[3];
    const float* b_rab1 = (const float*)d_in[4];
    const float* w_rab2 = (const float*)d_in[5];
    const float* b_rab2 = (const float*)d_in[6];
    const float* w_fa1  = (const float*)d_in[7];
    const float* b_fa1  = (const float*)d_in[8];
    const float* w_fa2  = (const float*)d_in[9];
    const float* b_fa2  = (const float*)d_in[10];
    const float* w_fa3  = (const float*)d_in[11];
    const float* b_fa3  = (const float*)d_in[12];
    const float* w_d1   = (const float*)d_in[13];
    const float* b_d1   = (const float*)d_in[14];
    const float* w_d2   = (const float*)d_in[15];
    const float* b_d2   = (const float*)d_in[16];

    __half *tnh, *tnl, *rnh, *Ahi, *Alo, *fTh;
    float *frab1, *fa, *mpp, *mp, *d1p, *g1, *logits;
    cudaGetSymbolAddress((void**)&tnh,    g_tn_hi);
    cudaGetSymbolAddress((void**)&tnl,    g_tn_lo);
    cudaGetSymbolAddress((void**)&rnh,    g_rn_hi);
    cudaGetSymbolAddress((void**)&Ahi,    g_A_hi);
    cudaGetSymbolAddress((void**)&Alo,    g_A_lo);
    cudaGetSymbolAddress((void**)&fTh,    g_frabT_hi);
    cudaGetSymbolAddress((void**)&frab1,  g_frab1);
    cudaGetSymbolAddress((void**)&fa,     g_fa);
    cudaGetSymbolAddress((void**)&mpp,    g_mpp);
    cudaGetSymbolAddress((void**)&mp,     g_mp);
    cudaGetSymbolAddress((void**)&d1p,    g_d1p);
    cudaGetSymbolAddress((void**)&g1,     g_g1);
    cudaGetSymbolAddress((void**)&logits, g_logits);

    cudaFuncSetAttribute(gemm_nt_mma, cudaFuncAttributeMaxDynamicSharedMemorySize, GEMM_SMEM);
    cudaFuncSetAttribute(gemm_nn_mma, cudaFuncAttributeMaxDynamicSharedMemorySize, GEMM2_SMEM);

    float* out  = (float*)d_out;
    float* Cmat = out + 8000;
    float* s1   = out + 8396608;
    float* s2   = out + 8462144;
    float* s3   = out + 8593216;

    // 1,2: normalize + fp16 split
    normalize_split_hl<<<NB * NN, 256>>>(t_lum, tnh, tnl);
    normalize_split_h<<<NB * NN, 256>>>(r_lum, rnh);

    // 3: chroma conv1 (Cin=2, cheap)
    conv2d_relu_t<16, 1, 2><<<dim3(4, 64, NB), 64, 3 * 18 * 2 * 4>>>(
        r_ab, w_rab1, b_rab1, frab1, 64, 64, 64, 64, 64, 1);

    // 4: conv2 batch-fused -> transposed fp16  <- PROFILE SLOT
    conv2_t_fp16_b<<<dim3(8, 32), 128, 3 * 11 * 8 * 32 * 4>>>(
        frab1, w_rab2, b_rab2, fTh);

    // 5: cost volume (HMMA-rate-bound, ~246us floor)
    gemm_nt_mma<<<dim3(8, 8, NB), 256, GEMM_SMEM>>>(tnh, tnl, rnh, Cmat);

    // 6: softmax -> split-fp16
    softmax_split_rows<<<NB * NN, 256>>>(Cmat, Ahi, Alo);

    // 7: attention
    gemm_nn_mma<<<dim3(NN / 64, NB), 256, GEMM2_SMEM>>>(Ahi, Alo, fTh, fa);

    // 8-10: pyramid, batch-fused
    conv2d_relu_b<2, 2, 128, 64, 1><<<dim3(8, 16), 128, 3 * 5 * 8 * 64 * 4>>>(
        fa, w_fa1, b_fa1, s3, 32, 32, 16, 16, 128, 0);
    conv2d_relu_b<2, 2, 128, 64, 2><<<dim3(8, 8), 128, 3 * 5 * 8 * 64 * 4>>>(
        s3, w_fa2, b_fa2, s2, 16, 16, 8, 8, 256, 0);
    conv2d_relu_b<1, 2, 256, 64, 4><<<dim3(16, 4), 128, 3 * 3 * 8 * 64 * 4>>>(
        s2, w_fa3, b_fa3, s1, 8, 8, 4, 4, 512, 0);

    // 11-12: maxpool 2-phase
    maxpool_p1<<<dim3(8, 8, NB), 256>>>(t_lum, mpp);
    maxpool_p2<<<dim3(8, NB), 256>>>(mpp, mp);

    // 13-14: dense1 2-phase
    dense1_p1<<<dim3(8, NB), 512>>>(mp, w_d1, d1p);
    dense1_p2<<<NB, 512>>>(d1p, b_d1, g1);

    // 15-16: dense2 + softmax
    dense2_p1<<<dim3(8, NB), 128>>>(g1, w_d2, b_d2, logits);
    softmax1000<<<NB, 256>>>(logits, out);
}

// round 12
// speedup vs baseline: 1.2757x; 1.2757x over previous
#include <cuda_runtime.h>
#include <cuda_fp16.h>
#include <math.h>
#include <stdint.h>

#define CF   1984
#define NB   8
#define NN   1024    // h*w = 32*32
#define NCLS 1000

// ---------------- scratch (static device globals; no allocation) ----------------
__device__ __half g_tn_hi[NB * NN * CF];
__device__ __half g_tn_lo[NB * NN * CF];
__device__ __half g_rn_hi[NB * NN * CF];
__device__ __half g_A_hi[NB * NN * NN];
__device__ __half g_A_lo[NB * NN * NN];
__device__ __half g_frabT_hi[NB * 128 * NN];
__device__ float g_frab1[NB * 64 * 64 * 64];
__device__ float g_fa[NB * NN * 128];
__device__ float g_mpp[8 * NB * CF];     // maxpool partials [ns][b][c]
__device__ float g_d1p[8 * NB * 512];    // dense1 partials [ks][b][j]
__device__ float g_logits[NB * NCLS];

// ============================ helpers ============================
__device__ __forceinline__ uint32_t smem_u32(const void* p) {
    uint32_t a;
    asm("{ .reg .u64 t; cvta.to.shared.u64 t, %1; cvt.u32.u64 %0, t; }" : "=r"(a) : "l"(p));
    return a;
}
__device__ __forceinline__ void cp_async16(uint32_t dst, const void* src) {
    asm volatile("cp.async.cg.shared.global [%0], [%1], 16;" :: "r"(dst), "l"(src));
}
#define CP_COMMIT() asm volatile("cp.async.commit_group;" ::: "memory")
#define CP_WAIT(n)  asm volatile("cp.async.wait_group %0;" :: "n"(n) : "memory")

__device__ __forceinline__ void ldsm_x4(uint32_t* r, uint32_t addr) {
    asm volatile("ldmatrix.sync.aligned.m8n8.x4.shared.b16 {%0,%1,%2,%3}, [%4];"
                 : "=r"(r[0]), "=r"(r[1]), "=r"(r[2]), "=r"(r[3]) : "r"(addr));
}
__device__ __forceinline__ void mma16816(float* d, const uint32_t* a, const uint32_t* b) {
    asm volatile(
        "mma.sync.aligned.m16n8k16.row.col.f32.f16.f16.f32 "
        "{%0,%1,%2,%3}, {%4,%5,%6,%7}, {%8,%9}, {%0,%1,%2,%3};"
        : "+f"(d[0]), "+f"(d[1]), "+f"(d[2]), "+f"(d[3])
        : "r"(a[0]), "r"(a[1]), "r"(a[2]), "r"(a[3]), "r"(b[0]), "r"(b[1]));
}

// ---------------- normalize + fp16 hi/lo split (float4 loads, packed stores) ----------------
__global__ void normalize_split_hl(const float* __restrict__ in,
                                   __half* __restrict__ hi, __half* __restrict__ lo) {
    int row = blockIdx.x;
    const float4* src4 = (const float4*)(in + (size_t)row * CF);   // 496 float4
    __half* dh = hi + (size_t)row * CF;
    __half* dl = lo + (size_t)row * CF;
    int tid = threadIdx.x;
    float4 v[2];
    float ss = 0.f;
#pragma unroll
    for (int i = 0; i < 2; i++) {
        int c4 = tid + i * 256;
        if (c4 < 496) {
            v[i] = src4[c4];
            ss += v[i].x * v[i].x + v[i].y * v[i].y + v[i].z * v[i].z + v[i].w * v[i].w;
        } else v[i] = make_float4(0.f, 0.f, 0.f, 0.f);
    }
    __shared__ float red[256];
    red[tid] = ss; __syncthreads();
    for (int s = 128; s > 0; s >>= 1) {
        if (tid < s) red[tid] += red[tid + s];
        __syncthreads();
    }
    float inv = 1.f / (sqrtf(red[0]) + 1e-6f);
#pragma unroll
    for (int i = 0; i < 2; i++) {
        int c4 = tid + i * 256;
        if (c4 < 496) {
            float x0 = v[i].x * inv, x1 = v[i].y * inv, x2 = v[i].z * inv, x3 = v[i].w * inv;
            __half h0 = __float2half_rn(x0), h1 = __float2half_rn(x1);
            __half h2 = __float2half_rn(x2), h3 = __float2half_rn(x3);
            __half2 hh[2] = { __halves2half2(h0, h1), __halves2half2(h2, h3) };
            *(uint2*)(dh + c4 * 4) = *(uint2*)hh;
            __half2 ll[2] = {
                __halves2half2(__float2half_rn(x0 - __half2float(h0)),
                               __float2half_rn(x1 - __half2float(h1))),
                __halves2half2(__float2half_rn(x2 - __half2float(h2)),
                               __float2half_rn(x3 - __half2float(h3))) };
            *(uint2*)(dl + c4 * 4) = *(uint2*)ll;
        }
    }
}
__global__ void normalize_split_h(const float* __restrict__ in, __half* __restrict__ hi) {
    int row = blockIdx.x;
    const float4* src4 = (const float4*)(in + (size_t)row * CF);
    __half* dh = hi + (size_t)row * CF;
    int tid = threadIdx.x;
    float4 v[2];
    float ss = 0.f;
#pragma unroll
    for (int i = 0; i < 2; i++) {
        int c4 = tid + i * 256;
        if (c4 < 496) {
            v[i] = src4[c4];
            ss += v[i].x * v[i].x + v[i].y * v[i].y + v[i].z * v[i].z + v[i].w * v[i].w;
        } else v[i] = make_float4(0.f, 0.f, 0.f, 0.f);
    }
    __shared__ float red[256];
    red[tid] = ss; __syncthreads();
    for (int s = 128; s > 0; s >>= 1) {
        if (tid < s) red[tid] += red[tid + s];
        __syncthreads();
    }
    float inv = 1.f / (sqrtf(red[0]) + 1e-6f);
#pragma unroll
    for (int i = 0; i < 2; i++) {
        int c4 = tid + i * 256;
        if (c4 < 496) {
            __half2 hh[2] = {
                __halves2half2(__float2half_rn(v[i].x * inv), __float2half_rn(v[i].y * inv)),
                __halves2half2(__float2half_rn(v[i].z * inv), __float2half_rn(v[i].w * inv)) };
            *(uint2*)(dh + c4 * 4) = *(uint2*)hh;
        }
    }
}

// =====================================================================
// gemm_nt_mma: C = Ah*Bh^T + Al*Bh^T  (2-term fp16 split) [HMMA rate-bound ~246us]
// =====================================================================
#define KCH    32
#define NCH    (CF / KCH)        // 62
#define RSTR   80
#define TILE_BYTES (128 * RSTR)
#define STG_BYTES  (3 * TILE_BYTES)
#define PIPE3  3
#define GEMM_SMEM (PIPE3 * STG_BYTES)    // 92160

__global__ __launch_bounds__(256, 2) void gemm_nt_mma(
    const __half* __restrict__ Ahi, const __half* __restrict__ Alo,
    const __half* __restrict__ Bhi, float* __restrict__ Cg)
{
    extern __shared__ __align__(128) char smem[];
    uint32_t sbase = smem_u32(smem);
    int tid = threadIdx.x;
    int wid = tid >> 5, lane = tid & 31;
    int warp_m = wid & 1;
    int warp_n = wid >> 1;

    int b = blockIdx.z;
    int row0 = blockIdx.y * 128;
    int col0 = blockIdx.x * 128;

    const __half* srcs[3] = {
        Ahi + ((size_t)b * NN + row0) * CF,
        Alo + ((size_t)b * NN + row0) * CF,
        Bhi + ((size_t)b * NN + col0) * CF };
    float* C = Cg + (size_t)b * NN * NN;

    float acc[4][4][4];
#pragma unroll
    for (int i = 0; i < 4; i++)
#pragma unroll
        for (int j = 0; j < 4; j++)
#pragma unroll
            for (int k = 0; k < 4; k++) acc[i][j][k] = 0.f;

    auto prefetch = [&](int c) {
        int kk = c * KCH;
        uint32_t stg = sbase + (c % PIPE3) * STG_BYTES;
#pragma unroll
        for (int it = 0; it < 6; it++) {
            int idx = it * 256 + tid;
            int t = idx >> 9;
            int w = idx & 511;
            int r = w >> 2, seg = w & 3;
            cp_async16(stg + (uint32_t)(t * TILE_BYTES + r * RSTR + seg * 16),
                       srcs[t] + (size_t)r * CF + kk + seg * 8);
        }
    };

    prefetch(0); CP_COMMIT();
    prefetch(1); CP_COMMIT();

    int a_row = (lane & 7) + ((lane >> 3) & 1) * 8;
    int a_k8  = (lane >> 4) * 8;
    int bg    = lane >> 3;
    int b_nat = bg >> 1;
    int b_k8  = (bg & 1) * 8;

    for (int c = 0; c < NCH; c++) {
        CP_WAIT(1);
        __syncthreads();
        if (c + 2 < NCH) { prefetch(c + 2); CP_COMMIT(); }

        uint32_t stg = sbase + (c % PIPE3) * STG_BYTES;
        uint32_t sAh = stg, sAl = stg + TILE_BYTES, sBh = stg + 2 * TILE_BYTES;
#pragma unroll
        for (int k16 = 0; k16 < 2; k16++) {
            int kb = k16 * 16;
            uint32_t afh[4][4], afl[4][4];
#pragma unroll
            for (int am = 0; am < 4; am++) {
                uint32_t off = (uint32_t)((warp_m * 64 + am * 16 + a_row) * RSTR + (kb + a_k8) * 2);
                ldsm_x4(afh[am], sAh + off);
                ldsm_x4(afl[am], sAl + off);
            }
            uint32_t bfh[4][2];
#pragma unroll
            for (int bp = 0; bp < 2; bp++) {
                uint32_t boff = (uint32_t)((warp_n * 32 + (bp * 2 + b_nat) * 8 + (lane & 7)) * RSTR
                                           + (kb + b_k8) * 2);
                uint32_t r4[4];
                ldsm_x4(r4, sBh + boff);
                bfh[bp * 2 + 0][0] = r4[0]; bfh[bp * 2 + 0][1] = r4[1];
                bfh[bp * 2 + 1][0] = r4[2]; bfh[bp * 2 + 1][1] = r4[3];
            }
#pragma unroll
            for (int am = 0; am < 4; am++)
#pragma unroll
                for (int an = 0; an < 4; an++) {
                    mma16816(acc[am][an], afh[am], bfh[an]);
                    mma16816(acc[am][an], afl[am], bfh[an]);
                }
        }
    }

    int tr = lane >> 2, tc = (lane & 3) * 2;
#pragma unroll
    for (int am = 0; am < 4; am++)
#pragma unroll
        for (int an = 0; an < 4; an++) {
            int r = row0 + warp_m * 64 + am * 16 + tr;
            int cc = col0 + warp_n * 32 + an * 8 + tc;
            *(float2*)(C + (size_t)r * NN + cc) = make_float2(acc[am][an][0], acc[am][an][1]);
            *(float2*)(C + (size_t)(r + 8) * NN + cc) = make_float2(acc[am][an][2], acc[am][an][3]);
        }
}

// ---------------- row softmax, split-fp16 half2 output ----------------
__global__ void softmax_split_rows(const float* __restrict__ Cmat,
                                   __half* __restrict__ Ahi, __half* __restrict__ Alo) {
    int row = blockIdx.x;
    const float* src = Cmat + (size_t)row * NN;
    __half* dh = Ahi + (size_t)row * NN;
    __half* dl = Alo + (size_t)row * NN;
    int tid = threadIdx.x;
    float2 v[2];
    float m = -1e30f;
#pragma unroll
    for (int i = 0; i < 2; i++) {
        int c2 = (tid + i * 256) * 2;
        v[i] = *(const float2*)(src + c2);
        m = fmaxf(m, fmaxf(v[i].x, v[i].y));
    }
    __shared__ float red[256];
    red[tid] = m; __syncthreads();
    for (int s = 128; s > 0; s >>= 1) { if (tid < s) red[tid] = fmaxf(red[tid], red[tid + s]); __syncthreads(); }
    m = red[0]; __syncthreads();
    float ssum = 0.f;
#pragma unroll
    for (int i = 0; i < 2; i++) {
        v[i].x = __expf(v[i].x - m); v[i].y = __expf(v[i].y - m);
        ssum += v[i].x + v[i].y;
    }
    red[tid] = ssum; __syncthreads();
    for (int s = 128; s > 0; s >>= 1) { if (tid < s) red[tid] += red[tid + s]; __syncthreads(); }
    float inv = 1.f / red[0];
#pragma unroll
    for (int i = 0; i < 2; i++) {
        int c2 = (tid + i * 256) * 2;
        float x0 = v[i].x * inv, x1 = v[i].y * inv;
        __half h0 = __float2half_rn(x0), h1 = __float2half_rn(x1);
        *(__half2*)(dh + c2) = __halves2half2(h0, h1);
        *(__half2*)(dl + c2) = __halves2half2(
            __float2half_rn(x0 - __half2float(h0)), __float2half_rn(x1 - __half2float(h1)));
    }
}

// =====================================================================
// gemm_nn_mma: f_a = (Ah+Al) @ Bh^T
// =====================================================================
#define NKCH   (NN / KCH)
#define AT_BYTES (64 * RSTR)
#define BT_BYTES (128 * RSTR)
#define STG2_BYTES (2 * AT_BYTES + BT_BYTES)
#define PIPE4  4
#define GEMM2_SMEM (PIPE4 * STG2_BYTES)

__global__ __launch_bounds__(256) void gemm_nn_mma(
    const __half* __restrict__ Ahi, const __half* __restrict__ Alo,
    const __half* __restrict__ Bhi, float* __restrict__ Fg)
{
    extern __shared__ __align__(128) char smem[];
    uint32_t sbase = smem_u32(smem);
    int tid = threadIdx.x;
    int wid = tid >> 5, lane = tid & 31;
    int warp_m = wid & 1;
    int warp_n = wid >> 1;

    int b = blockIdx.y;
    int mrow0 = blockIdx.x * 64;

    const __half* Ah = Ahi + ((size_t)b * NN + mrow0) * NN;
    const __half* Al = Alo + ((size_t)b * NN + mrow0) * NN;
    const __half* Bh = Bhi + (size_t)b * 128 * NN;
    float* F = Fg + (size_t)b * NN * 128;

    float acc[2][4][4];
#pragma unroll
    for (int i = 0; i < 2; i++)
#pragma unroll
        for (int j = 0; j < 4; j++)
#pragma unroll
            for (int k = 0; k < 4; k++) acc[i][j][k] = 0.f;

    auto prefetch = [&](int c) {
        int kk = c * KCH;
        uint32_t stg = sbase + (c % PIPE4) * STG2_BYTES;
#pragma unroll
        for (int it = 0; it < 4; it++) {
            int idx = it * 256 + tid;
            if (idx < 512) {
                int pl = idx >> 8, w = idx & 255;
                int r = w >> 2, seg = w & 3;
                const __half* s = pl ? Al : Ah;
                cp_async16(stg + (uint32_t)(pl * AT_BYTES + r * RSTR + seg * 16),
                           s + (size_t)r * NN + kk + seg * 8);
            } else {
                int w = idx - 512;
                int r = w >> 2, seg = w & 3;
                cp_async16(stg + (uint32_t)(2 * AT_BYTES + r * RSTR + seg * 16),
                           Bh + (size_t)r * NN + kk + seg * 8);
            }
        }
    };

    prefetch(0); CP_COMMIT();
    prefetch(1); CP_COMMIT();

    int a_row = (lane & 7) + ((lane >> 3) & 1) * 8;
    int a_k8  = (lane >> 4) * 8;
    int bg    = lane >> 3;
    int b_nat = bg >> 1;
    int b_k8  = (bg & 1) * 8;

    for (int c = 0; c < NKCH; c++) {
        if (c + 2 < NKCH) prefetch(c + 2);
        CP_COMMIT();
        CP_WAIT(2);
        __syncthreads();

        uint32_t stg = sbase + (c % PIPE4) * STG2_BYTES;
        uint32_t sAh = stg, sAl = stg + AT_BYTES, sBh = stg + 2 * AT_BYTES;
#pragma unroll
        for (int k16 = 0; k16 < 2; k16++) {
            int kb = k16 * 16;
            uint32_t afh[2][4], afl[2][4];
#pragma unroll
            for (int am = 0; am < 2; am++) {
                uint32_t off = (uint32_t)((warp_m * 32 + am * 16 + a_row) * RSTR + (kb + a_k8) * 2);
                ldsm_x4(afh[am], sAh + off);
                ldsm_x4(afl[am], sAl + off);
            }
            uint32_t bfh[4][2];
#pragma unroll
            for (int bp = 0; bp < 2; bp++) {
                uint32_t boff = (uint32_t)((warp_n * 32 + (bp * 2 + b_nat) * 8 + (lane & 7)) * RSTR
                                           + (kb + b_k8) * 2);
                uint32_t r4[4];
                ldsm_x4(r4, sBh + boff);
                bfh[bp * 2 + 0][0] = r4[0]; bfh[bp * 2 + 0][1] = r4[1];
                bfh[bp * 2 + 1][0] = r4[2]; bfh[bp * 2 + 1][1] = r4[3];
            }
#pragma unroll
            for (int am = 0; am < 2; am++)
#pragma unroll
                for (int an = 0; an < 4; an++) {
                    mma16816(acc[am][an], afh[am], bfh[an]);
                    mma16816(acc[am][an], afl[am], bfh[an]);
                }
        }
    }

    int tr = lane >> 2, tc = (lane & 3) * 2;
#pragma unroll
    for (int am = 0; am < 2; am++)
#pragma unroll
        for (int an = 0; an < 4; an++) {
            int r = mrow0 + warp_m * 32 + am * 16 + tr;
            int cc = warp_n * 32 + an * 8 + tc;
            *(float2*)(F + (size_t)r * 128 + cc) = make_float2(acc[am][an][0], acc[am][an][1]);
            *(float2*)(F + (size_t)(r + 8) * 128 + cc) = make_float2(acc[am][an][2], acc[am][an][3]);
        }
}

// ------- templated 3x3 conv + bias + relu, NHWC (R8-proven) -------
template <int TILE, int STRIDE, int CIN, int COSPLIT>
__global__ void conv2d_relu_t(
    const float* __restrict__ in, const float* __restrict__ w,
    const float* __restrict__ bias, float* __restrict__ out,
    int Hin, int Win, int Hout, int Wout, int Cout, int pad)
{
    constexpr int SPANX = (TILE - 1) * STRIDE + 3;
    extern __shared__ float sm[];
    int b = blockIdx.z;
    int oy = blockIdx.y;
    int xt = blockIdx.x / COSPLIT;
    int cs = blockIdx.x % COSPLIT;
    int ox0 = xt * TILE;
    int co = cs * blockDim.x + threadIdx.x;

    int iy0 = oy * STRIDE - pad;
    int ix0 = ox0 * STRIDE - pad;
    constexpr int TOT = 3 * SPANX * CIN;
    for (int i = threadIdx.x; i < TOT; i += blockDim.x) {
        int ci = i % CIN; int rest = i / CIN;
        int xx = rest % SPANX; int r = rest / SPANX;
        int iy = iy0 + r, ix = ix0 + xx;
        float v = 0.f;
        if (iy >= 0 && iy < Hin && ix >= 0 && ix < Win)
            v = in[(((size_t)b * Hin + iy) * Win + ix) * CIN + ci];
        sm[(r * SPANX + xx) * CIN + ci] = v;
    }
    __syncthreads();

    float acc[TILE];
    float bv = bias[co];
#pragma unroll
    for (int p = 0; p < TILE; p++) acc[p] = bv;

#pragma unroll
    for (int r = 0; r < 3; r++)
#pragma unroll
        for (int kx = 0; kx < 3; kx++) {
#pragma unroll 8
            for (int ci = 0; ci < CIN; ci++) {
                float wv = w[(size_t)((r * 3 + kx) * CIN + ci) * Cout + co];
                const float* srow = &sm[(r * SPANX + kx) * CIN + ci];
#pragma unroll
                for (int p = 0; p < TILE; p++)
                    acc[p] += srow[(size_t)p * STRIDE * CIN] * wv;
            }
        }
#pragma unroll
    for (int p = 0; p < TILE; p++) {
        int ox = ox0 + p;
        out[(((size_t)b * Hout + oy) * Wout + ox) * Cout + co] = fmaxf(acc[p], 0.f);
    }
}

// ---- conv2: stride-2 3x3, 64->128, TRANSPOSED fp16, TILE=8 (R8-proven) ----
__global__ void conv2_t_fp16(
    const float* __restrict__ in, const float* __restrict__ w,
    const float* __restrict__ bias, __half* __restrict__ out_hi)
{
    constexpr int TILE = 8, STRIDE = 2, SPANX = 17, CIN = 64, COUT = 128;
    extern __shared__ float sm[];
    int b = blockIdx.z;
    int oy = blockIdx.y;
    int ox0 = blockIdx.x * TILE;
    int co = threadIdx.x;

    int iy0 = oy * STRIDE;
    int ix0 = ox0 * STRIDE;
    constexpr int TOT = 3 * SPANX * CIN;
    for (int i = threadIdx.x; i < TOT; i += COUT) {
        int ci = i % CIN; int rest = i / CIN;
        int xx = rest % SPANX; int r = rest / SPANX;
        int iy = iy0 + r, ix = ix0 + xx;
        float v = 0.f;
        if (iy < 64 && ix < 64)
            v = in[(((size_t)b * 64 + iy) * 64 + ix) * CIN + ci];
        sm[(r * SPANX + xx) * CIN + ci] = v;
    }
    __syncthreads();

    float acc[TILE];
    float bv = bias[co];
#pragma unroll
    for (int p = 0; p < TILE; p++) acc[p] = bv;

#pragma unroll
    for (int r = 0; r < 3; r++)
#pragma unroll
        for (int kx = 0; kx < 3; kx++) {
#pragma unroll 8
            for (int ci = 0; ci < CIN; ci++) {
                float wv = w[(size_t)((r * 3 + kx) * CIN + ci) * COUT + co];
                const float* srow = &sm[(r * SPANX + kx) * CIN + ci];
#pragma unroll
                for (int p = 0; p < TILE; p++)
                    acc[p] += srow[(size_t)p * STRIDE * CIN] * wv;
            }
        }
    __half* dh = out_hi + ((size_t)b * COUT + co) * NN + oy * 32 + ox0;
#pragma unroll
    for (int p = 0; p < TILE; p++)
        dh[p] = __float2half_rn(fmaxf(acc[p], 0.f));
}

// ---------------- maxpool phase 1 (phase 2 fused into dense1) ----------------
__global__ void maxpool_p1(const float* __restrict__ t, float* __restrict__ mpp) {
    int b = blockIdx.z;
    int ns = blockIdx.y;
    int c = blockIdx.x * 256 + threadIdx.x;
    if (c >= CF) return;
    const float* src = t + ((size_t)b * NN + ns * 128) * CF + c;
    float m = -1e30f;
#pragma unroll 8
    for (int n = 0; n < 128; n++) m = fmaxf(m, src[(size_t)n * CF]);
    mpp[((size_t)ns * NB + b) * CF + c] = m;
}

// ---------------- dense1 (fused maxpool reduce): partials over K-slices ----------------
__global__ void dense1_p1(const float* __restrict__ mpp, const float* __restrict__ w,
                          float* __restrict__ d1p) {
    int ks = blockIdx.x;                    // 0..7
    int b = blockIdx.y;
    int j = threadIdx.x;                    // 512
    __shared__ float sm[248];
    for (int k = threadIdx.x; k < 248; k += 512) {
        int c = ks * 248 + k;
        float m = -1e30f;
#pragma unroll
        for (int ns = 0; ns < 8; ns++) m = fmaxf(m, mpp[((size_t)ns * NB + b) * CF + c]);
        sm[k] = m;
    }
    __syncthreads();
    float s = 0.f;
#pragma unroll 8
    for (int k = 0; k < 248; k++) s += sm[k] * w[(size_t)(ks * 248 + k) * 512 + j];
    d1p[((size_t)ks * NB + b) * 512 + j] = s;
}

// ---------------- dense2 (fused dense1 reduce + bias + relu) + logits ----------------
__global__ void dense2_p1(const float* __restrict__ d1p, const float* __restrict__ b1,
                          const float* __restrict__ w, const float* __restrict__ bias,
                          float* __restrict__ logits) {
    int jb = blockIdx.x;                    // 0..7
    int b = blockIdx.y;
    int j = jb * 128 + threadIdx.x;
    __shared__ float sg[512];
    for (int k = threadIdx.x; k < 512; k += 128) {
        float s = b1[k];
#pragma unroll
        for (int ks = 0; ks < 8; ks++) s += d1p[((size_t)ks * NB + b) * 512 + k];
        sg[k] = fmaxf(s, 0.f);
    }
    __syncthreads();
    if (j >= NCLS) return;
    float s = bias[j];
#pragma unroll 8
    for (int k = 0; k < 512; k++) s += sg[k] * w[(size_t)k * NCLS + j];
    logits[b * NCLS + j] = s;
}
__global__ void softmax1000(const float* __restrict__ logits, float* __restrict__ out) {
    int b = blockIdx.x;
    const float* src = logits + b * NCLS;
    int tid = threadIdx.x;
    __shared__ float red[256];
    float m = -1e30f;
    for (int j = tid; j < NCLS; j += 256) m = fmaxf(m, src[j]);
    red[tid] = m; __syncthreads();
    for (int s = 128; s > 0; s >>= 1) { if (tid < s) red[tid] = fmaxf(red[tid], red[tid + s]); __syncthreads(); }
    m = red[0]; __syncthreads();
    float ssum = 0.f;
    for (int j = tid; j < NCLS; j += 256) ssum += __expf(src[j] - m);
    red[tid] = ssum; __syncthreads();
    for (int s = 128; s > 0; s >>= 1) { if (tid < s) red[tid] += red[tid + s]; __syncthreads(); }
    float inv = 1.f / red[0];
    for (int j = tid; j < NCLS; j += 256) out[b * NCLS + j] = __expf(src[j] - m) * inv;
}

// ---------------- launcher ----------------
extern "C" void kernel_launch(void* const* d_in, const int* in_sizes, int n_in,
                              void* d_out, int out_size) {
    const float* t_lum  = (const float*)d_in[0];
    const float* r_lum  = (const float*)d_in[1];
    const float* r_ab   = (const float*)d_in[2];
    const float* w_rab1 = (const float*)d_in[3];
    const float* b_rab1 = (const float*)d_in[4];
    const float* w_rab2 = (const float*)d_in[5];
    const float* b_rab2 = (const float*)d_in[6];
    const float* w_fa1  = (const float*)d_in[7];
    const float* b_fa1  = (const float*)d_in[8];
    const float* w_fa2  = (const float*)d_in[9];
    const float* b_fa2  = (const float*)d_in[10];
    const float* w_fa3  = (const float*)d_in[11];
    const float* b_fa3  = (const float*)d_in[12];
    const float* w_d1   = (const float*)d_in[13];
    const float* b_d1   = (const float*)d_in[14];
    const float* w_d2   = (const float*)d_in[15];
    const float* b_d2   = (const float*)d_in[16];

    __half *tnh, *tnl, *rnh, *Ahi, *Alo, *fTh;
    float *frab1, *fa, *mpp, *d1p, *logits;
    cudaGetSymbolAddress((void**)&tnh,    g_tn_hi);
    cudaGetSymbolAddress((void**)&tnl,    g_tn_lo);
    cudaGetSymbolAddress((void**)&rnh,    g_rn_hi);
    cudaGetSymbolAddress((void**)&Ahi,    g_A_hi);
    cudaGetSymbolAddress((void**)&Alo,    g_A_lo);
    cudaGetSymbolAddress((void**)&fTh,    g_frabT_hi);
    cudaGetSymbolAddress((void**)&frab1,  g_frab1);
    cudaGetSymbolAddress((void**)&fa,     g_fa);
    cudaGetSymbolAddress((void**)&mpp,    g_mpp);
    cudaGetSymbolAddress((void**)&d1p,    g_d1p);
    cudaGetSymbolAddress((void**)&logits, g_logits);

    cudaFuncSetAttribute(gemm_nt_mma, cudaFuncAttributeMaxDynamicSharedMemorySize, GEMM_SMEM);
    cudaFuncSetAttribute(gemm_nn_mma, cudaFuncAttributeMaxDynamicSharedMemorySize, GEMM2_SMEM);

    float* out  = (float*)d_out;
    float* Cmat = out + 8000;
    float* s1   = out + 8396608;
    float* s2   = out + 8462144;
    float* s3   = out + 8593216;

    // 1: maxpool phase 1 (independent)
    maxpool_p1<<<dim3(8, 8, NB), 256>>>(t_lum, mpp);

    // 2: normalize r (hi only)
    normalize_split_h<<<NB * NN, 256>>>(r_lum, rnh);

    // 3: chroma conv1
    conv2d_relu_t<16, 1, 2, 1><<<dim3(4, 64, NB), 64, 3 * 18 * 2 * 4>>>(
        r_ab, w_rab1, b_rab1, frab1, 64, 64, 64, 64, 64, 1);

    // 4: normalize t (hi+lo)   <- PROFILE SLOT
    normalize_split_hl<<<NB * NN, 256>>>(t_lum, tnh, tnl);

    // 5: cost volume (HMMA rate-bound)
    gemm_nt_mma<<<dim3(8, 8, NB), 256, GEMM_SMEM>>>(tnh, tnl, rnh, Cmat);

    // 6: chroma conv2 -> transposed fp16 (R8 config)
    conv2_t_fp16<<<dim3(4, 32, NB), 128, 3 * 17 * 64 * 4>>>(
        frab1, w_rab2, b_rab2, fTh);

    // 7: softmax -> split-fp16
    softmax_split_rows<<<NB * NN, 256>>>(Cmat, Ahi, Alo);

    // 8: attention
    gemm_nn_mma<<<dim3(NN / 64, NB), 256, GEMM2_SMEM>>>(Ahi, Alo, fTh, fa);

    // 9-11: pyramid (R8-proven configs)
    conv2d_relu_t<4, 2, 128, 1><<<dim3(4, 16, NB), 128, 3 * 9 * 128 * 4>>>(
        fa, w_fa1, b_fa1, s3, 32, 32, 16, 16, 128, 0);
    conv2d_relu_t<4, 2, 128, 1><<<dim3(2, 8, NB), 256, 3 * 9 * 128 * 4>>>(
        s3, w_fa2, b_fa2, s2, 16, 16, 8, 8, 256, 0);
    conv2d_relu_t<2, 2, 256, 2><<<dim3(4, 4, NB), 256, 3 * 5 * 256 * 4>>>(
        s2, w_fa3, b_fa3, s1, 8, 8, 4, 4, 512, 0);

    // 12-14: classifier head (fused: maxpool_p2 into dense1, dense1_p2 into dense2)
    dense1_p1<<<dim3(8, NB), 512>>>(mpp, w_d1, d1p);
    dense2_p1<<<dim3(8, NB), 128>>>(d1p, b_d1, w_d2, b_d2, logits);
    softmax1000<<<NB, 256>>>(logits, out);
}

// round 13
// speedup vs baseline: 1.2815x; 1.0045x over previous
#include <cuda_runtime.h>
#include <cuda_fp16.h>
#include <math.h>
#include <stdint.h>

#define CF   1984
#define NB   8
#define NN   1024    // h*w = 32*32
#define NCLS 1000

// ---------------- scratch (static device globals; no allocation) ----------------
__device__ __half g_tn_hi[NB * NN * CF];
__device__ __half g_tn_lo[NB * NN * CF];
__device__ __half g_rn_hi[NB * NN * CF];
__device__ __half g_A_hi[NB * NN * NN];
__device__ __half g_A_lo[NB * NN * NN];
__device__ __half g_frabT_hi[NB * 128 * NN];
__device__ float g_frab1[NB * 64 * 64 * 64];
__device__ float g_fa[NB * NN * 128];
__device__ float g_mpp[8 * NB * CF];     // maxpool partials [ns][b][c]
__device__ float g_d1p[8 * NB * 512];    // dense1 partials [ks][b][j]
__device__ float g_logits[NB * NCLS];

// ============================ helpers ============================
__device__ __forceinline__ uint32_t smem_u32(const void* p) {
    uint32_t a;
    asm("{ .reg .u64 t; cvta.to.shared.u64 t, %1; cvt.u32.u64 %0, t; }" : "=r"(a) : "l"(p));
    return a;
}
__device__ __forceinline__ void cp_async16(uint32_t dst, const void* src) {
    asm volatile("cp.async.cg.shared.global [%0], [%1], 16;" :: "r"(dst), "l"(src));
}
#define CP_COMMIT() asm volatile("cp.async.commit_group;" ::: "memory")
#define CP_WAIT(n)  asm volatile("cp.async.wait_group %0;" :: "n"(n) : "memory")

__device__ __forceinline__ void ldsm_x4(uint32_t* r, uint32_t addr) {
    asm volatile("ldmatrix.sync.aligned.m8n8.x4.shared.b16 {%0,%1,%2,%3}, [%4];"
                 : "=r"(r[0]), "=r"(r[1]), "=r"(r[2]), "=r"(r[3]) : "r"(addr));
}
__device__ __forceinline__ void mma16816(float* d, const uint32_t* a, const uint32_t* b) {
    asm volatile(
        "mma.sync.aligned.m16n8k16.row.col.f32.f16.f16.f32 "
        "{%0,%1,%2,%3}, {%4,%5,%6,%7}, {%8,%9}, {%0,%1,%2,%3};"
        : "+f"(d[0]), "+f"(d[1]), "+f"(d[2]), "+f"(d[3])
        : "r"(a[0]), "r"(a[1]), "r"(a[2]), "r"(a[3]), "r"(b[0]), "r"(b[1]));
}

// ---------------- normalize + fp16 hi/lo split (float4 loads, packed stores) ----------------
__global__ void normalize_split_hl(const float* __restrict__ in,
                                   __half* __restrict__ hi, __half* __restrict__ lo) {
    int row = blockIdx.x;
    const float4* src4 = (const float4*)(in + (size_t)row * CF);   // 496 float4
    __half* dh = hi + (size_t)row * CF;
    __half* dl = lo + (size_t)row * CF;
    int tid = threadIdx.x;
    float4 v[2];
    float ss = 0.f;
#pragma unroll
    for (int i = 0; i < 2; i++) {
        int c4 = tid + i * 256;
        if (c4 < 496) {
            v[i] = src4[c4];
            ss += v[i].x * v[i].x + v[i].y * v[i].y + v[i].z * v[i].z + v[i].w * v[i].w;
        } else v[i] = make_float4(0.f, 0.f, 0.f, 0.f);
    }
    __shared__ float red[256];
    red[tid] = ss; __syncthreads();
    for (int s = 128; s > 0; s >>= 1) {
        if (tid < s) red[tid] += red[tid + s];
        __syncthreads();
    }
    float inv = 1.f / (sqrtf(red[0]) + 1e-6f);
#pragma unroll
    for (int i = 0; i < 2; i++) {
        int c4 = tid + i * 256;
        if (c4 < 496) {
            float x0 = v[i].x * inv, x1 = v[i].y * inv, x2 = v[i].z * inv, x3 = v[i].w * inv;
            __half h0 = __float2half_rn(x0), h1 = __float2half_rn(x1);
            __half h2 = __float2half_rn(x2), h3 = __float2half_rn(x3);
            __half2 hh[2] = { __halves2half2(h0, h1), __halves2half2(h2, h3) };
            *(uint2*)(dh + c4 * 4) = *(uint2*)hh;
            __half2 ll[2] = {
                __halves2half2(__float2half_rn(x0 - __half2float(h0)),
                               __float2half_rn(x1 - __half2float(h1))),
                __halves2half2(__float2half_rn(x2 - __half2float(h2)),
                               __float2half_rn(x3 - __half2float(h3))) };
            *(uint2*)(dl + c4 * 4) = *(uint2*)ll;
        }
    }
}
__global__ void normalize_split_h(const float* __restrict__ in, __half* __restrict__ hi) {
    int row = blockIdx.x;
    const float4* src4 = (const float4*)(in + (size_t)row * CF);
    __half* dh = hi + (size_t)row * CF;
    int tid = threadIdx.x;
    float4 v[2];
    float ss = 0.f;
#pragma unroll
    for (int i = 0; i < 2; i++) {
        int c4 = tid + i * 256;
        if (c4 < 496) {
            v[i] = src4[c4];
            ss += v[i].x * v[i].x + v[i].y * v[i].y + v[i].z * v[i].z + v[i].w * v[i].w;
        } else v[i] = make_float4(0.f, 0.f, 0.f, 0.f);
    }
    __shared__ float red[256];
    red[tid] = ss; __syncthreads();
    for (int s = 128; s > 0; s >>= 1) {
        if (tid < s) red[tid] += red[tid + s];
        __syncthreads();
    }
    float inv = 1.f / (sqrtf(red[0]) + 1e-6f);
#pragma unroll
    for (int i = 0; i < 2; i++) {
        int c4 = tid + i * 256;
        if (c4 < 496) {
            __half2 hh[2] = {
                __halves2half2(__float2half_rn(v[i].x * inv), __float2half_rn(v[i].y * inv)),
                __halves2half2(__float2half_rn(v[i].z * inv), __float2half_rn(v[i].w * inv)) };
            *(uint2*)(dh + c4 * 4) = *(uint2*)hh;
        }
    }
}

// =====================================================================
// gemm_nt_mma: C = Ah*Bh^T + Al*Bh^T  (2-term fp16 split) [HMMA rate-bound ~246us]
// =====================================================================
#define KCH    32
#define NCH    (CF / KCH)        // 62
#define RSTR   80
#define TILE_BYTES (128 * RSTR)
#define STG_BYTES  (3 * TILE_BYTES)
#define PIPE3  3
#define GEMM_SMEM (PIPE3 * STG_BYTES)    // 92160

__global__ __launch_bounds__(256, 2) void gemm_nt_mma(
    const __half* __restrict__ Ahi, const __half* __restrict__ Alo,
    const __half* __restrict__ Bhi, float* __restrict__ Cg)
{
    extern __shared__ __align__(128) char smem[];
    uint32_t sbase = smem_u32(smem);
    int tid = threadIdx.x;
    int wid = tid >> 5, lane = tid & 31;
    int warp_m = wid & 1;
    int warp_n = wid >> 1;

    int b = blockIdx.z;
    int row0 = blockIdx.y * 128;
    int col0 = blockIdx.x * 128;

    const __half* srcs[3] = {
        Ahi + ((size_t)b * NN + row0) * CF,
        Alo + ((size_t)b * NN + row0) * CF,
        Bhi + ((size_t)b * NN + col0) * CF };
    float* C = Cg + (size_t)b * NN * NN;

    float acc[4][4][4];
#pragma unroll
    for (int i = 0; i < 4; i++)
#pragma unroll
        for (int j = 0; j < 4; j++)
#pragma unroll
            for (int k = 0; k < 4; k++) acc[i][j][k] = 0.f;

    auto prefetch = [&](int c) {
        int kk = c * KCH;
        uint32_t stg = sbase + (c % PIPE3) * STG_BYTES;
#pragma unroll
        for (int it = 0; it < 6; it++) {
            int idx = it * 256 + tid;
            int t = idx >> 9;
            int w = idx & 511;
            int r = w >> 2, seg = w & 3;
            cp_async16(stg + (uint32_t)(t * TILE_BYTES + r * RSTR + seg * 16),
                       srcs[t] + (size_t)r * CF + kk + seg * 8);
        }
    };

    prefetch(0); CP_COMMIT();
    prefetch(1); CP_COMMIT();

    int a_row = (lane & 7) + ((lane >> 3) & 1) * 8;
    int a_k8  = (lane >> 4) * 8;
    int bg    = lane >> 3;
    int b_nat = bg >> 1;
    int b_k8  = (bg & 1) * 8;

    for (int c = 0; c < NCH; c++) {
        CP_WAIT(1);
        __syncthreads();
        if (c + 2 < NCH) { prefetch(c + 2); CP_COMMIT(); }

        uint32_t stg = sbase + (c % PIPE3) * STG_BYTES;
        uint32_t sAh = stg, sAl = stg + TILE_BYTES, sBh = stg + 2 * TILE_BYTES;
#pragma unroll
        for (int k16 = 0; k16 < 2; k16++) {
            int kb = k16 * 16;
            uint32_t afh[4][4], afl[4][4];
#pragma unroll
            for (int am = 0; am < 4; am++) {
                uint32_t off = (uint32_t)((warp_m * 64 + am * 16 + a_row) * RSTR + (kb + a_k8) * 2);
                ldsm_x4(afh[am], sAh + off);
                ldsm_x4(afl[am], sAl + off);
            }
            uint32_t bfh[4][2];
#pragma unroll
            for (int bp = 0; bp < 2; bp++) {
                uint32_t boff = (uint32_t)((warp_n * 32 + (bp * 2 + b_nat) * 8 + (lane & 7)) * RSTR
                                           + (kb + b_k8) * 2);
                uint32_t r4[4];
                ldsm_x4(r4, sBh + boff);
                bfh[bp * 2 + 0][0] = r4[0]; bfh[bp * 2 + 0][1] = r4[1];
                bfh[bp * 2 + 1][0] = r4[2]; bfh[bp * 2 + 1][1] = r4[3];
            }
#pragma unroll
            for (int am = 0; am < 4; am++)
#pragma unroll
                for (int an = 0; an < 4; an++) {
                    mma16816(acc[am][an], afh[am], bfh[an]);
                    mma16816(acc[am][an], afl[am], bfh[an]);
                }
        }
    }

    int tr = lane >> 2, tc = (lane & 3) * 2;
#pragma unroll
    for (int am = 0; am < 4; am++)
#pragma unroll
        for (int an = 0; an < 4; an++) {
            int r = row0 + warp_m * 64 + am * 16 + tr;
            int cc = col0 + warp_n * 32 + an * 8 + tc;
            *(float2*)(C + (size_t)r * NN + cc) = make_float2(acc[am][an][0], acc[am][an][1]);
            *(float2*)(C + (size_t)(r + 8) * NN + cc) = make_float2(acc[am][an][2], acc[am][an][3]);
        }
}

// ---------------- row softmax, split-fp16 half2 output ----------------
__global__ void softmax_split_rows(const float* __restrict__ Cmat,
                                   __half* __restrict__ Ahi, __half* __restrict__ Alo) {
    int row = blockIdx.x;
    const float* src = Cmat + (size_t)row * NN;
    __half* dh = Ahi + (size_t)row * NN;
    __half* dl = Alo + (size_t)row * NN;
    int tid = threadIdx.x;
    float2 v[2];
    float m = -1e30f;
#pragma unroll
    for (int i = 0; i < 2; i++) {
        int c2 = (tid + i * 256) * 2;
        v[i] = *(const float2*)(src + c2);
        m = fmaxf(m, fmaxf(v[i].x, v[i].y));
    }
    __shared__ float red[256];
    red[tid] = m; __syncthreads();
    for (int s = 128; s > 0; s >>= 1) { if (tid < s) red[tid] = fmaxf(red[tid], red[tid + s]); __syncthreads(); }
    m = red[0]; __syncthreads();
    float ssum = 0.f;
#pragma unroll
    for (int i = 0; i < 2; i++) {
        v[i].x = __expf(v[i].x - m); v[i].y = __expf(v[i].y - m);
        ssum += v[i].x + v[i].y;
    }
    red[tid] = ssum; __syncthreads();
    for (int s = 128; s > 0; s >>= 1) { if (tid < s) red[tid] += red[tid + s]; __syncthreads(); }
    float inv = 1.f / red[0];
#pragma unroll
    for (int i = 0; i < 2; i++) {
        int c2 = (tid + i * 256) * 2;
        float x0 = v[i].x * inv, x1 = v[i].y * inv;
        __half h0 = __float2half_rn(x0), h1 = __float2half_rn(x1);
        *(__half2*)(dh + c2) = __halves2half2(h0, h1);
        *(__half2*)(dl + c2) = __halves2half2(
            __float2half_rn(x0 - __half2float(h0)), __float2half_rn(x1 - __half2float(h1)));
    }
}

// =====================================================================
// gemm_nn_mma: f_a = (Ah+Al) @ Bh^T
// =====================================================================
#define NKCH   (NN / KCH)
#define AT_BYTES (64 * RSTR)
#define BT_BYTES (128 * RSTR)
#define STG2_BYTES (2 * AT_BYTES + BT_BYTES)
#define PIPE4  4
#define GEMM2_SMEM (PIPE4 * STG2_BYTES)

__global__ __launch_bounds__(256) void gemm_nn_mma(
    const __half* __restrict__ Ahi, const __half* __restrict__ Alo,
    const __half* __restrict__ Bhi, float* __restrict__ Fg)
{
    extern __shared__ __align__(128) char smem[];
    uint32_t sbase = smem_u32(smem);
    int tid = threadIdx.x;
    int wid = tid >> 5, lane = tid & 31;
    int warp_m = wid & 1;
    int warp_n = wid >> 1;

    int b = blockIdx.y;
    int mrow0 = blockIdx.x * 64;

    const __half* Ah = Ahi + ((size_t)b * NN + mrow0) * NN;
    const __half* Al = Alo + ((size_t)b * NN + mrow0) * NN;
    const __half* Bh = Bhi + (size_t)b * 128 * NN;
    float* F = Fg + (size_t)b * NN * 128;

    float acc[2][4][4];
#pragma unroll
    for (int i = 0; i < 2; i++)
#pragma unroll
        for (int j = 0; j < 4; j++)
#pragma unroll
            for (int k = 0; k < 4; k++) acc[i][j][k] = 0.f;

    auto prefetch = [&](int c) {
        int kk = c * KCH;
        uint32_t stg = sbase + (c % PIPE4) * STG2_BYTES;
#pragma unroll
        for (int it = 0; it < 4; it++) {
            int idx = it * 256 + tid;
            if (idx < 512) {
                int pl = idx >> 8, w = idx & 255;
                int r = w >> 2, seg = w & 3;
                const __half* s = pl ? Al : Ah;
                cp_async16(stg + (uint32_t)(pl * AT_BYTES + r * RSTR + seg * 16),
                           s + (size_t)r * NN + kk + seg * 8);
            } else {
                int w = idx - 512;
                int r = w >> 2, seg = w & 3;
                cp_async16(stg + (uint32_t)(2 * AT_BYTES + r * RSTR + seg * 16),
                           Bh + (size_t)r * NN + kk + seg * 8);
            }
        }
    };

    prefetch(0); CP_COMMIT();
    prefetch(1); CP_COMMIT();

    int a_row = (lane & 7) + ((lane >> 3) & 1) * 8;
    int a_k8  = (lane >> 4) * 8;
    int bg    = lane >> 3;
    int b_nat = bg >> 1;
    int b_k8  = (bg & 1) * 8;

    for (int c = 0; c < NKCH; c++) {
        if (c + 2 < NKCH) prefetch(c + 2);
        CP_COMMIT();
        CP_WAIT(2);
        __syncthreads();

        uint32_t stg = sbase + (c % PIPE4) * STG2_BYTES;
        uint32_t sAh = stg, sAl = stg + AT_BYTES, sBh = stg + 2 * AT_BYTES;
#pragma unroll
        for (int k16 = 0; k16 < 2; k16++) {
            int kb = k16 * 16;
            uint32_t afh[2][4], afl[2][4];
#pragma unroll
            for (int am = 0; am < 2; am++) {
                uint32_t off = (uint32_t)((warp_m * 32 + am * 16 + a_row) * RSTR + (kb + a_k8) * 2);
                ldsm_x4(afh[am], sAh + off);
                ldsm_x4(afl[am], sAl + off);
            }
            uint32_t bfh[4][2];
#pragma unroll
            for (int bp = 0; bp < 2; bp++) {
                uint32_t boff = (uint32_t)((warp_n * 32 + (bp * 2 + b_nat) * 8 + (lane & 7)) * RSTR
                                           + (kb + b_k8) * 2);
                uint32_t r4[4];
                ldsm_x4(r4, sBh + boff);
                bfh[bp * 2 + 0][0] = r4[0]; bfh[bp * 2 + 0][1] = r4[1];
                bfh[bp * 2 + 1][0] = r4[2]; bfh[bp * 2 + 1][1] = r4[3];
            }
#pragma unroll
            for (int am = 0; am < 2; am++)
#pragma unroll
                for (int an = 0; an < 4; an++) {
                    mma16816(acc[am][an], afh[am], bfh[an]);
                    mma16816(acc[am][an], afl[am], bfh[an]);
                }
        }
    }

    int tr = lane >> 2, tc = (lane & 3) * 2;
#pragma unroll
    for (int am = 0; am < 2; am++)
#pragma unroll
        for (int an = 0; an < 4; an++) {
            int r = mrow0 + warp_m * 32 + am * 16 + tr;
            int cc = warp_n * 32 + an * 8 + tc;
            *(float2*)(F + (size_t)r * 128 + cc) = make_float2(acc[am][an][0], acc[am][an][1]);
            *(float2*)(F + (size_t)(r + 8) * 128 + cc) = make_float2(acc[am][an][2], acc[am][an][3]);
        }
}

// ------- templated 3x3 conv + bias + relu, NHWC (R8-proven, pyramid) -------
template <int TILE, int STRIDE, int CIN, int COSPLIT>
__global__ void conv2d_relu_t(
    const float* __restrict__ in, const float* __restrict__ w,
    const float* __restrict__ bias, float* __restrict__ out,
    int Hin, int Win, int Hout, int Wout, int Cout, int pad)
{
    constexpr int SPANX = (TILE - 1) * STRIDE + 3;
    extern __shared__ float sm[];
    int b = blockIdx.z;
    int oy = blockIdx.y;
    int xt = blockIdx.x / COSPLIT;
    int cs = blockIdx.x % COSPLIT;
    int ox0 = xt * TILE;
    int co = cs * blockDim.x + threadIdx.x;

    int iy0 = oy * STRIDE - pad;
    int ix0 = ox0 * STRIDE - pad;
    constexpr int TOT = 3 * SPANX * CIN;
    for (int i = threadIdx.x; i < TOT; i += blockDim.x) {
        int ci = i % CIN; int rest = i / CIN;
        int xx = rest % SPANX; int r = rest / SPANX;
        int iy = iy0 + r, ix = ix0 + xx;
        float v = 0.f;
        if (iy >= 0 && iy < Hin && ix >= 0 && ix < Win)
            v = in[(((size_t)b * Hin + iy) * Win + ix) * CIN + ci];
        sm[(r * SPANX + xx) * CIN + ci] = v;
    }
    __syncthreads();

    float acc[TILE];
    float bv = bias[co];
#pragma unroll
    for (int p = 0; p < TILE; p++) acc[p] = bv;

#pragma unroll
    for (int r = 0; r < 3; r++)
#pragma unroll
        for (int kx = 0; kx < 3; kx++) {
#pragma unroll 8
            for (int ci = 0; ci < CIN; ci++) {
                float wv = w[(size_t)((r * 3 + kx) * CIN + ci) * Cout + co];
                const float* srow = &sm[(r * SPANX + kx) * CIN + ci];
#pragma unroll
                for (int p = 0; p < TILE; p++)
                    acc[p] += srow[(size_t)p * STRIDE * CIN] * wv;
            }
        }
#pragma unroll
    for (int p = 0; p < TILE; p++) {
        int ox = ox0 + p;
        out[(((size_t)b * Hout + oy) * Wout + ox) * Cout + co] = fmaxf(acc[p], 0.f);
    }
}

// ---- conv2 NEW: weight-staged smem + 2-batch fusion, TRANSPOSED fp16 out ----
// block = (x-tile of 8 outputs) x (row oy) x (batch pair); 256 thr = 128 co x 2 bt
// weights: 9 slices of [64ci x 128co] staged via float4 coalesced loads
__global__ __launch_bounds__(256) void conv2_t_fp16_w(
    const float* __restrict__ in, const float* __restrict__ w,
    const float* __restrict__ bias, __half* __restrict__ out_hi)
{
    constexpr int TILE = 8, STRIDE = 2, SPANX = 17, CIN = 64, COUT = 128;
    extern __shared__ float sm[];
    float* smw = sm;                       // [64][128] weights slice (32768 B)
    float* smi = sm + CIN * COUT;          // [2][3][SPANX][64] inputs (2 batches)
    constexpr int ITILE = 3 * SPANX * CIN; // per-batch input tile floats (3264)

    int tid = threadIdx.x;
    int co = tid & 127;
    int bt2 = tid >> 7;                    // 0/1 within batch pair
    int oy = blockIdx.y;
    int ox0 = blockIdx.x * TILE;
    int bp = blockIdx.z;                   // batch pair 0..3

    int iy0 = oy * STRIDE;
    int ix0 = ox0 * STRIDE;
    // load both batches' input tiles
    for (int i = tid; i < 2 * ITILE; i += 256) {
        int bt = i / ITILE;
        int j = i % ITILE;
        int ci = j % CIN; int rest = j / CIN;
        int xx = rest % SPANX; int r = rest / SPANX;
        int iy = iy0 + r, ix = ix0 + xx;
        float v = 0.f;
        if (iy < 64 && ix < 64)
            v = in[(((size_t)(bp * 2 + bt) * 64 + iy) * 64 + ix) * CIN + ci];
        smi[bt * ITILE + (r * SPANX + xx) * CIN + ci] = v;
    }

    float acc[TILE];
    float bv = bias[co];
#pragma unroll
    for (int p = 0; p < TILE; p++) acc[p] = bv;

    const float* smin = smi + bt2 * ITILE;
#pragma unroll
    for (int r = 0; r < 3; r++)
#pragma unroll
        for (int kx = 0; kx < 3; kx++) {
            __syncthreads();               // protect smw reuse
            // stage weight slice [64ci][128co] - coalesced float4
            const float4* wsrc = (const float4*)(w + (size_t)((r * 3 + kx) * CIN) * COUT);
            float4* wdst = (float4*)smw;
            for (int i = tid; i < CIN * COUT / 4; i += 256) wdst[i] = wsrc[i];
            __syncthreads();
#pragma unroll 8
            for (int ci = 0; ci < CIN; ci++) {
                float wv = smw[ci * COUT + co];
                const float* srow = &smin[(r * SPANX + kx) * CIN + ci];
#pragma unroll
                for (int p = 0; p < TILE; p++)
                    acc[p] += srow[(size_t)p * STRIDE * CIN] * wv;
            }
        }
    __half* dh = out_hi + ((size_t)(bp * 2 + bt2) * COUT + co) * NN + oy * 32 + ox0;
#pragma unroll
    for (int p = 0; p < TILE; p++)
        dh[p] = __float2half_rn(fmaxf(acc[p], 0.f));
}

// ---------------- maxpool phase 1 (phase 2 fused into dense1) ----------------
__global__ void maxpool_p1(const float* __restrict__ t, float* __restrict__ mpp) {
    int b = blockIdx.z;
    int ns = blockIdx.y;
    int c = blockIdx.x * 256 + threadIdx.x;
    if (c >= CF) return;
    const float* src = t + ((size_t)b * NN + ns * 128) * CF + c;
    float m = -1e30f;
#pragma unroll 8
    for (int n = 0; n < 128; n++) m = fmaxf(m, src[(size_t)n * CF]);
    mpp[((size_t)ns * NB + b) * CF + c] = m;
}

// ---------------- dense1 (fused maxpool reduce): partials over K-slices ----------------
__global__ void dense1_p1(const float* __restrict__ mpp, const float* __restrict__ w,
                          float* __restrict__ d1p) {
    int ks = blockIdx.x;
    int b = blockIdx.y;
    int j = threadIdx.x;
    __shared__ float sm[248];
    for (int k = threadIdx.x; k < 248; k += 512) {
        int c = ks * 248 + k;
        float m = -1e30f;
#pragma unroll
        for (int ns = 0; ns < 8; ns++) m = fmaxf(m, mpp[((size_t)ns * NB + b) * CF + c]);
        sm[k] = m;
    }
    __syncthreads();
    float s = 0.f;
#pragma unroll 8
    for (int k = 0; k < 248; k++) s += sm[k] * w[(size_t)(ks * 248 + k) * 512 + j];
    d1p[((size_t)ks * NB + b) * 512 + j] = s;
}

// ---------------- dense2 (fused dense1 reduce + bias + relu) + logits ----------------
__global__ void dense2_p1(const float* __restrict__ d1p, const float* __restrict__ b1,
                          const float* __restrict__ w, const float* __restrict__ bias,
                          float* __restrict__ logits) {
    int jb = blockIdx.x;
    int b = blockIdx.y;
    int j = jb * 128 + threadIdx.x;
    __shared__ float sg[512];
    for (int k = threadIdx.x; k < 512; k += 128) {
        float s = b1[k];
#pragma unroll
        for (int ks = 0; ks < 8; ks++) s += d1p[((size_t)ks * NB + b) * 512 + k];
        sg[k] = fmaxf(s, 0.f);
    }
    __syncthreads();
    if (j >= NCLS) return;
    float s = bias[j];
#pragma unroll 8
    for (int k = 0; k < 512; k++) s += sg[k] * w[(size_t)k * NCLS + j];
    logits[b * NCLS + j] = s;
}
__global__ void softmax1000(const float* __restrict__ logits, float* __restrict__ out) {
    int b = blockIdx.x;
    const float* src = logits + b * NCLS;
    int tid = threadIdx.x;
    __shared__ float red[256];
    float m = -1e30f;
    for (int j = tid; j < NCLS; j += 256) m = fmaxf(m, src[j]);
    red[tid] = m; __syncthreads();
    for (int s = 128; s > 0; s >>= 1) { if (tid < s) red[tid] = fmaxf(red[tid], red[tid + s]); __syncthreads(); }
    m = red[0]; __syncthreads();
    float ssum = 0.f;
    for (int j = tid; j < NCLS; j += 256) ssum += __expf(src[j] - m);
    red[tid] = ssum; __syncthreads();
    for (int s = 128; s > 0; s >>= 1) { if (tid < s) red[tid] += red[tid + s]; __syncthreads(); }
    float inv = 1.f / red[0];
    for (int j = tid; j < NCLS; j += 256) out[b * NCLS + j] = __expf(src[j] - m) * inv;
}

// ---------------- launcher ----------------
extern "C" void kernel_launch(void* const* d_in, const int* in_sizes, int n_in,
                              void* d_out, int out_size) {
    const float* t_lum  = (const float*)d_in[0];
    const float* r_lum  = (const float*)d_in[1];
    const float* r_ab   = (const float*)d_in[2];
    const float* w_rab1 = (const float*)d_in[3];
    const float* b_rab1 = (const float*)d_in[4];
    const float* w_rab2 = (const float*)d_in[5];
    const float* b_rab2 = (const float*)d_in[6];
    const float* w_fa1  = (const float*)d_in[7];
    const float* b_fa1  = (const float*)d_in[8];
    const float* w_fa2  = (const float*)d_in[9];
    const float* b_fa2  = (const float*)d_in[10];
    const float* w_fa3  = (const float*)d_in[11];
    const float* b_fa3  = (const float*)d_in[12];
    const float* w_d1   = (const float*)d_in[13];
    const float* b_d1   = (const float*)d_in[14];
    const float* w_d2   = (const float*)d_in[15];
    const float* b_d2   = (const float*)d_in[16];

    __half *tnh, *tnl, *rnh, *Ahi, *Alo, *fTh;
    float *frab1, *fa, *mpp, *d1p, *logits;
    cudaGetSymbolAddress((void**)&tnh,    g_tn_hi);
    cudaGetSymbolAddress((void**)&tnl,    g_tn_lo);
    cudaGetSymbolAddress((void**)&rnh,    g_rn_hi);
    cudaGetSymbolAddress((void**)&Ahi,    g_A_hi);
    cudaGetSymbolAddress((void**)&Alo,    g_A_lo);
    cudaGetSymbolAddress((void**)&fTh,    g_frabT_hi);
    cudaGetSymbolAddress((void**)&frab1,  g_frab1);
    cudaGetSymbolAddress((void**)&fa,     g_fa);
    cudaGetSymbolAddress((void**)&mpp,    g_mpp);
    cudaGetSymbolAddress((void**)&d1p,    g_d1p);
    cudaGetSymbolAddress((void**)&logits, g_logits);

    cudaFuncSetAttribute(gemm_nt_mma, cudaFuncAttributeMaxDynamicSharedMemorySize, GEMM_SMEM);
    cudaFuncSetAttribute(gemm_nn_mma, cudaFuncAttributeMaxDynamicSharedMemorySize, GEMM2_SMEM);
    // conv2 smem: weights 32768 B + inputs 2*3264*4 B = 58880 B -> needs opt-in
    cudaFuncSetAttribute(conv2_t_fp16_w, cudaFuncAttributeMaxDynamicSharedMemorySize, 65536);

    float* out  = (float*)d_out;
    float* Cmat = out + 8000;
    float* s1   = out + 8396608;
    float* s2   = out + 8462144;
    float* s3   = out + 8593216;

    const int CONV2_SMEM = (64 * 128 + 2 * 3 * 17 * 64) * 4;   // 58880

    // 1: normalize r (hi only)
    normalize_split_h<<<NB * NN, 256>>>(r_lum, rnh);

    // 2: chroma conv1
    conv2d_relu_t<16, 1, 2, 1><<<dim3(4, 64, NB), 64, 3 * 18 * 2 * 4>>>(
        r_ab, w_rab1, b_rab1, frab1, 64, 64, 64, 64, 64, 1);

    // 3: normalize t (hi+lo)
    normalize_split_hl<<<NB * NN, 256>>>(t_lum, tnh, tnl);

    // 4: conv2 NEW (weight-staged, 2-batch fused)  <- PROFILE SLOT
    conv2_t_fp16_w<<<dim3(4, 32, 4), 256, CONV2_SMEM>>>(
        frab1, w_rab2, b_rab2, fTh);

    // 5: cost volume (HMMA rate-bound)
    gemm_nt_mma<<<dim3(8, 8, NB), 256, GEMM_SMEM>>>(tnh, tnl, rnh, Cmat);

    // 6: maxpool phase 1
    maxpool_p1<<<dim3(8, 8, NB), 256>>>(t_lum, mpp);

    // 7: softmax -> split-fp16
    softmax_split_rows<<<NB * NN, 256>>>(Cmat, Ahi, Alo);

    // 8: attention
    gemm_nn_mma<<<dim3(NN / 64, NB), 256, GEMM2_SMEM>>>(Ahi, Alo, fTh, fa);

    // 9-11: pyramid (R8-proven configs)
    conv2d_relu_t<4, 2, 128, 1><<<dim3(4, 16, NB), 128, 3 * 9 * 128 * 4>>>(
        fa, w_fa1, b_fa1, s3, 32, 32, 16, 16, 128, 0);
    conv2d_relu_t<4, 2, 128, 1><<<dim3(2, 8, NB), 256, 3 * 9 * 128 * 4>>>(
        s3, w_fa2, b_fa2, s2, 16, 16, 8, 8, 256, 0);
    conv2d_relu_t<2, 2, 256, 2><<<dim3(4, 4, NB), 256, 3 * 5 * 256 * 4>>>(
        s2, w_fa3, b_fa3, s1, 8, 8, 4, 4, 512, 0);

    // 12-14: classifier head (fused)
    dense1_p1<<<dim3(8, NB), 512>>>(mpp, w_d1, d1p);
    dense2_p1<<<dim3(8, NB), 128>>>(d1p, b_d1, w_d2, b_d2, logits);
    softmax1000<<<NB, 256>>>(logits, out);
}

// round 14
// speedup vs baseline: 1.4185x; 1.1070x over previous
#include <cuda_runtime.h>
#include <cuda_fp16.h>
#include <math.h>
#include <stdint.h>

#define CF   1984
#define NB   8
#define NN   1024    // h*w = 32*32
#define NCLS 1000

// ---------------- scratch (static device globals; no allocation) ----------------
__device__ __half g_tn_hi[NB * NN * CF];
__device__ __half g_tn_lo[NB * NN * CF];
__device__ __half g_rn_hi[NB * NN * CF];
__device__ __half g_A_hi[NB * NN * NN];
__device__ __half g_A_lo[NB * NN * NN];
__device__ __half g_frabT_hi[NB * 128 * NN];
__device__ float g_frab1[NB * 64 * 64 * 64];
__device__ float g_fa[NB * NN * 128];
__device__ float g_mpp[8 * NB * CF];     // maxpool partials [ns][b][c]
__device__ float g_d1p[8 * NB * 512];    // dense1 partials [ks][b][j]
__device__ float g_logits[NB * NCLS];

// ============================ helpers ============================
__device__ __forceinline__ uint32_t smem_u32(const void* p) {
    uint32_t a;
    asm("{ .reg .u64 t; cvta.to.shared.u64 t, %1; cvt.u32.u64 %0, t; }" : "=r"(a) : "l"(p));
    return a;
}
__device__ __forceinline__ void cp_async16(uint32_t dst, const void* src) {
    asm volatile("cp.async.cg.shared.global [%0], [%1], 16;" :: "r"(dst), "l"(src));
}
#define CP_COMMIT() asm volatile("cp.async.commit_group;" ::: "memory")
#define CP_WAIT(n)  asm volatile("cp.async.wait_group %0;" :: "n"(n) : "memory")

__device__ __forceinline__ void ldsm_x4(uint32_t* r, uint32_t addr) {
    asm volatile("ldmatrix.sync.aligned.m8n8.x4.shared.b16 {%0,%1,%2,%3}, [%4];"
                 : "=r"(r[0]), "=r"(r[1]), "=r"(r[2]), "=r"(r[3]) : "r"(addr));
}
__device__ __forceinline__ void mma16816(float* d, const uint32_t* a, const uint32_t* b) {
    asm volatile(
        "mma.sync.aligned.m16n8k16.row.col.f32.f16.f16.f32 "
        "{%0,%1,%2,%3}, {%4,%5,%6,%7}, {%8,%9}, {%0,%1,%2,%3};"
        : "+f"(d[0]), "+f"(d[1]), "+f"(d[2]), "+f"(d[3])
        : "r"(a[0]), "r"(a[1]), "r"(a[2]), "r"(a[3]), "r"(b[0]), "r"(b[1]));
}

// ---------------- normalize + fp16 hi/lo split ----------------
__global__ void normalize_split_hl(const float* __restrict__ in,
                                   __half* __restrict__ hi, __half* __restrict__ lo) {
    int row = blockIdx.x;
    const float4* src4 = (const float4*)(in + (size_t)row * CF);   // 496 float4
    __half* dh = hi + (size_t)row * CF;
    __half* dl = lo + (size_t)row * CF;
    int tid = threadIdx.x;
    float4 v[2];
    float ss = 0.f;
#pragma unroll
    for (int i = 0; i < 2; i++) {
        int c4 = tid + i * 256;
        if (c4 < 496) {
            v[i] = src4[c4];
            ss += v[i].x * v[i].x + v[i].y * v[i].y + v[i].z * v[i].z + v[i].w * v[i].w;
        } else v[i] = make_float4(0.f, 0.f, 0.f, 0.f);
    }
    __shared__ float red[256];
    red[tid] = ss; __syncthreads();
    for (int s = 128; s > 0; s >>= 1) {
        if (tid < s) red[tid] += red[tid + s];
        __syncthreads();
    }
    float inv = 1.f / (sqrtf(red[0]) + 1e-6f);
#pragma unroll
    for (int i = 0; i < 2; i++) {
        int c4 = tid + i * 256;
        if (c4 < 496) {
            float x0 = v[i].x * inv, x1 = v[i].y * inv, x2 = v[i].z * inv, x3 = v[i].w * inv;
            __half h0 = __float2half_rn(x0), h1 = __float2half_rn(x1);
            __half h2 = __float2half_rn(x2), h3 = __float2half_rn(x3);
            __half2 hh[2] = { __halves2half2(h0, h1), __halves2half2(h2, h3) };
            *(uint2*)(dh + c4 * 4) = *(uint2*)hh;
            __half2 ll[2] = {
                __halves2half2(__float2half_rn(x0 - __half2float(h0)),
                               __float2half_rn(x1 - __half2float(h1))),
                __halves2half2(__float2half_rn(x2 - __half2float(h2)),
                               __float2half_rn(x3 - __half2float(h3))) };
            *(uint2*)(dl + c4 * 4) = *(uint2*)ll;
        }
    }
}
__global__ void normalize_split_h(const float* __restrict__ in, __half* __restrict__ hi) {
    int row = blockIdx.x;
    const float4* src4 = (const float4*)(in + (size_t)row * CF);
    __half* dh = hi + (size_t)row * CF;
    int tid = threadIdx.x;
    float4 v[2];
    float ss = 0.f;
#pragma unroll
    for (int i = 0; i < 2; i++) {
        int c4 = tid + i * 256;
        if (c4 < 496) {
            v[i] = src4[c4];
            ss += v[i].x * v[i].x + v[i].y * v[i].y + v[i].z * v[i].z + v[i].w * v[i].w;
        } else v[i] = make_float4(0.f, 0.f, 0.f, 0.f);
    }
    __shared__ float red[256];
    red[tid] = ss; __syncthreads();
    for (int s = 128; s > 0; s >>= 1) {
        if (tid < s) red[tid] += red[tid + s];
        __syncthreads();
    }
    float inv = 1.f / (sqrtf(red[0]) + 1e-6f);
#pragma unroll
    for (int i = 0; i < 2; i++) {
        int c4 = tid + i * 256;
        if (c4 < 496) {
            __half2 hh[2] = {
                __halves2half2(__float2half_rn(v[i].x * inv), __float2half_rn(v[i].y * inv)),
                __halves2half2(__float2half_rn(v[i].z * inv), __float2half_rn(v[i].w * inv)) };
            *(uint2*)(dh + c4 * 4) = *(uint2*)hh;
        }
    }
}

// =====================================================================
// gemm_nt_mma: C = Ah*Bh^T + Al*Bh^T  (2-term fp16 split) [HMMA rate-bound]
// =====================================================================
#define KCH    32
#define NCH    (CF / KCH)        // 62
#define RSTR   80
#define TILE_BYTES (128 * RSTR)
#define STG_BYTES  (3 * TILE_BYTES)
#define PIPE3  3
#define GEMM_SMEM (PIPE3 * STG_BYTES)    // 92160

__global__ __launch_bounds__(256, 2) void gemm_nt_mma(
    const __half* __restrict__ Ahi, const __half* __restrict__ Alo,
    const __half* __restrict__ Bhi, float* __restrict__ Cg)
{
    extern __shared__ __align__(128) char smem[];
    uint32_t sbase = smem_u32(smem);
    int tid = threadIdx.x;
    int wid = tid >> 5, lane = tid & 31;
    int warp_m = wid & 1;
    int warp_n = wid >> 1;

    int b = blockIdx.z;
    int row0 = blockIdx.y * 128;
    int col0 = blockIdx.x * 128;

    const __half* srcs[3] = {
        Ahi + ((size_t)b * NN + row0) * CF,
        Alo + ((size_t)b * NN + row0) * CF,
        Bhi + ((size_t)b * NN + col0) * CF };
    float* C = Cg + (size_t)b * NN * NN;

    float acc[4][4][4];
#pragma unroll
    for (int i = 0; i < 4; i++)
#pragma unroll
        for (int j = 0; j < 4; j++)
#pragma unroll
            for (int k = 0; k < 4; k++) acc[i][j][k] = 0.f;

    auto prefetch = [&](int c) {
        int kk = c * KCH;
        uint32_t stg = sbase + (c % PIPE3) * STG_BYTES;
#pragma unroll
        for (int it = 0; it < 6; it++) {
            int idx = it * 256 + tid;
            int t = idx >> 9;
            int w = idx & 511;
            int r = w >> 2, seg = w & 3;
            cp_async16(stg + (uint32_t)(t * TILE_BYTES + r * RSTR + seg * 16),
                       srcs[t] + (size_t)r * CF + kk + seg * 8);
        }
    };

    prefetch(0); CP_COMMIT();
    prefetch(1); CP_COMMIT();

    int a_row = (lane & 7) + ((lane >> 3) & 1) * 8;
    int a_k8  = (lane >> 4) * 8;
    int bg    = lane >> 3;
    int b_nat = bg >> 1;
    int b_k8  = (bg & 1) * 8;

    for (int c = 0; c < NCH; c++) {
        CP_WAIT(1);
        __syncthreads();
        if (c + 2 < NCH) { prefetch(c + 2); CP_COMMIT(); }

        uint32_t stg = sbase + (c % PIPE3) * STG_BYTES;
        uint32_t sAh = stg, sAl = stg + TILE_BYTES, sBh = stg + 2 * TILE_BYTES;
#pragma unroll
        for (int k16 = 0; k16 < 2; k16++) {
            int kb = k16 * 16;
            uint32_t afh[4][4], afl[4][4];
#pragma unroll
            for (int am = 0; am < 4; am++) {
                uint32_t off = (uint32_t)((warp_m * 64 + am * 16 + a_row) * RSTR + (kb + a_k8) * 2);
                ldsm_x4(afh[am], sAh + off);
                ldsm_x4(afl[am], sAl + off);
            }
            uint32_t bfh[4][2];
#pragma unroll
            for (int bp = 0; bp < 2; bp++) {
                uint32_t boff = (uint32_t)((warp_n * 32 + (bp * 2 + b_nat) * 8 + (lane & 7)) * RSTR
                                           + (kb + b_k8) * 2);
                uint32_t r4[4];
                ldsm_x4(r4, sBh + boff);
                bfh[bp * 2 + 0][0] = r4[0]; bfh[bp * 2 + 0][1] = r4[1];
                bfh[bp * 2 + 1][0] = r4[2]; bfh[bp * 2 + 1][1] = r4[3];
            }
#pragma unroll
            for (int am = 0; am < 4; am++)
#pragma unroll
                for (int an = 0; an < 4; an++) {
                    mma16816(acc[am][an], afh[am], bfh[an]);
                    mma16816(acc[am][an], afl[am], bfh[an]);
                }
        }
    }

    int tr = lane >> 2, tc = (lane & 3) * 2;
#pragma unroll
    for (int am = 0; am < 4; am++)
#pragma unroll
        for (int an = 0; an < 4; an++) {
            int r = row0 + warp_m * 64 + am * 16 + tr;
            int cc = col0 + warp_n * 32 + an * 8 + tc;
            *(float2*)(C + (size_t)r * NN + cc) = make_float2(acc[am][an][0], acc[am][an][1]);
            *(float2*)(C + (size_t)(r + 8) * NN + cc) = make_float2(acc[am][an][2], acc[am][an][3]);
        }
}

// ---------------- row softmax, split-fp16 half2 output ----------------
__global__ void softmax_split_rows(const float* __restrict__ Cmat,
                                   __half* __restrict__ Ahi, __half* __restrict__ Alo) {
    int row = blockIdx.x;
    const float* src = Cmat + (size_t)row * NN;
    __half* dh = Ahi + (size_t)row * NN;
    __half* dl = Alo + (size_t)row * NN;
    int tid = threadIdx.x;
    float2 v[2];
    float m = -1e30f;
#pragma unroll
    for (int i = 0; i < 2; i++) {
        int c2 = (tid + i * 256) * 2;
        v[i] = *(const float2*)(src + c2);
        m = fmaxf(m, fmaxf(v[i].x, v[i].y));
    }
    __shared__ float red[256];
    red[tid] = m; __syncthreads();
    for (int s = 128; s > 0; s >>= 1) { if (tid < s) red[tid] = fmaxf(red[tid], red[tid + s]); __syncthreads(); }
    m = red[0]; __syncthreads();
    float ssum = 0.f;
#pragma unroll
    for (int i = 0; i < 2; i++) {
        v[i].x = __expf(v[i].x - m); v[i].y = __expf(v[i].y - m);
        ssum += v[i].x + v[i].y;
    }
    red[tid] = ssum; __syncthreads();
    for (int s = 128; s > 0; s >>= 1) { if (tid < s) red[tid] += red[tid + s]; __syncthreads(); }
    float inv = 1.f / red[0];
#pragma unroll
    for (int i = 0; i < 2; i++) {
        int c2 = (tid + i * 256) * 2;
        float x0 = v[i].x * inv, x1 = v[i].y * inv;
        __half h0 = __float2half_rn(x0), h1 = __float2half_rn(x1);
        *(__half2*)(dh + c2) = __halves2half2(h0, h1);
        *(__half2*)(dl + c2) = __halves2half2(
            __float2half_rn(x0 - __half2float(h0)), __float2half_rn(x1 - __half2float(h1)));
    }
}

// =====================================================================
// gemm_nn_mma: f_a = (Ah+Al) @ Bh^T
// =====================================================================
#define NKCH   (NN / KCH)
#define AT_BYTES (64 * RSTR)
#define BT_BYTES (128 * RSTR)
#define STG2_BYTES (2 * AT_BYTES + BT_BYTES)
#define PIPE4  4
#define GEMM2_SMEM (PIPE4 * STG2_BYTES)

__global__ __launch_bounds__(256) void gemm_nn_mma(
    const __half* __restrict__ Ahi, const __half* __restrict__ Alo,
    const __half* __restrict__ Bhi, float* __restrict__ Fg)
{
    extern __shared__ __align__(128) char smem[];
    uint32_t sbase = smem_u32(smem);
    int tid = threadIdx.x;
    int wid = tid >> 5, lane = tid & 31;
    int warp_m = wid & 1;
    int warp_n = wid >> 1;

    int b = blockIdx.y;
    int mrow0 = blockIdx.x * 64;

    const __half* Ah = Ahi + ((size_t)b * NN + mrow0) * NN;
    const __half* Al = Alo + ((size_t)b * NN + mrow0) * NN;
    const __half* Bh = Bhi + (size_t)b * 128 * NN;
    float* F = Fg + (size_t)b * NN * 128;

    float acc[2][4][4];
#pragma unroll
    for (int i = 0; i < 2; i++)
#pragma unroll
        for (int j = 0; j < 4; j++)
#pragma unroll
            for (int k = 0; k < 4; k++) acc[i][j][k] = 0.f;

    auto prefetch = [&](int c) {
        int kk = c * KCH;
        uint32_t stg = sbase + (c % PIPE4) * STG2_BYTES;
#pragma unroll
        for (int it = 0; it < 4; it++) {
            int idx = it * 256 + tid;
            if (idx < 512) {
                int pl = idx >> 8, w = idx & 255;
                int r = w >> 2, seg = w & 3;
                const __half* s = pl ? Al : Ah;
                cp_async16(stg + (uint32_t)(pl * AT_BYTES + r * RSTR + seg * 16),
                           s + (size_t)r * NN + kk + seg * 8);
            } else {
                int w = idx - 512;
                int r = w >> 2, seg = w & 3;
                cp_async16(stg + (uint32_t)(2 * AT_BYTES + r * RSTR + seg * 16),
                           Bh + (size_t)r * NN + kk + seg * 8);
            }
        }
    };

    prefetch(0); CP_COMMIT();
    prefetch(1); CP_COMMIT();

    int a_row = (lane & 7) + ((lane >> 3) & 1) * 8;
    int a_k8  = (lane >> 4) * 8;
    int bg    = lane >> 3;
    int b_nat = bg >> 1;
    int b_k8  = (bg & 1) * 8;

    for (int c = 0; c < NKCH; c++) {
        if (c + 2 < NKCH) prefetch(c + 2);
        CP_COMMIT();
        CP_WAIT(2);
        __syncthreads();

        uint32_t stg = sbase + (c % PIPE4) * STG2_BYTES;
        uint32_t sAh = stg, sAl = stg + AT_BYTES, sBh = stg + 2 * AT_BYTES;
#pragma unroll
        for (int k16 = 0; k16 < 2; k16++) {
            int kb = k16 * 16;
            uint32_t afh[2][4], afl[2][4];
#pragma unroll
            for (int am = 0; am < 2; am++) {
                uint32_t off = (uint32_t)((warp_m * 32 + am * 16 + a_row) * RSTR + (kb + a_k8) * 2);
                ldsm_x4(afh[am], sAh + off);
                ldsm_x4(afl[am], sAl + off);
            }
            uint32_t bfh[4][2];
#pragma unroll
            for (int bp = 0; bp < 2; bp++) {
                uint32_t boff = (uint32_t)((warp_n * 32 + (bp * 2 + b_nat) * 8 + (lane & 7)) * RSTR
                                           + (kb + b_k8) * 2);
                uint32_t r4[4];
                ldsm_x4(r4, sBh + boff);
                bfh[bp * 2 + 0][0] = r4[0]; bfh[bp * 2 + 0][1] = r4[1];
                bfh[bp * 2 + 1][0] = r4[2]; bfh[bp * 2 + 1][1] = r4[3];
            }
#pragma unroll
            for (int am = 0; am < 2; am++)
#pragma unroll
                for (int an = 0; an < 4; an++) {
                    mma16816(acc[am][an], afh[am], bfh[an]);
                    mma16816(acc[am][an], afl[am], bfh[an]);
                }
        }
    }

    int tr = lane >> 2, tc = (lane & 3) * 2;
#pragma unroll
    for (int am = 0; am < 2; am++)
#pragma unroll
        for (int an = 0; an < 4; an++) {
            int r = mrow0 + warp_m * 32 + am * 16 + tr;
            int cc = warp_n * 32 + an * 8 + tc;
            *(float2*)(F + (size_t)r * 128 + cc) = make_float2(acc[am][an][0], acc[am][an][1]);
            *(float2*)(F + (size_t)(r + 8) * 128 + cc) = make_float2(acc[am][an][2], acc[am][an][3]);
        }
}

// ------- conv1: Cin=2 (cheap, unchanged) -------
template <int TILE, int STRIDE, int CIN>
__global__ void conv2d_relu_t(
    const float* __restrict__ in, const float* __restrict__ w,
    const float* __restrict__ bias, float* __restrict__ out,
    int Hin, int Win, int Hout, int Wout, int Cout, int pad)
{
    constexpr int SPANX = (TILE - 1) * STRIDE + 3;
    extern __shared__ float sm[];
    int b = blockIdx.z;
    int oy = blockIdx.y;
    int ox0 = blockIdx.x * TILE;
    int co = threadIdx.x;

    int iy0 = oy * STRIDE - pad;
    int ix0 = ox0 * STRIDE - pad;
    constexpr int TOT = 3 * SPANX * CIN;
    for (int i = threadIdx.x; i < TOT; i += blockDim.x) {
        int ci = i % CIN; int rest = i / CIN;
        int xx = rest % SPANX; int r = rest / SPANX;
        int iy = iy0 + r, ix = ix0 + xx;
        float v = 0.f;
        if (iy >= 0 && iy < Hin && ix >= 0 && ix < Win)
            v = in[(((size_t)b * Hin + iy) * Win + ix) * CIN + ci];
        sm[(r * SPANX + xx) * CIN + ci] = v;
    }
    __syncthreads();

    float acc[TILE];
    float bv = bias[co];
#pragma unroll
    for (int p = 0; p < TILE; p++) acc[p] = bv;

#pragma unroll
    for (int r = 0; r < 3; r++)
#pragma unroll
        for (int kx = 0; kx < 3; kx++) {
#pragma unroll
            for (int ci = 0; ci < CIN; ci++) {
                float wv = w[(size_t)((r * 3 + kx) * CIN + ci) * Cout + co];
                const float* srow = &sm[(r * SPANX + kx) * CIN + ci];
#pragma unroll
                for (int p = 0; p < TILE; p++)
                    acc[p] += srow[(size_t)p * STRIDE * CIN] * wv;
            }
        }
#pragma unroll
    for (int p = 0; p < TILE; p++) {
        int ox = ox0 + p;
        out[(((size_t)b * Hout + oy) * Wout + ox) * Cout + co] = fmaxf(acc[p], 0.f);
    }
}

// =====================================================================
// conv_v4: vectorized conv. 128 thr = 64 co-threads x 2 batches.
// each co-thread computes co = cs*128+lane64 and +64 (conflict-free weight LDS),
// input read as float4 across ci (broadcast), weights staged in smem [ci][128].
// OUTMODE 0: float NHWC relu. OUTMODE 1: fp16 transposed [b][co][pos] (conv2).
// =====================================================================
template <int TILE, int STRIDE, int CIN, int CICH, int COSPLIT, int OUTMODE>
__global__ __launch_bounds__(128) void conv_v4(
    const float* __restrict__ in, const float* __restrict__ w,
    const float* __restrict__ bias, float* __restrict__ outf,
    __half* __restrict__ outh,
    int Hin, int Win, int Hout, int Wout, int Cout, int pad)
{
    constexpr int SPANX = (TILE - 1) * STRIDE + 3;
    constexpr int COBLK = 128;
    constexpr int NCK = CIN / CICH;
    constexpr int ITOT1 = 3 * SPANX * CICH;          // per-batch chunk floats
    extern __shared__ float sm[];
    float* smw = sm;                                  // [CICH][128]
    float* smi = sm + CICH * COBLK;                   // [2][ITOT1]

    int tid = threadIdx.x;
    int l64 = tid & 63;
    int bt2 = tid >> 6;                               // 0/1
    int xt = blockIdx.x / COSPLIT;
    int cs = blockIdx.x % COSPLIT;
    int oy = blockIdx.y;
    int bp = blockIdx.z;                              // batch pair
    int coA = cs * COBLK + l64;
    int coB = coA + 64;
    int ox0 = xt * TILE;
    int iy0 = oy * STRIDE - pad;
    int ix0 = ox0 * STRIDE - pad;

    float acc0[TILE], acc1[TILE];
    float bv0 = bias[coA], bv1 = bias[coB];
#pragma unroll
    for (int p = 0; p < TILE; p++) { acc0[p] = bv0; acc1[p] = bv1; }

    for (int ck = 0; ck < NCK; ck++) {
        __syncthreads();
        // stage inputs for both batches of this ci-chunk
        for (int i = tid; i < 2 * ITOT1; i += 128) {
            int bt = i / ITOT1, j = i % ITOT1;
            int ci = j % CICH; int rest = j / CICH;
            int xx = rest % SPANX; int r = rest / SPANX;
            int iy = iy0 + r, ix = ix0 + xx;
            float v = 0.f;
            if (iy >= 0 && iy < Hin && ix >= 0 && ix < Win)
                v = in[(((size_t)(bp * 2 + bt) * Hin + iy) * Win + ix) * CIN + ck * CICH + ci];
            smi[bt * ITOT1 + (r * SPANX + xx) * CICH + ci] = v;
        }
        const float* smin = smi + bt2 * ITOT1;
#pragma unroll
        for (int r = 0; r < 3; r++)
#pragma unroll
            for (int kx = 0; kx < 3; kx++) {
                __syncthreads();
                // stage weight slice [CICH][128] (natural layout, float4 coalesced)
                const float* wsrc = w + ((size_t)((r * 3 + kx) * CIN + ck * CICH)) * Cout
                                      + cs * COBLK;
                for (int i = tid; i < CICH * COBLK / 4; i += 128) {
                    int ci = i / (COBLK / 4), c4 = i % (COBLK / 4);
                    ((float4*)smw)[ci * (COBLK / 4) + c4] =
                        *(const float4*)(wsrc + (size_t)ci * Cout + c4 * 4);
                }
                __syncthreads();
#pragma unroll 4
                for (int c4 = 0; c4 < CICH / 4; c4++) {
                    float4 iv[TILE];
#pragma unroll
                    for (int p = 0; p < TILE; p++)
                        iv[p] = *(const float4*)&smin[(r * SPANX + kx + p * STRIDE) * CICH + c4 * 4];
                    float w0[4], w1[4];
#pragma unroll
                    for (int q = 0; q < 4; q++) {
                        w0[q] = smw[(c4 * 4 + q) * COBLK + l64];
                        w1[q] = smw[(c4 * 4 + q) * COBLK + l64 + 64];
                    }
#pragma unroll
                    for (int p = 0; p < TILE; p++) {
                        acc0[p] += iv[p].x * w0[0] + iv[p].y * w0[1]
                                 + iv[p].z * w0[2] + iv[p].w * w0[3];
                        acc1[p] += iv[p].x * w1[0] + iv[p].y * w1[1]
                                 + iv[p].z * w1[2] + iv[p].w * w1[3];
                    }
                }
            }
    }

    int b = bp * 2 + bt2;
    if (OUTMODE == 0) {
#pragma unroll
        for (int p = 0; p < TILE; p++) {
            size_t base = (((size_t)b * Hout + oy) * Wout + ox0 + p) * Cout;
            outf[base + coA] = fmaxf(acc0[p], 0.f);
            outf[base + coB] = fmaxf(acc1[p], 0.f);
        }
    } else {
        __half* dA = outh + ((size_t)b * Cout + coA) * NN + oy * Wout + ox0;
        __half* dB = outh + ((size_t)b * Cout + coB) * NN + oy * Wout + ox0;
#pragma unroll
        for (int p = 0; p < TILE; p++) {
            dA[p] = __float2half_rn(fmaxf(acc0[p], 0.f));
            dB[p] = __float2half_rn(fmaxf(acc1[p], 0.f));
        }
    }
}

// ---------------- maxpool phase 1 ----------------
__global__ void maxpool_p1(const float* __restrict__ t, float* __restrict__ mpp) {
    int b = blockIdx.z;
    int ns = blockIdx.y;
    int c = blockIdx.x * 256 + threadIdx.x;
    if (c >= CF) return;
    const float* src = t + ((size_t)b * NN + ns * 128) * CF + c;
    float m = -1e30f;
#pragma unroll 8
    for (int n = 0; n < 128; n++) m = fmaxf(m, src[(size_t)n * CF]);
    mpp[((size_t)ns * NB + b) * CF + c] = m;
}

// ---------------- dense1 (fused maxpool reduce) ----------------
__global__ void dense1_p1(const float* __restrict__ mpp, const float* __restrict__ w,
                          float* __restrict__ d1p) {
    int ks = blockIdx.x;
    int b = blockIdx.y;
    int j = threadIdx.x;
    __shared__ float sm[248];
    for (int k = threadIdx.x; k < 248; k += 512) {
        int c = ks * 248 + k;
        float m = -1e30f;
#pragma unroll
        for (int ns = 0; ns < 8; ns++) m = fmaxf(m, mpp[((size_t)ns * NB + b) * CF + c]);
        sm[k] = m;
    }
    __syncthreads();
    float s = 0.f;
#pragma unroll 8
    for (int k = 0; k < 248; k++) s += sm[k] * w[(size_t)(ks * 248 + k) * 512 + j];
    d1p[((size_t)ks * NB + b) * 512 + j] = s;
}

// ---------------- dense2 (fused dense1 reduce + bias + relu) + logits ----------------
__global__ void dense2_p1(const float* __restrict__ d1p, const float* __restrict__ b1,
                          const float* __restrict__ w, const float* __restrict__ bias,
                          float* __restrict__ logits) {
    int jb = blockIdx.x;
    int b = blockIdx.y;
    int j = jb * 128 + threadIdx.x;
    __shared__ float sg[512];
    for (int k = threadIdx.x; k < 512; k += 128) {
        float s = b1[k];
#pragma unroll
        for (int ks = 0; ks < 8; ks++) s += d1p[((size_t)ks * NB + b) * 512 + k];
        sg[k] = fmaxf(s, 0.f);
    }
    __syncthreads();
    if (j >= NCLS) return;
    float s = bias[j];
#pragma unroll 8
    for (int k = 0; k < 512; k++) s += sg[k] * w[(size_t)k * NCLS + j];
    logits[b * NCLS + j] = s;
}
__global__ void softmax1000(const float* __restrict__ logits, float* __restrict__ out) {
    int b = blockIdx.x;
    const float* src = logits + b * NCLS;
    int tid = threadIdx.x;
    __shared__ float red[256];
    float m = -1e30f;
    for (int j = tid; j < NCLS; j += 256) m = fmaxf(m, src[j]);
    red[tid] = m; __syncthreads();
    for (int s = 128; s > 0; s >>= 1) { if (tid < s) red[tid] = fmaxf(red[tid], red[tid + s]); __syncthreads(); }
    m = red[0]; __syncthreads();
    float ssum = 0.f;
    for (int j = tid; j < NCLS; j += 256) ssum += __expf(src[j] - m);
    red[tid] = ssum; __syncthreads();
    for (int s = 128; s > 0; s >>= 1) { if (tid < s) red[tid] += red[tid + s]; __syncthreads(); }
    float inv = 1.f / red[0];
    for (int j = tid; j < NCLS; j += 256) out[b * NCLS + j] = __expf(src[j] - m) * inv;
}

// ---------------- launcher ----------------
extern "C" void kernel_launch(void* const* d_in, const int* in_sizes, int n_in,
                              void* d_out, int out_size) {
    const float* t_lum  = (const float*)d_in[0];
    const float* r_lum  = (const float*)d_in[1];
    const float* r_ab   = (const float*)d_in[2];
    const float* w_rab1 = (const float*)d_in[3];
    const float* b_rab1 = (const float*)d_in[4];
    const float* w_rab2 = (const float*)d_in[5];
    const float* b_rab2 = (const float*)d_in[6];
    const float* w_fa1  = (const float*)d_in[7];
    const float* b_fa1  = (const float*)d_in[8];
    const float* w_fa2  = (const float*)d_in[9];
    const float* b_fa2  = (const float*)d_in[10];
    const float* w_fa3  = (const float*)d_in[11];
    const float* b_fa3  = (const float*)d_in[12];
    const float* w_d1   = (const float*)d_in[13];
    const float* b_d1   = (const float*)d_in[14];
    const float* w_d2   = (const float*)d_in[15];
    const float* b_d2   = (const float*)d_in[16];

    __half *tnh, *tnl, *rnh, *Ahi, *Alo, *fTh;
    float *frab1, *fa, *mpp, *d1p, *logits;
    cudaGetSymbolAddress((void**)&tnh,    g_tn_hi);
    cudaGetSymbolAddress((void**)&tnl,    g_tn_lo);
    cudaGetSymbolAddress((void**)&rnh,    g_rn_hi);
    cudaGetSymbolAddress((void**)&Ahi,    g_A_hi);
    cudaGetSymbolAddress((void**)&Alo,    g_A_lo);
    cudaGetSymbolAddress((void**)&fTh,    g_frabT_hi);
    cudaGetSymbolAddress((void**)&frab1,  g_frab1);
    cudaGetSymbolAddress((void**)&fa,     g_fa);
    cudaGetSymbolAddress((void**)&mpp,    g_mpp);
    cudaGetSymbolAddress((void**)&d1p,    g_d1p);
    cudaGetSymbolAddress((void**)&logits, g_logits);

    cudaFuncSetAttribute(gemm_nt_mma, cudaFuncAttributeMaxDynamicSharedMemorySize, GEMM_SMEM);
    cudaFuncSetAttribute(gemm_nn_mma, cudaFuncAttributeMaxDynamicSharedMemorySize, GEMM2_SMEM);

    // conv_v4 smem sizes
    const int SM_CONV2 = (64 * 128 + 2 * 3 * 17 * 64) * 4;   // 58880
    const int SM_FA12  = (64 * 128 + 2 * 3 * 9 * 64) * 4;    // 46592
    const int SM_FA3   = (64 * 128 + 2 * 3 * 5 * 64) * 4;    // 40448
    cudaFuncSetAttribute((void*)conv_v4<8, 2, 64, 64, 1, 1>,
                         cudaFuncAttributeMaxDynamicSharedMemorySize, SM_CONV2);
    cudaFuncSetAttribute((void*)conv_v4<4, 2, 128, 64, 1, 0>,
                         cudaFuncAttributeMaxDynamicSharedMemorySize, SM_FA12);
    cudaFuncSetAttribute((void*)conv_v4<4, 2, 128, 64, 2, 0>,
                         cudaFuncAttributeMaxDynamicSharedMemorySize, SM_FA12);
    cudaFuncSetAttribute((void*)conv_v4<2, 2, 256, 64, 4, 0>,
                         cudaFuncAttributeMaxDynamicSharedMemorySize, SM_FA3);

    float* out  = (float*)d_out;
    float* Cmat = out + 8000;
    float* s1   = out + 8396608;
    float* s2   = out + 8462144;
    float* s3   = out + 8593216;

    // 1: normalize r (hi only)
    normalize_split_h<<<NB * NN, 256>>>(r_lum, rnh);

    // 2: chroma conv1
    conv2d_relu_t<16, 1, 2><<<dim3(4, 64, NB), 64, 3 * 18 * 2 * 4>>>(
        r_ab, w_rab1, b_rab1, frab1, 64, 64, 64, 64, 64, 1);

    // 3: normalize t (hi+lo)
    normalize_split_hl<<<NB * NN, 256>>>(t_lum, tnh, tnl);

    // 4: conv2 vectorized -> transposed fp16  <- PROFILE SLOT
    conv_v4<8, 2, 64, 64, 1, 1><<<dim3(4, 32, 4), 128, SM_CONV2>>>(
        frab1, w_rab2, b_rab2, nullptr, fTh, 64, 64, 32, 32, 128, 0);

    // 5: cost volume (HMMA rate-bound)
    gemm_nt_mma<<<dim3(8, 8, NB), 256, GEMM_SMEM>>>(tnh, tnl, rnh, Cmat);

    // 6: maxpool phase 1
    maxpool_p1<<<dim3(8, 8, NB), 256>>>(t_lum, mpp);

    // 7: softmax -> split-fp16
    softmax_split_rows<<<NB * NN, 256>>>(Cmat, Ahi, Alo);

    // 8: attention
    gemm_nn_mma<<<dim3(NN / 64, NB), 256, GEMM2_SMEM>>>(Ahi, Alo, fTh, fa);

    // 9-11: pyramid, vectorized convs
    conv_v4<4, 2, 128, 64, 1, 0><<<dim3(4, 16, 4), 128, SM_FA12>>>(
        fa, w_fa1, b_fa1, s3, nullptr, 32, 32, 16, 16, 128, 0);
    conv_v4<4, 2, 128, 64, 2, 0><<<dim3(4, 8, 4), 128, SM_FA12>>>(
        s3, w_fa2, b_fa2, s2, nullptr, 16, 16, 8, 8, 256, 0);
    conv_v4<2, 2, 256, 64, 4, 0><<<dim3(8, 4, 4), 128, SM_FA3>>>(
        s2, w_fa3, b_fa3, s1, nullptr, 8, 8, 4, 4, 512, 0);

    // 12-14: classifier head (fused)
    dense1_p1<<<dim3(8, NB), 512>>>(mpp, w_d1, d1p);
    dense2_p1<<<dim3(8, NB), 128>>>(d1p, b_d1, w_d2, b_d2, logits);
    softmax1000<<<NB, 256>>>(logits, out);
}

// round 15
// speedup vs baseline: 1.7330x; 1.2217x over previous
#include <cuda_runtime.h>
#include <cuda_fp16.h>
#include <math.h>
#include <stdint.h>

#define CF   1984
#define NB   8
#define NN   1024    // h*w = 32*32
#define NCLS 1000

// ---------------- scratch (static device globals; no allocation) ----------------
__device__ __half g_tn_hi[NB * NN * CF];
__device__ __half g_rn_hi[NB * NN * CF];
__device__ __half g_A_hi[NB * NN * NN];
__device__ __half g_frabT_hi[NB * 128 * NN];
__device__ float g_frab1[NB * 64 * 64 * 64];
__device__ float g_fa[NB * NN * 128];
__device__ float g_mpp[8 * NB * CF];     // maxpool partials [ns][b][c]
__device__ float g_d1p[8 * NB * 512];    // dense1 partials [ks][b][j]
__device__ float g_logits[NB * NCLS];

// ============================ helpers ============================
__device__ __forceinline__ uint32_t smem_u32(const void* p) {
    uint32_t a;
    asm("{ .reg .u64 t; cvta.to.shared.u64 t, %1; cvt.u32.u64 %0, t; }" : "=r"(a) : "l"(p));
    return a;
}
__device__ __forceinline__ void cp_async16(uint32_t dst, const void* src) {
    asm volatile("cp.async.cg.shared.global [%0], [%1], 16;" :: "r"(dst), "l"(src));
}
#define CP_COMMIT() asm volatile("cp.async.commit_group;" ::: "memory")
#define CP_WAIT(n)  asm volatile("cp.async.wait_group %0;" :: "n"(n) : "memory")

__device__ __forceinline__ void ldsm_x4(uint32_t* r, uint32_t addr) {
    asm volatile("ldmatrix.sync.aligned.m8n8.x4.shared.b16 {%0,%1,%2,%3}, [%4];"
                 : "=r"(r[0]), "=r"(r[1]), "=r"(r[2]), "=r"(r[3]) : "r"(addr));
}
__device__ __forceinline__ void mma16816(float* d, const uint32_t* a, const uint32_t* b) {
    asm volatile(
        "mma.sync.aligned.m16n8k16.row.col.f32.f16.f16.f32 "
        "{%0,%1,%2,%3}, {%4,%5,%6,%7}, {%8,%9}, {%0,%1,%2,%3};"
        : "+f"(d[0]), "+f"(d[1]), "+f"(d[2]), "+f"(d[3])
        : "r"(a[0]), "r"(a[1]), "r"(a[2]), "r"(a[3]), "r"(b[0]), "r"(b[1]));
}

// ---------------- normalize -> fp16 (single plane) ----------------
__global__ void normalize_h(const float* __restrict__ in, __half* __restrict__ hi) {
    int row = blockIdx.x;
    const float4* src4 = (const float4*)(in + (size_t)row * CF);   // 496 float4
    __half* dh = hi + (size_t)row * CF;
    int tid = threadIdx.x;
    float4 v[2];
    float ss = 0.f;
#pragma unroll
    for (int i = 0; i < 2; i++) {
        int c4 = tid + i * 256;
        if (c4 < 496) {
            v[i] = src4[c4];
            ss += v[i].x * v[i].x + v[i].y * v[i].y + v[i].z * v[i].z + v[i].w * v[i].w;
        } else v[i] = make_float4(0.f, 0.f, 0.f, 0.f);
    }
    __shared__ float red[256];
    red[tid] = ss; __syncthreads();
    for (int s = 128; s > 0; s >>= 1) {
        if (tid < s) red[tid] += red[tid + s];
        __syncthreads();
    }
    float inv = 1.f / (sqrtf(red[0]) + 1e-6f);
#pragma unroll
    for (int i = 0; i < 2; i++) {
        int c4 = tid + i * 256;
        if (c4 < 496) {
            __half2 hh[2] = {
                __halves2half2(__float2half_rn(v[i].x * inv), __float2half_rn(v[i].y * inv)),
                __halves2half2(__float2half_rn(v[i].z * inv), __float2half_rn(v[i].w * inv)) };
            *(uint2*)(dh + c4 * 4) = *(uint2*)hh;
        }
    }
}

// =====================================================================
// gemm_nt_mma: C = Ah*Bh^T  (single-term fp16)  [HMMA rate-bound]
// PIPE=3, 2 CTAs/SM, single sync per chunk (R10-verified schedule)
// =====================================================================
#define KCH    32
#define NCH    (CF / KCH)        // 62
#define RSTR   80
#define TILE_BYTES (128 * RSTR)
#define STG_BYTES  (2 * TILE_BYTES)      // 20480: Ah, Bh
#define PIPE3  3
#define GEMM_SMEM (PIPE3 * STG_BYTES)    // 61440

__global__ __launch_bounds__(256, 2) void gemm_nt_mma(
    const __half* __restrict__ Ahi, const __half* __restrict__ Bhi,
    float* __restrict__ Cg)
{
    extern __shared__ __align__(128) char smem[];
    uint32_t sbase = smem_u32(smem);
    int tid = threadIdx.x;
    int wid = tid >> 5, lane = tid & 31;
    int warp_m = wid & 1;
    int warp_n = wid >> 1;

    int b = blockIdx.z;
    int row0 = blockIdx.y * 128;
    int col0 = blockIdx.x * 128;

    const __half* srcs[2] = {
        Ahi + ((size_t)b * NN + row0) * CF,
        Bhi + ((size_t)b * NN + col0) * CF };
    float* C = Cg + (size_t)b * NN * NN;

    float acc[4][4][4];
#pragma unroll
    for (int i = 0; i < 4; i++)
#pragma unroll
        for (int j = 0; j < 4; j++)
#pragma unroll
            for (int k = 0; k < 4; k++) acc[i][j][k] = 0.f;

    auto prefetch = [&](int c) {
        int kk = c * KCH;
        uint32_t stg = sbase + (c % PIPE3) * STG_BYTES;
#pragma unroll
        for (int it = 0; it < 4; it++) {
            int idx = it * 256 + tid;          // 0..1023
            int t = idx >> 9;                  // tile 0..1
            int w = idx & 511;
            int r = w >> 2, seg = w & 3;
            cp_async16(stg + (uint32_t)(t * TILE_BYTES + r * RSTR + seg * 16),
                       srcs[t] + (size_t)r * CF + kk + seg * 8);
        }
    };

    prefetch(0); CP_COMMIT();
    prefetch(1); CP_COMMIT();

    int a_row = (lane & 7) + ((lane >> 3) & 1) * 8;
    int a_k8  = (lane >> 4) * 8;
    int bg    = lane >> 3;
    int b_nat = bg >> 1;
    int b_k8  = (bg & 1) * 8;

    for (int c = 0; c < NCH; c++) {
        CP_WAIT(1);
        __syncthreads();
        if (c + 2 < NCH) { prefetch(c + 2); CP_COMMIT(); }

        uint32_t stg = sbase + (c % PIPE3) * STG_BYTES;
        uint32_t sAh = stg, sBh = stg + TILE_BYTES;
#pragma unroll
        for (int k16 = 0; k16 < 2; k16++) {
            int kb = k16 * 16;
            uint32_t afh[4][4];
#pragma unroll
            for (int am = 0; am < 4; am++) {
                uint32_t off = (uint32_t)((warp_m * 64 + am * 16 + a_row) * RSTR + (kb + a_k8) * 2);
                ldsm_x4(afh[am], sAh + off);
            }
            uint32_t bfh[4][2];
#pragma unroll
            for (int bp = 0; bp < 2; bp++) {
                uint32_t boff = (uint32_t)((warp_n * 32 + (bp * 2 + b_nat) * 8 + (lane & 7)) * RSTR
                                           + (kb + b_k8) * 2);
                uint32_t r4[4];
                ldsm_x4(r4, sBh + boff);
                bfh[bp * 2 + 0][0] = r4[0]; bfh[bp * 2 + 0][1] = r4[1];
                bfh[bp * 2 + 1][0] = r4[2]; bfh[bp * 2 + 1][1] = r4[3];
            }
#pragma unroll
            for (int am = 0; am < 4; am++)
#pragma unroll
                for (int an = 0; an < 4; an++)
                    mma16816(acc[am][an], afh[am], bfh[an]);
        }
    }

    int tr = lane >> 2, tc = (lane & 3) * 2;
#pragma unroll
    for (int am = 0; am < 4; am++)
#pragma unroll
        for (int an = 0; an < 4; an++) {
            int r = row0 + warp_m * 64 + am * 16 + tr;
            int cc = col0 + warp_n * 32 + an * 8 + tc;
            *(float2*)(C + (size_t)r * NN + cc) = make_float2(acc[am][an][0], acc[am][an][1]);
            *(float2*)(C + (size_t)(r + 8) * NN + cc) = make_float2(acc[am][an][2], acc[am][an][3]);
        }
}

// ---------------- row softmax -> fp16 (single plane) ----------------
__global__ void softmax_h(const float* __restrict__ Cmat, __half* __restrict__ Ahi) {
    int row = blockIdx.x;
    const float* src = Cmat + (size_t)row * NN;
    __half* dh = Ahi + (size_t)row * NN;
    int tid = threadIdx.x;
    float2 v[2];
    float m = -1e30f;
#pragma unroll
    for (int i = 0; i < 2; i++) {
        int c2 = (tid + i * 256) * 2;
        v[i] = *(const float2*)(src + c2);
        m = fmaxf(m, fmaxf(v[i].x, v[i].y));
    }
    __shared__ float red[256];
    red[tid] = m; __syncthreads();
    for (int s = 128; s > 0; s >>= 1) { if (tid < s) red[tid] = fmaxf(red[tid], red[tid + s]); __syncthreads(); }
    m = red[0]; __syncthreads();
    float ssum = 0.f;
#pragma unroll
    for (int i = 0; i < 2; i++) {
        v[i].x = __expf(v[i].x - m); v[i].y = __expf(v[i].y - m);
        ssum += v[i].x + v[i].y;
    }
    red[tid] = ssum; __syncthreads();
    for (int s = 128; s > 0; s >>= 1) { if (tid < s) red[tid] += red[tid + s]; __syncthreads(); }
    float inv = 1.f / red[0];
#pragma unroll
    for (int i = 0; i < 2; i++) {
        int c2 = (tid + i * 256) * 2;
        *(__half2*)(dh + c2) = __halves2half2(
            __float2half_rn(v[i].x * inv), __float2half_rn(v[i].y * inv));
    }
}

// =====================================================================
// gemm_nn_mma: f_a = Ah @ Bh^T  (single-term fp16)
// =====================================================================
#define NKCH   (NN / KCH)
#define AT_BYTES (64 * RSTR)
#define BT_BYTES (128 * RSTR)
#define STG2_BYTES (AT_BYTES + BT_BYTES)          // 15360
#define PIPE4  4
#define GEMM2_SMEM (PIPE4 * STG2_BYTES)           // 61440

__global__ __launch_bounds__(256) void gemm_nn_mma(
    const __half* __restrict__ Ahi, const __half* __restrict__ Bhi,
    float* __restrict__ Fg)
{
    extern __shared__ __align__(128) char smem[];
    uint32_t sbase = smem_u32(smem);
    int tid = threadIdx.x;
    int wid = tid >> 5, lane = tid & 31;
    int warp_m = wid & 1;
    int warp_n = wid >> 1;

    int b = blockIdx.y;
    int mrow0 = blockIdx.x * 64;

    const __half* Ah = Ahi + ((size_t)b * NN + mrow0) * NN;
    const __half* Bh = Bhi + (size_t)b * 128 * NN;
    float* F = Fg + (size_t)b * NN * 128;

    float acc[2][4][4];
#pragma unroll
    for (int i = 0; i < 2; i++)
#pragma unroll
        for (int j = 0; j < 4; j++)
#pragma unroll
            for (int k = 0; k < 4; k++) acc[i][j][k] = 0.f;

    auto prefetch = [&](int c) {
        int kk = c * KCH;
        uint32_t stg = sbase + (c % PIPE4) * STG2_BYTES;
#pragma unroll
        for (int it = 0; it < 3; it++) {
            int idx = it * 256 + tid;          // 0..767
            if (idx < 256) {                   // A: 64 rows x 4 segs
                int r = idx >> 2, seg = idx & 3;
                cp_async16(stg + (uint32_t)(r * RSTR + seg * 16),
                           Ah + (size_t)r * NN + kk + seg * 8);
            } else {                           // B: 128 rows x 4 segs
                int w = idx - 256;
                int r = w >> 2, seg = w & 3;
                cp_async16(stg + (uint32_t)(AT_BYTES + r * RSTR + seg * 16),
                           Bh + (size_t)r * NN + kk + seg * 8);
            }
        }
    };

    prefetch(0); CP_COMMIT();
    prefetch(1); CP_COMMIT();

    int a_row = (lane & 7) + ((lane >> 3) & 1) * 8;
    int a_k8  = (lane >> 4) * 8;
    int bg    = lane >> 3;
    int b_nat = bg >> 1;
    int b_k8  = (bg & 1) * 8;

    for (int c = 0; c < NKCH; c++) {
        if (c + 2 < NKCH) prefetch(c + 2);
        CP_COMMIT();
        CP_WAIT(2);
        __syncthreads();

        uint32_t stg = sbase + (c % PIPE4) * STG2_BYTES;
        uint32_t sAh = stg, sBh = stg + AT_BYTES;
#pragma unroll
        for (int k16 = 0; k16 < 2; k16++) {
            int kb = k16 * 16;
            uint32_t afh[2][4];
#pragma unroll
            for (int am = 0; am < 2; am++) {
                uint32_t off = (uint32_t)((warp_m * 32 + am * 16 + a_row) * RSTR + (kb + a_k8) * 2);
                ldsm_x4(afh[am], sAh + off);
            }
            uint32_t bfh[4][2];
#pragma unroll
            for (int bp = 0; bp < 2; bp++) {
                uint32_t boff = (uint32_t)((warp_n * 32 + (bp * 2 + b_nat) * 8 + (lane & 7)) * RSTR
                                           + (kb + b_k8) * 2);
                uint32_t r4[4];
                ldsm_x4(r4, sBh + boff);
                bfh[bp * 2 + 0][0] = r4[0]; bfh[bp * 2 + 0][1] = r4[1];
                bfh[bp * 2 + 1][0] = r4[2]; bfh[bp * 2 + 1][1] = r4[3];
            }
#pragma unroll
            for (int am = 0; am < 2; am++)
#pragma unroll
                for (int an = 0; an < 4; an++)
                    mma16816(acc[am][an], afh[am], bfh[an]);
        }
        __syncthreads();
    }

    int tr = lane >> 2, tc = (lane & 3) * 2;
#pragma unroll
    for (int am = 0; am < 2; am++)
#pragma unroll
        for (int an = 0; an < 4; an++) {
            int r = mrow0 + warp_m * 32 + am * 16 + tr;
            int cc = warp_n * 32 + an * 8 + tc;
            *(float2*)(F + (size_t)r * 128 + cc) = make_float2(acc[am][an][0], acc[am][an][1]);
            *(float2*)(F + (size_t)(r + 8) * 128 + cc) = make_float2(acc[am][an][2], acc[am][an][3]);
        }
}

// ------- conv1: Cin=2 (cheap) -------
template <int TILE, int STRIDE, int CIN>
__global__ void conv2d_relu_t(
    const float* __restrict__ in, const float* __restrict__ w,
    const float* __restrict__ bias, float* __restrict__ out,
    int Hin, int Win, int Hout, int Wout, int Cout, int pad)
{
    constexpr int SPANX = (TILE - 1) * STRIDE + 3;
    extern __shared__ float sm[];
    int b = blockIdx.z;
    int oy = blockIdx.y;
    int ox0 = blockIdx.x * TILE;
    int co = threadIdx.x;

    int iy0 = oy * STRIDE - pad;
    int ix0 = ox0 * STRIDE - pad;
    constexpr int TOT = 3 * SPANX * CIN;
    for (int i = threadIdx.x; i < TOT; i += blockDim.x) {
        int ci = i % CIN; int rest = i / CIN;
        int xx = rest % SPANX; int r = rest / SPANX;
        int iy = iy0 + r, ix = ix0 + xx;
        float v = 0.f;
        if (iy >= 0 && iy < Hin && ix >= 0 && ix < Win)
            v = in[(((size_t)b * Hin + iy) * Win + ix) * CIN + ci];
        sm[(r * SPANX + xx) * CIN + ci] = v;
    }
    __syncthreads();

    float acc[TILE];
    float bv = bias[co];
#pragma unroll
    for (int p = 0; p < TILE; p++) acc[p] = bv;

#pragma unroll
    for (int r = 0; r < 3; r++)
#pragma unroll
        for (int kx = 0; kx < 3; kx++) {
#pragma unroll
            for (int ci = 0; ci < CIN; ci++) {
                float wv = w[(size_t)((r * 3 + kx) * CIN + ci) * Cout + co];
                const float* srow = &sm[(r * SPANX + kx) * CIN + ci];
#pragma unroll
                for (int p = 0; p < TILE; p++)
                    acc[p] += srow[(size_t)p * STRIDE * CIN] * wv;
            }
        }
#pragma unroll
    for (int p = 0; p < TILE; p++) {
        int ox = ox0 + p;
        out[(((size_t)b * Hout + oy) * Wout + ox) * Cout + co] = fmaxf(acc[p], 0.f);
    }
}

// ---- conv2: stride-2 3x3, 64->128, TRANSPOSED fp16, TILE=8 (R8-proven, 81us) ----
__global__ void conv2_t_fp16(
    const float* __restrict__ in, const float* __restrict__ w,
    const float* __restrict__ bias, __half* __restrict__ out_hi)
{
    constexpr int TILE = 8, STRIDE = 2, SPANX = 17, CIN = 64, COUT = 128;
    extern __shared__ float sm[];
    int b = blockIdx.z;
    int oy = blockIdx.y;
    int ox0 = blockIdx.x * TILE;
    int co = threadIdx.x;

    int iy0 = oy * STRIDE;
    int ix0 = ox0 * STRIDE;
    constexpr int TOT = 3 * SPANX * CIN;
    for (int i = threadIdx.x; i < TOT; i += COUT) {
        int ci = i % CIN; int rest = i / CIN;
        int xx = rest % SPANX; int r = rest / SPANX;
        int iy = iy0 + r, ix = ix0 + xx;
        float v = 0.f;
        if (iy < 64 && ix < 64)
            v = in[(((size_t)b * 64 + iy) * 64 + ix) * CIN + ci];
        sm[(r * SPANX + xx) * CIN + ci] = v;
    }
    __syncthreads();

    float acc[TILE];
    float bv = bias[co];
#pragma unroll
    for (int p = 0; p < TILE; p++) acc[p] = bv;

#pragma unroll
    for (int r = 0; r < 3; r++)
#pragma unroll
        for (int kx = 0; kx < 3; kx++) {
#pragma unroll 8
            for (int ci = 0; ci < CIN; ci++) {
                float wv = w[(size_t)((r * 3 + kx) * CIN + ci) * COUT + co];
                const float* srow = &sm[(r * SPANX + kx) * CIN + ci];
#pragma unroll
                for (int p = 0; p < TILE; p++)
                    acc[p] += srow[(size_t)p * STRIDE * CIN] * wv;
            }
        }
    __half* dh = out_hi + ((size_t)b * COUT + co) * NN + oy * 32 + ox0;
#pragma unroll
    for (int p = 0; p < TILE; p++)
        dh[p] = __float2half_rn(fmaxf(acc[p], 0.f));
}

// =====================================================================
// conv_v4 (pyramid): 128 thr = 64 co-threads x 2 batches; weights staged smem
// =====================================================================
template <int TILE, int STRIDE, int CIN, int CICH, int COSPLIT, int OUTMODE>
__global__ __launch_bounds__(128) void conv_v4(
    const float* __restrict__ in, const float* __restrict__ w,
    const float* __restrict__ bias, float* __restrict__ outf,
    __half* __restrict__ outh,
    int Hin, int Win, int Hout, int Wout, int Cout, int pad)
{
    constexpr int SPANX = (TILE - 1) * STRIDE + 3;
    constexpr int COBLK = 128;
    constexpr int NCK = CIN / CICH;
    constexpr int ITOT1 = 3 * SPANX * CICH;
    extern __shared__ float sm[];
    float* smw = sm;                                  // [CICH][128]
    float* smi = sm + CICH * COBLK;                   // [2][ITOT1]

    int tid = threadIdx.x;
    int l64 = tid & 63;
    int bt2 = tid >> 6;
    int xt = blockIdx.x / COSPLIT;
    int cs = blockIdx.x % COSPLIT;
    int oy = blockIdx.y;
    int bp = blockIdx.z;
    int coA = cs * COBLK + l64;
    int coB = coA + 64;
    int ox0 = xt * TILE;
    int iy0 = oy * STRIDE - pad;
    int ix0 = ox0 * STRIDE - pad;

    float acc0[TILE], acc1[TILE];
    float bv0 = bias[coA], bv1 = bias[coB];
#pragma unroll
    for (int p = 0; p < TILE; p++) { acc0[p] = bv0; acc1[p] = bv1; }

    for (int ck = 0; ck < NCK; ck++) {
        __syncthreads();
        for (int i = tid; i < 2 * ITOT1; i += 128) {
            int bt = i / ITOT1, j = i % ITOT1;
            int ci = j % CICH; int rest = j / CICH;
            int xx = rest % SPANX; int r = rest / SPANX;
            int iy = iy0 + r, ix = ix0 + xx;
            float v = 0.f;
            if (iy >= 0 && iy < Hin && ix >= 0 && ix < Win)
                v = in[(((size_t)(bp * 2 + bt) * Hin + iy) * Win + ix) * CIN + ck * CICH + ci];
            smi[bt * ITOT1 + (r * SPANX + xx) * CICH + ci] = v;
        }
        const float* smin = smi + bt2 * ITOT1;
#pragma unroll
        for (int r = 0; r < 3; r++)
#pragma unroll
            for (int kx = 0; kx < 3; kx++) {
                __syncthreads();
                const float* wsrc = w + ((size_t)((r * 3 + kx) * CIN + ck * CICH)) * Cout
                                      + cs * COBLK;
                for (int i = tid; i < CICH * COBLK / 4; i += 128) {
                    int ci = i / (COBLK / 4), c4 = i % (COBLK / 4);
                    ((float4*)smw)[ci * (COBLK / 4) + c4] =
                        *(const float4*)(wsrc + (size_t)ci * Cout + c4 * 4);
                }
                __syncthreads();
#pragma unroll 4
                for (int c4 = 0; c4 < CICH / 4; c4++) {
                    float4 iv[TILE];
#pragma unroll
                    for (int p = 0; p < TILE; p++)
                        iv[p] = *(const float4*)&smin[(r * SPANX + kx + p * STRIDE) * CICH + c4 * 4];
                    float w0[4], w1[4];
#pragma unroll
                    for (int q = 0; q < 4; q++) {
                        w0[q] = smw[(c4 * 4 + q) * COBLK + l64];
                        w1[q] = smw[(c4 * 4 + q) * COBLK + l64 + 64];
                    }
#pragma unroll
                    for (int p = 0; p < TILE; p++) {
                        acc0[p] += iv[p].x * w0[0] + iv[p].y * w0[1]
                                 + iv[p].z * w0[2] + iv[p].w * w0[3];
                        acc1[p] += iv[p].x * w1[0] + iv[p].y * w1[1]
                                 + iv[p].z * w1[2] + iv[p].w * w1[3];
                    }
                }
            }
    }

    int b = bp * 2 + bt2;
    if (OUTMODE == 0) {
#pragma unroll
        for (int p = 0; p < TILE; p++) {
            size_t base = (((size_t)b * Hout + oy) * Wout + ox0 + p) * Cout;
            outf[base + coA] = fmaxf(acc0[p], 0.f);
            outf[base + coB] = fmaxf(acc1[p], 0.f);
        }
    } else {
        __half* dA = outh + ((size_t)b * Cout + coA) * NN + oy * Wout + ox0;
        __half* dB = outh + ((size_t)b * Cout + coB) * NN + oy * Wout + ox0;
#pragma unroll
        for (int p = 0; p < TILE; p++) {
            dA[p] = __float2half_rn(fmaxf(acc0[p], 0.f));
            dB[p] = __float2half_rn(fmaxf(acc1[p], 0.f));
        }
    }
}

// ---------------- maxpool phase 1 ----------------
__global__ void maxpool_p1(const float* __restrict__ t, float* __restrict__ mpp) {
    int b = blockIdx.z;
    int ns = blockIdx.y;
    int c = blockIdx.x * 256 + threadIdx.x;
    if (c >= CF) return;
    const float* src = t + ((size_t)b * NN + ns * 128) * CF + c;
    float m = -1e30f;
#pragma unroll 8
    for (int n = 0; n < 128; n++) m = fmaxf(m, src[(size_t)n * CF]);
    mpp[((size_t)ns * NB + b) * CF + c] = m;
}

// ---------------- dense1 (fused maxpool reduce) ----------------
__global__ void dense1_p1(const float* __restrict__ mpp, const float* __restrict__ w,
                          float* __restrict__ d1p) {
    int ks = blockIdx.x;
    int b = blockIdx.y;
    int j = threadIdx.x;
    __shared__ float sm[248];
    for (int k = threadIdx.x; k < 248; k += 512) {
        int c = ks * 248 + k;
        float m = -1e30f;
#pragma unroll
        for (int ns = 0; ns < 8; ns++) m = fmaxf(m, mpp[((size_t)ns * NB + b) * CF + c]);
        sm[k] = m;
    }
    __syncthreads();
    float s = 0.f;
#pragma unroll 8
    for (int k = 0; k < 248; k++) s += sm[k] * w[(size_t)(ks * 248 + k) * 512 + j];
    d1p[((size_t)ks * NB + b) * 512 + j] = s;
}

// ---------------- dense2 (fused dense1 reduce + bias + relu) + logits ----------------
__global__ void dense2_p1(const float* __restrict__ d1p, const float* __restrict__ b1,
                          const float* __restrict__ w, const float* __restrict__ bias,
                          float* __restrict__ logits) {
    int jb = blockIdx.x;
    int b = blockIdx.y;
    int j = jb * 128 + threadIdx.x;
    __shared__ float sg[512];
    for (int k = threadIdx.x; k < 512; k += 128) {
        float s = b1[k];
#pragma unroll
        for (int ks = 0; ks < 8; ks++) s += d1p[((size_t)ks * NB + b) * 512 + k];
        sg[k] = fmaxf(s, 0.f);
    }
    __syncthreads();
    if (j >= NCLS) return;
    float s = bias[j];
#pragma unroll 8
    for (int k = 0; k < 512; k++) s += sg[k] * w[(size_t)k * NCLS + j];
    logits[b * NCLS + j] = s;
}
__global__ void softmax1000(const float* __restrict__ logits, float* __restrict__ out) {
    int b = blockIdx.x;
    const float* src = logits + b * NCLS;
    int tid = threadIdx.x;
    __shared__ float red[256];
    float m = -1e30f;
    for (int j = tid; j < NCLS; j += 256) m = fmaxf(m, src[j]);
    red[tid] = m; __syncthreads();
    for (int s = 128; s > 0; s >>= 1) { if (tid < s) red[tid] = fmaxf(red[tid], red[tid + s]); __syncthreads(); }
    m = red[0]; __syncthreads();
    float ssum = 0.f;
    for (int j = tid; j < NCLS; j += 256) ssum += __expf(src[j] - m);
    red[tid] = ssum; __syncthreads();
    for (int s = 128; s > 0; s >>= 1) { if (tid < s) red[tid] += red[tid + s]; __syncthreads(); }
    float inv = 1.f / red[0];
    for (int j = tid; j < NCLS; j += 256) out[b * NCLS + j] = __expf(src[j] - m) * inv;
}

// ---------------- launcher ----------------
extern "C" void kernel_launch(void* const* d_in, const int* in_sizes, int n_in,
                              void* d_out, int out_size) {
    const float* t_lum  = (const float*)d_in[0];
    const float* r_lum  = (const float*)d_in[1];
    const float* r_ab   = (const float*)d_in[2];
    const float* w_rab1 = (const float*)d_in[3];
    const float* b_rab1 = (const float*)d_in[4];
    const float* w_rab2 = (const float*)d_in[5];
    const float* b_rab2 = (const float*)d_in[6];
    const float* w_fa1  = (const float*)d_in[7];
    const float* b_fa1  = (const float*)d_in[8];
    const float* w_fa2  = (const float*)d_in[9];
    const float* b_fa2  = (const float*)d_in[10];
    const float* w_fa3  = (const float*)d_in[11];
    const float* b_fa3  = (const float*)d_in[12];
    const float* w_d1   = (const float*)d_in[13];
    const float* b_d1   = (const float*)d_in[14];
    const float* w_d2   = (const float*)d_in[15];
    const float* b_d2   = (const float*)d_in[16];

    __half *tnh, *rnh, *Ahi, *fTh;
    float *frab1, *fa, *mpp, *d1p, *logits;
    cudaGetSymbolAddress((void**)&tnh,    g_tn_hi);
    cudaGetSymbolAddress((void**)&rnh,    g_rn_hi);
    cudaGetSymbolAddress((void**)&Ahi,    g_A_hi);
    cudaGetSymbolAddress((void**)&fTh,    g_frabT_hi);
    cudaGetSymbolAddress((void**)&frab1,  g_frab1);
    cudaGetSymbolAddress((void**)&fa,     g_fa);
    cudaGetSymbolAddress((void**)&mpp,    g_mpp);
    cudaGetSymbolAddress((void**)&d1p,    g_d1p);
    cudaGetSymbolAddress((void**)&logits, g_logits);

    cudaFuncSetAttribute(gemm_nt_mma, cudaFuncAttributeMaxDynamicSharedMemorySize, GEMM_SMEM);
    cudaFuncSetAttribute(gemm_nn_mma, cudaFuncAttributeMaxDynamicSharedMemorySize, GEMM2_SMEM);

    const int SM_FA12 = (64 * 128 + 2 * 3 * 9 * 64) * 4;    // 46592
    const int SM_FA3  = (64 * 128 + 2 * 3 * 5 * 64) * 4;    // 40448
    cudaFuncSetAttribute((void*)conv_v4<4, 2, 128, 64, 1, 0>,
                         cudaFuncAttributeMaxDynamicSharedMemorySize, SM_FA12);
    cudaFuncSetAttribute((void*)conv_v4<4, 2, 128, 64, 2, 0>,
                         cudaFuncAttributeMaxDynamicSharedMemorySize, SM_FA12);
    cudaFuncSetAttribute((void*)conv_v4<2, 2, 256, 64, 4, 0>,
                         cudaFuncAttributeMaxDynamicSharedMemorySize, SM_FA3);

    float* out  = (float*)d_out;
    float* Cmat = out + 8000;
    float* s1   = out + 8396608;
    float* s2   = out + 8462144;
    float* s3   = out + 8593216;

    // 1,2: normalize -> fp16
    normalize_h<<<NB * NN, 256>>>(r_lum, rnh);
    normalize_h<<<NB * NN, 256>>>(t_lum, tnh);

    // 3: chroma conv1
    conv2d_relu_t<16, 1, 2><<<dim3(4, 64, NB), 64, 3 * 18 * 2 * 4>>>(
        r_ab, w_rab1, b_rab1, frab1, 64, 64, 64, 64, 64, 1);

    // 4: cost volume C = tn @ rn^T (single-term fp16)  <- PROFILE SLOT
    gemm_nt_mma<<<dim3(8, 8, NB), 256, GEMM_SMEM>>>(tnh, rnh, Cmat);

    // 5: conv2 (R8-proven config)
    conv2_t_fp16<<<dim3(4, 32, NB), 128, 3 * 17 * 64 * 4>>>(
        frab1, w_rab2, b_rab2, fTh);

    // 6: softmax -> fp16
    softmax_h<<<NB * NN, 256>>>(Cmat, Ahi);

    // 7: attention (single-term fp16)
    gemm_nn_mma<<<dim3(NN / 64, NB), 256, GEMM2_SMEM>>>(Ahi, fTh, fa);

    // 8-10: pyramid (conv_v4, R14-proven)
    conv_v4<4, 2, 128, 64, 1, 0><<<dim3(4, 16, 4), 128, SM_FA12>>>(
        fa, w_fa1, b_fa1, s3, nullptr, 32, 32, 16, 16, 128, 0);
    conv_v4<4, 2, 128, 64, 2, 0><<<dim3(4, 8, 4), 128, SM_FA12>>>(
        s3, w_fa2, b_fa2, s2, nullptr, 16, 16, 8, 8, 256, 0);
    conv_v4<2, 2, 256, 64, 4, 0><<<dim3(8, 4, 4), 128, SM_FA3>>>(
        s2, w_fa3, b_fa3, s1, nullptr, 8, 8, 4, 4, 512, 0);

    // 11: maxpool phase 1
    maxpool_p1<<<dim3(8, 8, NB), 256>>>(t_lum, mpp);

    // 12-14: classifier head (fused)
    dense1_p1<<<dim3(8, NB), 512>>>(mpp, w_d1, d1p);
    dense2_p1<<<dim3(8, NB), 128>>>(d1p, b_d1, w_d2, b_d2, logits);
    softmax1000<<<NB, 256>>>(logits, out);
}

// round 16
// speedup vs baseline: 1.7599x; 1.0156x over previous
#include <cuda_runtime.h>
#include <cuda_fp16.h>
#include <math.h>
#include <stdint.h>

#define CF   1984
#define NB   8
#define NN   1024    // h*w = 32*32
#define NCLS 1000

// ---------------- scratch (static device globals; no allocation) ----------------
__device__ __half g_tn_hi[NB * NN * CF];
__device__ __half g_rn_hi[NB * NN * CF];
__device__ __half g_A_hi[NB * NN * NN];
__device__ __half g_frabT_hi[NB * 128 * NN];
__device__ float g_frab1[NB * 64 * 64 * 64];
__device__ float g_fa[NB * NN * 128];
__device__ float g_mpp[8 * NB * CF];
__device__ float g_d1p[8 * NB * 512];
__device__ float g_logits[NB * NCLS];

// ============================ helpers ============================
__device__ __forceinline__ uint32_t smem_u32(const void* p) {
    uint32_t a;
    asm("{ .reg .u64 t; cvta.to.shared.u64 t, %1; cvt.u32.u64 %0, t; }" : "=r"(a) : "l"(p));
    return a;
}
__device__ __forceinline__ void cp_async16(uint32_t dst, const void* src) {
    asm volatile("cp.async.cg.shared.global [%0], [%1], 16;" :: "r"(dst), "l"(src));
}
#define CP_COMMIT() asm volatile("cp.async.commit_group;" ::: "memory")
#define CP_WAIT(n)  asm volatile("cp.async.wait_group %0;" :: "n"(n) : "memory")

__device__ __forceinline__ void ldsm_x4(uint32_t* r, uint32_t addr) {
    asm volatile("ldmatrix.sync.aligned.m8n8.x4.shared.b16 {%0,%1,%2,%3}, [%4];"
                 : "=r"(r[0]), "=r"(r[1]), "=r"(r[2]), "=r"(r[3]) : "r"(addr));
}
__device__ __forceinline__ void mma16816(float* d, const uint32_t* a, const uint32_t* b) {
    asm volatile(
        "mma.sync.aligned.m16n8k16.row.col.f32.f16.f16.f32 "
        "{%0,%1,%2,%3}, {%4,%5,%6,%7}, {%8,%9}, {%0,%1,%2,%3};"
        : "+f"(d[0]), "+f"(d[1]), "+f"(d[2]), "+f"(d[3])
        : "r"(a[0]), "r"(a[1]), "r"(a[2]), "r"(a[3]), "r"(b[0]), "r"(b[1]));
}

// ---------------- normalize -> fp16 ----------------
__global__ void normalize_h(const float* __restrict__ in, __half* __restrict__ hi) {
    int row = blockIdx.x;
    const float4* src4 = (const float4*)(in + (size_t)row * CF);
    __half* dh = hi + (size_t)row * CF;
    int tid = threadIdx.x;
    float4 v[2];
    float ss = 0.f;
#pragma unroll
    for (int i = 0; i < 2; i++) {
        int c4 = tid + i * 256;
        if (c4 < 496) {
            v[i] = src4[c4];
            ss += v[i].x * v[i].x + v[i].y * v[i].y + v[i].z * v[i].z + v[i].w * v[i].w;
        } else v[i] = make_float4(0.f, 0.f, 0.f, 0.f);
    }
    __shared__ float red[256];
    red[tid] = ss; __syncthreads();
    for (int s = 128; s > 0; s >>= 1) {
        if (tid < s) red[tid] += red[tid + s];
        __syncthreads();
    }
    float inv = 1.f / (sqrtf(red[0]) + 1e-6f);
#pragma unroll
    for (int i = 0; i < 2; i++) {
        int c4 = tid + i * 256;
        if (c4 < 496) {
            __half2 hh[2] = {
                __halves2half2(__float2half_rn(v[i].x * inv), __float2half_rn(v[i].y * inv)),
                __halves2half2(__float2half_rn(v[i].z * inv), __float2half_rn(v[i].w * inv)) };
            *(uint2*)(dh + c4 * 4) = *(uint2*)hh;
        }
    }
}

// =====================================================================
// gemm_nt_mma: C = Ah*Bh^T  (single-term fp16), KCH=64, PIPE=3, 2 CTAs/SM
// =====================================================================
#define KCHN   64
#define NCHN   (CF / KCHN)       // 31
#define RSTN   144               // 128B row + 16B pad (conflict-free ldmatrix)
#define TILEB_N (128 * RSTN)     // 18432
#define STGB_N  (2 * TILEB_N)    // 36864
#define PIPE3  3
#define GEMM_SMEM (PIPE3 * STGB_N)   // 110592

__global__ __launch_bounds__(256, 2) void gemm_nt_mma(
    const __half* __restrict__ Ahi, const __half* __restrict__ Bhi,
    float* __restrict__ Cg)
{
    extern __shared__ __align__(128) char smem[];
    uint32_t sbase = smem_u32(smem);
    int tid = threadIdx.x;
    int wid = tid >> 5, lane = tid & 31;
    int warp_m = wid & 1;
    int warp_n = wid >> 1;

    int b = blockIdx.z;
    int row0 = blockIdx.y * 128;
    int col0 = blockIdx.x * 128;

    const __half* srcs[2] = {
        Ahi + ((size_t)b * NN + row0) * CF,
        Bhi + ((size_t)b * NN + col0) * CF };
    float* C = Cg + (size_t)b * NN * NN;

    float acc[4][4][4];
#pragma unroll
    for (int i = 0; i < 4; i++)
#pragma unroll
        for (int j = 0; j < 4; j++)
#pragma unroll
            for (int k = 0; k < 4; k++) acc[i][j][k] = 0.f;

    auto prefetch = [&](int c) {
        int kk = c * KCHN;
        uint32_t stg = sbase + (c % PIPE3) * STGB_N;
#pragma unroll
        for (int it = 0; it < 8; it++) {
            int idx = it * 256 + tid;          // 0..2047
            int t = idx >> 10;                 // tile 0..1
            int w = idx & 1023;
            int r = w >> 3, seg = w & 7;       // row 0..127, 16B seg 0..7
            cp_async16(stg + (uint32_t)(t * TILEB_N + r * RSTN + seg * 16),
                       srcs[t] + (size_t)r * CF + kk + seg * 8);
        }
    };

    prefetch(0); CP_COMMIT();
    prefetch(1); CP_COMMIT();

    int a_row = (lane & 7) + ((lane >> 3) & 1) * 8;
    int a_k8  = (lane >> 4) * 8;
    int bg    = lane >> 3;
    int b_nat = bg >> 1;
    int b_k8  = (bg & 1) * 8;

    for (int c = 0; c < NCHN; c++) {
        CP_WAIT(1);
        __syncthreads();
        if (c + 2 < NCHN) { prefetch(c + 2); CP_COMMIT(); }

        uint32_t stg = sbase + (c % PIPE3) * STGB_N;
        uint32_t sAh = stg, sBh = stg + TILEB_N;
#pragma unroll
        for (int k16 = 0; k16 < 4; k16++) {
            int kb = k16 * 16;
            uint32_t afh[4][4];
#pragma unroll
            for (int am = 0; am < 4; am++) {
                uint32_t off = (uint32_t)((warp_m * 64 + am * 16 + a_row) * RSTN + (kb + a_k8) * 2);
                ldsm_x4(afh[am], sAh + off);
            }
            uint32_t bfh[4][2];
#pragma unroll
            for (int bp = 0; bp < 2; bp++) {
                uint32_t boff = (uint32_t)((warp_n * 32 + (bp * 2 + b_nat) * 8 + (lane & 7)) * RSTN
                                           + (kb + b_k8) * 2);
                uint32_t r4[4];
                ldsm_x4(r4, sBh + boff);
                bfh[bp * 2 + 0][0] = r4[0]; bfh[bp * 2 + 0][1] = r4[1];
                bfh[bp * 2 + 1][0] = r4[2]; bfh[bp * 2 + 1][1] = r4[3];
            }
#pragma unroll
            for (int am = 0; am < 4; am++)
#pragma unroll
                for (int an = 0; an < 4; an++)
                    mma16816(acc[am][an], afh[am], bfh[an]);
        }
    }

    int tr = lane >> 2, tc = (lane & 3) * 2;
#pragma unroll
    for (int am = 0; am < 4; am++)
#pragma unroll
        for (int an = 0; an < 4; an++) {
            int r = row0 + warp_m * 64 + am * 16 + tr;
            int cc = col0 + warp_n * 32 + an * 8 + tc;
            *(float2*)(C + (size_t)r * NN + cc) = make_float2(acc[am][an][0], acc[am][an][1]);
            *(float2*)(C + (size_t)(r + 8) * NN + cc) = make_float2(acc[am][an][2], acc[am][an][3]);
        }
}

// ---------------- row softmax -> fp16 ----------------
__global__ void softmax_h(const float* __restrict__ Cmat, __half* __restrict__ Ahi) {
    int row = blockIdx.x;
    const float* src = Cmat + (size_t)row * NN;
    __half* dh = Ahi + (size_t)row * NN;
    int tid = threadIdx.x;
    float2 v[2];
    float m = -1e30f;
#pragma unroll
    for (int i = 0; i < 2; i++) {
        int c2 = (tid + i * 256) * 2;
        v[i] = *(const float2*)(src + c2);
        m = fmaxf(m, fmaxf(v[i].x, v[i].y));
    }
    __shared__ float red[256];
    red[tid] = m; __syncthreads();
    for (int s = 128; s > 0; s >>= 1) { if (tid < s) red[tid] = fmaxf(red[tid], red[tid + s]); __syncthreads(); }
    m = red[0]; __syncthreads();
    float ssum = 0.f;
#pragma unroll
    for (int i = 0; i < 2; i++) {
        v[i].x = __expf(v[i].x - m); v[i].y = __expf(v[i].y - m);
        ssum += v[i].x + v[i].y;
    }
    red[tid] = ssum; __syncthreads();
    for (int s = 128; s > 0; s >>= 1) { if (tid < s) red[tid] += red[tid + s]; __syncthreads(); }
    float inv = 1.f / red[0];
#pragma unroll
    for (int i = 0; i < 2; i++) {
        int c2 = (tid + i * 256) * 2;
        *(__half2*)(dh + c2) = __halves2half2(
            __float2half_rn(v[i].x * inv), __float2half_rn(v[i].y * inv));
    }
}

// =====================================================================
// gemm_nn_mma: f_a = Ah @ Bh^T  (single-term fp16), KCH=32, PIPE=4
// =====================================================================
#define KCH    32
#define NKCH   (NN / KCH)
#define RSTR   80
#define AT_BYTES (64 * RSTR)
#define BT_BYTES (128 * RSTR)
#define STG2_BYTES (AT_BYTES + BT_BYTES)
#define PIPE4  4
#define GEMM2_SMEM (PIPE4 * STG2_BYTES)

__global__ __launch_bounds__(256) void gemm_nn_mma(
    const __half* __restrict__ Ahi, const __half* __restrict__ Bhi,
    float* __restrict__ Fg)
{
    extern __shared__ __align__(128) char smem[];
    uint32_t sbase = smem_u32(smem);
    int tid = threadIdx.x;
    int wid = tid >> 5, lane = tid & 31;
    int warp_m = wid & 1;
    int warp_n = wid >> 1;

    int b = blockIdx.y;
    int mrow0 = blockIdx.x * 64;

    const __half* Ah = Ahi + ((size_t)b * NN + mrow0) * NN;
    const __half* Bh = Bhi + (size_t)b * 128 * NN;
    float* F = Fg + (size_t)b * NN * 128;

    float acc[2][4][4];
#pragma unroll
    for (int i = 0; i < 2; i++)
#pragma unroll
        for (int j = 0; j < 4; j++)
#pragma unroll
            for (int k = 0; k < 4; k++) acc[i][j][k] = 0.f;

    auto prefetch = [&](int c) {
        int kk = c * KCH;
        uint32_t stg = sbase + (c % PIPE4) * STG2_BYTES;
#pragma unroll
        for (int it = 0; it < 3; it++) {
            int idx = it * 256 + tid;
            if (idx < 256) {
                int r = idx >> 2, seg = idx & 3;
                cp_async16(stg + (uint32_t)(r * RSTR + seg * 16),
                           Ah + (size_t)r * NN + kk + seg * 8);
            } else {
                int w = idx - 256;
                int r = w >> 2, seg = w & 3;
                cp_async16(stg + (uint32_t)(AT_BYTES + r * RSTR + seg * 16),
                           Bh + (size_t)r * NN + kk + seg * 8);
            }
        }
    };

    prefetch(0); CP_COMMIT();
    prefetch(1); CP_COMMIT();

    int a_row = (lane & 7) + ((lane >> 3) & 1) * 8;
    int a_k8  = (lane >> 4) * 8;
    int bg    = lane >> 3;
    int b_nat = bg >> 1;
    int b_k8  = (bg & 1) * 8;

    for (int c = 0; c < NKCH; c++) {
        if (c + 2 < NKCH) prefetch(c + 2);
        CP_COMMIT();
        CP_WAIT(2);
        __syncthreads();

        uint32_t stg = sbase + (c % PIPE4) * STG2_BYTES;
        uint32_t sAh = stg, sBh = stg + AT_BYTES;
#pragma unroll
        for (int k16 = 0; k16 < 2; k16++) {
            int kb = k16 * 16;
            uint32_t afh[2][4];
#pragma unroll
            for (int am = 0; am < 2; am++) {
                uint32_t off = (uint32_t)((warp_m * 32 + am * 16 + a_row) * RSTR + (kb + a_k8) * 2);
                ldsm_x4(afh[am], sAh + off);
            }
            uint32_t bfh[4][2];
#pragma unroll
            for (int bp = 0; bp < 2; bp++) {
                uint32_t boff = (uint32_t)((warp_n * 32 + (bp * 2 + b_nat) * 8 + (lane & 7)) * RSTR
                                           + (kb + b_k8) * 2);
                uint32_t r4[4];
                ldsm_x4(r4, sBh + boff);
                bfh[bp * 2 + 0][0] = r4[0]; bfh[bp * 2 + 0][1] = r4[1];
                bfh[bp * 2 + 1][0] = r4[2]; bfh[bp * 2 + 1][1] = r4[3];
            }
#pragma unroll
            for (int am = 0; am < 2; am++)
#pragma unroll
                for (int an = 0; an < 4; an++)
                    mma16816(acc[am][an], afh[am], bfh[an]);
        }
        __syncthreads();
    }

    int tr = lane >> 2, tc = (lane & 3) * 2;
#pragma unroll
    for (int am = 0; am < 2; am++)
#pragma unroll
        for (int an = 0; an < 4; an++) {
            int r = mrow0 + warp_m * 32 + am * 16 + tr;
            int cc = warp_n * 32 + an * 8 + tc;
            *(float2*)(F + (size_t)r * 128 + cc) = make_float2(acc[am][an][0], acc[am][an][1]);
            *(float2*)(F + (size_t)(r + 8) * 128 + cc) = make_float2(acc[am][an][2], acc[am][an][3]);
        }
}

// ------- conv1: Cin=2 (cheap) -------
template <int TILE, int STRIDE, int CIN>
__global__ void conv2d_relu_t(
    const float* __restrict__ in, const float* __restrict__ w,
    const float* __restrict__ bias, float* __restrict__ out,
    int Hin, int Win, int Hout, int Wout, int Cout, int pad)
{
    constexpr int SPANX = (TILE - 1) * STRIDE + 3;
    extern __shared__ float sm[];
    int b = blockIdx.z;
    int oy = blockIdx.y;
    int ox0 = blockIdx.x * TILE;
    int co = threadIdx.x;

    int iy0 = oy * STRIDE - pad;
    int ix0 = ox0 * STRIDE - pad;
    constexpr int TOT = 3 * SPANX * CIN;
    for (int i = threadIdx.x; i < TOT; i += blockDim.x) {
        int ci = i % CIN; int rest = i / CIN;
        int xx = rest % SPANX; int r = rest / SPANX;
        int iy = iy0 + r, ix = ix0 + xx;
        float v = 0.f;
        if (iy >= 0 && iy < Hin && ix >= 0 && ix < Win)
            v = in[(((size_t)b * Hin + iy) * Win + ix) * CIN + ci];
        sm[(r * SPANX + xx) * CIN + ci] = v;
    }
    __syncthreads();

    float acc[TILE];
    float bv = bias[co];
#pragma unroll
    for (int p = 0; p < TILE; p++) acc[p] = bv;

#pragma unroll
    for (int r = 0; r < 3; r++)
#pragma unroll
        for (int kx = 0; kx < 3; kx++) {
#pragma unroll
            for (int ci = 0; ci < CIN; ci++) {
                float wv = w[(size_t)((r * 3 + kx) * CIN + ci) * Cout + co];
                const float* srow = &sm[(r * SPANX + kx) * CIN + ci];
#pragma unroll
                for (int p = 0; p < TILE; p++)
                    acc[p] += srow[(size_t)p * STRIDE * CIN] * wv;
            }
        }
#pragma unroll
    for (int p = 0; p < TILE; p++) {
        int ox = ox0 + p;
        out[(((size_t)b * Hout + oy) * Wout + ox) * Cout + co] = fmaxf(acc[p], 0.f);
    }
}

// ---- conv2: R8 structure + float4 smem input reads ----
__global__ void conv2_t_fp16(
    const float* __restrict__ in, const float* __restrict__ w,
    const float* __restrict__ bias, __half* __restrict__ out_hi)
{
    constexpr int TILE = 8, STRIDE = 2, SPANX = 17, CIN = 64, COUT = 128;
    extern __shared__ float sm[];
    int b = blockIdx.z;
    int oy = blockIdx.y;
    int ox0 = blockIdx.x * TILE;
    int co = threadIdx.x;

    int iy0 = oy * STRIDE;
    int ix0 = ox0 * STRIDE;
    constexpr int TOT = 3 * SPANX * CIN;
    for (int i = threadIdx.x; i < TOT; i += COUT) {
        int ci = i % CIN; int rest = i / CIN;
        int xx = rest % SPANX; int r = rest / SPANX;
        int iy = iy0 + r, ix = ix0 + xx;
        float v = 0.f;
        if (iy < 64 && ix < 64)
            v = in[(((size_t)b * 64 + iy) * 64 + ix) * CIN + ci];
        sm[(r * SPANX + xx) * CIN + ci] = v;
    }
    __syncthreads();

    float acc[TILE];
    float bv = bias[co];
#pragma unroll
    for (int p = 0; p < TILE; p++) acc[p] = bv;

#pragma unroll
    for (int r = 0; r < 3; r++)
#pragma unroll
        for (int kx = 0; kx < 3; kx++) {
            const float* base = &sm[(r * SPANX + kx) * CIN];
#pragma unroll 4
            for (int c4 = 0; c4 < CIN / 4; c4++) {
                float w0 = w[(size_t)((r * 3 + kx) * CIN + c4 * 4 + 0) * COUT + co];
                float w1 = w[(size_t)((r * 3 + kx) * CIN + c4 * 4 + 1) * COUT + co];
                float w2 = w[(size_t)((r * 3 + kx) * CIN + c4 * 4 + 2) * COUT + co];
                float w3 = w[(size_t)((r * 3 + kx) * CIN + c4 * 4 + 3) * COUT + co];
#pragma unroll
                for (int p = 0; p < TILE; p++) {
                    float4 iv = *(const float4*)(base + (size_t)p * STRIDE * CIN + c4 * 4);
                    acc[p] += iv.x * w0 + iv.y * w1 + iv.z * w2 + iv.w * w3;
                }
            }
        }
    __half* dh = out_hi + ((size_t)b * COUT + co) * NN + oy * 32 + ox0;
#pragma unroll
    for (int p = 0; p < TILE; p++)
        dh[p] = __float2half_rn(fmaxf(acc[p], 0.f));
}

// ===================== conv_v4 (pyramid, R14-proven) =====================
template <int TILE, int STRIDE, int CIN, int CICH, int COSPLIT, int OUTMODE>
__global__ __launch_bounds__(128) void conv_v4(
    const float* __restrict__ in, const float* __restrict__ w,
    const float* __restrict__ bias, float* __restrict__ outf,
    __half* __restrict__ outh,
    int Hin, int Win, int Hout, int Wout, int Cout, int pad)
{
    constexpr int SPANX = (TILE - 1) * STRIDE + 3;
    constexpr int COBLK = 128;
    constexpr int NCK = CIN / CICH;
    constexpr int ITOT1 = 3 * SPANX * CICH;
    extern __shared__ float sm[];
    float* smw = sm;
    float* smi = sm + CICH * COBLK;

    int tid = threadIdx.x;
    int l64 = tid & 63;
    int bt2 = tid >> 6;
    int xt = blockIdx.x / COSPLIT;
    int cs = blockIdx.x % COSPLIT;
    int oy = blockIdx.y;
    int bp = blockIdx.z;
    int coA = cs * COBLK + l64;
    int coB = coA + 64;
    int ox0 = xt * TILE;
    int iy0 = oy * STRIDE - pad;
    int ix0 = ox0 * STRIDE - pad;

    float acc0[TILE], acc1[TILE];
    float bv0 = bias[coA], bv1 = bias[coB];
#pragma unroll
    for (int p = 0; p < TILE; p++) { acc0[p] = bv0; acc1[p] = bv1; }

    for (int ck = 0; ck < NCK; ck++) {
        __syncthreads();
        for (int i = tid; i < 2 * ITOT1; i += 128) {
            int bt = i / ITOT1, j = i % ITOT1;
            int ci = j % CICH; int rest = j / CICH;
            int xx = rest % SPANX; int r = rest / SPANX;
            int iy = iy0 + r, ix = ix0 + xx;
            float v = 0.f;
            if (iy >= 0 && iy < Hin && ix >= 0 && ix < Win)
                v = in[(((size_t)(bp * 2 + bt) * Hin + iy) * Win + ix) * CIN + ck * CICH + ci];
            smi[bt * ITOT1 + (r * SPANX + xx) * CICH + ci] = v;
        }
        const float* smin = smi + bt2 * ITOT1;
#pragma unroll
        for (int r = 0; r < 3; r++)
#pragma unroll
            for (int kx = 0; kx < 3; kx++) {
                __syncthreads();
                const float* wsrc = w + ((size_t)((r * 3 + kx) * CIN + ck * CICH)) * Cout
                                      + cs * COBLK;
                for (int i = tid; i < CICH * COBLK / 4; i += 128) {
                    int ci = i / (COBLK / 4), c4 = i % (COBLK / 4);
                    ((float4*)smw)[ci * (COBLK / 4) + c4] =
                        *(const float4*)(wsrc + (size_t)ci * Cout + c4 * 4);
                }
                __syncthreads();
#pragma unroll 4
                for (int c4 = 0; c4 < CICH / 4; c4++) {
                    float4 iv[TILE];
#pragma unroll
                    for (int p = 0; p < TILE; p++)
                        iv[p] = *(const float4*)&smin[(r * SPANX + kx + p * STRIDE) * CICH + c4 * 4];
                    float w0[4], w1[4];
#pragma unroll
                    for (int q = 0; q < 4; q++) {
                        w0[q] = smw[(c4 * 4 + q) * COBLK + l64];
                        w1[q] = smw[(c4 * 4 + q) * COBLK + l64 + 64];
                    }
#pragma unroll
                    for (int p = 0; p < TILE; p++) {
                        acc0[p] += iv[p].x * w0[0] + iv[p].y * w0[1]
                                 + iv[p].z * w0[2] + iv[p].w * w0[3];
                        acc1[p] += iv[p].x * w1[0] + iv[p].y * w1[1]
                                 + iv[p].z * w1[2] + iv[p].w * w1[3];
                    }
                }
            }
    }

    int b = bp * 2 + bt2;
    if (OUTMODE == 0) {
#pragma unroll
        for (int p = 0; p < TILE; p++) {
            size_t base = (((size_t)b * Hout + oy) * Wout + ox0 + p) * Cout;
            outf[base + coA] = fmaxf(acc0[p], 0.f);
            outf[base + coB] = fmaxf(acc1[p], 0.f);
        }
    } else {
        __half* dA = outh + ((size_t)b * Cout + coA) * NN + oy * Wout + ox0;
        __half* dB = outh + ((size_t)b * Cout + coB) * NN + oy * Wout + ox0;
#pragma unroll
        for (int p = 0; p < TILE; p++) {
            dA[p] = __float2half_rn(fmaxf(acc0[p], 0.f));
            dB[p] = __float2half_rn(fmaxf(acc1[p], 0.f));
        }
    }
}

// ---------------- maxpool phase 1 ----------------
__global__ void maxpool_p1(const float* __restrict__ t, float* __restrict__ mpp) {
    int b = blockIdx.z;
    int ns = blockIdx.y;
    int c = blockIdx.x * 256 + threadIdx.x;
    if (c >= CF) return;
    const float* src = t + ((size_t)b * NN + ns * 128) * CF + c;
    float m = -1e30f;
#pragma unroll 8
    for (int n = 0; n < 128; n++) m = fmaxf(m, src[(size_t)n * CF]);
    mpp[((size_t)ns * NB + b) * CF + c] = m;
}

// ---------------- dense1 (fused maxpool reduce) ----------------
__global__ void dense1_p1(const float* __restrict__ mpp, const float* __restrict__ w,
                          float* __restrict__ d1p) {
    int ks = blockIdx.x;
    int b = blockIdx.y;
    int j = threadIdx.x;
    __shared__ float sm[248];
    for (int k = threadIdx.x; k < 248; k += 512) {
        int c = ks * 248 + k;
        float m = -1e30f;
#pragma unroll
        for (int ns = 0; ns < 8; ns++) m = fmaxf(m, mpp[((size_t)ns * NB + b) * CF + c]);
        sm[k] = m;
    }
    __syncthreads();
    float s = 0.f;
#pragma unroll 8
    for (int k = 0; k < 248; k++) s += sm[k] * w[(size_t)(ks * 248 + k) * 512 + j];
    d1p[((size_t)ks * NB + b) * 512 + j] = s;
}

// ---------------- dense2 + logits ----------------
__global__ void dense2_p1(const float* __restrict__ d1p, const float* __restrict__ b1,
                          const float* __restrict__ w, const float* __restrict__ bias,
                          float* __restrict__ logits) {
    int jb = blockIdx.x;
    int b = blockIdx.y;
    int j = jb * 128 + threadIdx.x;
    __shared__ float sg[512];
    for (int k = threadIdx.x; k < 512; k += 128) {
        float s = b1[k];
#pragma unroll
        for (int ks = 0; ks < 8; ks++) s += d1p[((size_t)ks * NB + b) * 512 + k];
        sg[k] = fmaxf(s, 0.f);
    }
    __syncthreads();
    if (j >= NCLS) return;
    float s = bias[j];
#pragma unroll 8
    for (int k = 0; k < 512; k++) s += sg[k] * w[(size_t)k * NCLS + j];
    logits[b * NCLS + j] = s;
}
__global__ void softmax1000(const float* __restrict__ logits, float* __restrict__ out) {
    int b = blockIdx.x;
    const float* src = logits + b * NCLS;
    int tid = threadIdx.x;
    __shared__ float red[256];
    float m = -1e30f;
    for (int j = tid; j < NCLS; j += 256) m = fmaxf(m, src[j]);
    red[tid] = m; __syncthreads();
    for (int s = 128; s > 0; s >>= 1) { if (tid < s) red[tid] = fmaxf(red[tid], red[tid + s]); __syncthreads(); }
    m = red[0]; __syncthreads();
    float ssum = 0.f;
    for (int j = tid; j < NCLS; j += 256) ssum += __expf(src[j] - m);
    red[tid] = ssum; __syncthreads();
    for (int s = 128; s > 0; s >>= 1) { if (tid < s) red[tid] += red[tid + s]; __syncthreads(); }
    float inv = 1.f / red[0];
    for (int j = tid; j < NCLS; j += 256) out[b * NCLS + j] = __expf(src[j] - m) * inv;
}

// ---------------- launcher ----------------
extern "C" void kernel_launch(void* const* d_in, const int* in_sizes, int n_in,
                              void* d_out, int out_size) {
    const float* t_lum  = (const float*)d_in[0];
    const float* r_lum  = (const float*)d_in[1];
    const float* r_ab   = (const float*)d_in[2];
    const float* w_rab1 = (const float*)d_in[3];
    const float* b_rab1 = (const float*)d_in[4];
    const float* w_rab2 = (const float*)d_in[5];
    const float* b_rab2 = (const float*)d_in[6];
    const float* w_fa1  = (const float*)d_in[7];
    const float* b_fa1  = (const float*)d_in[8];
    const float* w_fa2  = (const float*)d_in[9];
    const float* b_fa2  = (const float*)d_in[10];
    const float* w_fa3  = (const float*)d_in[11];
    const float* b_fa3  = (const float*)d_in[12];
    const float* w_d1   = (const float*)d_in[13];
    const float* b_d1   = (const float*)d_in[14];
    const float* w_d2   = (const float*)d_in[15];
    const float* b_d2   = (const float*)d_in[16];

    __half *tnh, *rnh, *Ahi, *fTh;
    float *frab1, *fa, *mpp, *d1p, *logits;
    cudaGetSymbolAddress((void**)&tnh,    g_tn_hi);
    cudaGetSymbolAddress((void**)&rnh,    g_rn_hi);
    cudaGetSymbolAddress((void**)&Ahi,    g_A_hi);
    cudaGetSymbolAddress((void**)&fTh,    g_frabT_hi);
    cudaGetSymbolAddress((void**)&frab1,  g_frab1);
    cudaGetSymbolAddress((void**)&fa,     g_fa);
    cudaGetSymbolAddress((void**)&mpp,    g_mpp);
    cudaGetSymbolAddress((void**)&d1p,    g_d1p);
    cudaGetSymbolAddress((void**)&logits, g_logits);

    cudaFuncSetAttribute(gemm_nt_mma, cudaFuncAttributeMaxDynamicSharedMemorySize, GEMM_SMEM);
    cudaFuncSetAttribute(gemm_nt_mma, cudaFuncAttributePreferredSharedMemoryCarveout, 100);
    cudaFuncSetAttribute(gemm_nn_mma, cudaFuncAttributeMaxDynamicSharedMemorySize, GEMM2_SMEM);

    const int SM_FA12 = (64 * 128 + 2 * 3 * 9 * 64) * 4;
    const int SM_FA3  = (64 * 128 + 2 * 3 * 5 * 64) * 4;
    cudaFuncSetAttribute((void*)conv_v4<4, 2, 128, 64, 1, 0>,
                         cudaFuncAttributeMaxDynamicSharedMemorySize, SM_FA12);
    cudaFuncSetAttribute((void*)conv_v4<4, 2, 128, 64, 2, 0>,
                         cudaFuncAttributeMaxDynamicSharedMemorySize, SM_FA12);
    cudaFuncSetAttribute((void*)conv_v4<2, 2, 256, 64, 4, 0>,
                         cudaFuncAttributeMaxDynamicSharedMemorySize, SM_FA3);

    float* out  = (float*)d_out;
    float* Cmat = out + 8000;
    float* s1   = out + 8396608;
    float* s2   = out + 8462144;
    float* s3   = out + 8593216;

    // 1,2: normalize -> fp16
    normalize_h<<<NB * NN, 256>>>(r_lum, rnh);
    normalize_h<<<NB * NN, 256>>>(t_lum, tnh);

    // 3: chroma conv1
    conv2d_relu_t<16, 1, 2><<<dim3(4, 64, NB), 64, 3 * 18 * 2 * 4>>>(
        r_ab, w_rab1, b_rab1, frab1, 64, 64, 64, 64, 64, 1);

    // 4: conv2 (float4 smem reads)  <- PROFILE SLOT
    conv2_t_fp16<<<dim3(4, 32, NB), 128, 3 * 17 * 64 * 4>>>(
        frab1, w_rab2, b_rab2, fTh);

    // 5: cost volume (single-term fp16, KCH=64)
    gemm_nt_mma<<<dim3(8, 8, NB), 256, GEMM_SMEM>>>(tnh, rnh, Cmat);

    // 6: softmax -> fp16
    softmax_h<<<NB * NN, 256>>>(Cmat, Ahi);

    // 7: attention
    gemm_nn_mma<<<dim3(NN / 64, NB), 256, GEMM2_SMEM>>>(Ahi, fTh, fa);

    // 8-10: pyramid
    conv_v4<4, 2, 128, 64, 1, 0><<<dim3(4, 16, 4), 128, SM_FA12>>>(
        fa, w_fa1, b_fa1, s3, nullptr, 32, 32, 16, 16, 128, 0);
    conv_v4<4, 2, 128, 64, 2, 0><<<dim3(4, 8, 4), 128, SM_FA12>>>(
        s3, w_fa2, b_fa2, s2, nullptr, 16, 16, 8, 8, 256, 0);
    conv_v4<2, 2, 256, 64, 4, 0><<<dim3(8, 4, 4), 128, SM_FA3>>>(
        s2, w_fa3, b_fa3, s1, nullptr, 8, 8, 4, 4, 512, 0);

    // 11: maxpool phase 1
    maxpool_p1<<<dim3(8, 8, NB), 256>>>(t_lum, mpp);

    // 12-14: classifier head
    dense1_p1<<<dim3(8, NB), 512>>>(mpp, w_d1, d1p);
    dense2_p1<<<dim3(8, NB), 128>>>(d1p, b_d1, w_d2, b_d2, logits);
    softmax1000<<<NB, 256>>>(logits, out);
}

// round 17
// speedup vs baseline: 1.7791x; 1.0109x over previous
#include <cuda_runtime.h>
#include <cuda_fp16.h>
#include <math.h>
#include <stdint.h>

#define CF   1984
#define NB   8
#define NN   1024    // h*w = 32*32
#define NCLS 1000

// ---------------- scratch (static device globals; no allocation) ----------------
__device__ __half g_tn_hi[NB * NN * CF];
__device__ __half g_rn_hi[NB * NN * CF];
__device__ __half g_A_hi[NB * NN * NN];
__device__ __half g_frabT_hi[NB * 128 * NN];
__device__ float g_frab1[NB * 64 * 64 * 64];
__device__ float g_fa[NB * NN * 128];
__device__ float g_mpp[8 * NB * CF];
__device__ float g_d1p[8 * NB * 512];
__device__ float g_logits[NB * NCLS];

// ============================ helpers ============================
__device__ __forceinline__ uint32_t smem_u32(const void* p) {
    uint32_t a;
    asm("{ .reg .u64 t; cvta.to.shared.u64 t, %1; cvt.u32.u64 %0, t; }" : "=r"(a) : "l"(p));
    return a;
}
__device__ __forceinline__ void cp_async16(uint32_t dst, const void* src) {
    asm volatile("cp.async.cg.shared.global [%0], [%1], 16;" :: "r"(dst), "l"(src));
}
#define CP_COMMIT() asm volatile("cp.async.commit_group;" ::: "memory")
#define CP_WAIT(n)  asm volatile("cp.async.wait_group %0;" :: "n"(n) : "memory")

__device__ __forceinline__ void ldsm_x4(uint32_t* r, uint32_t addr) {
    asm volatile("ldmatrix.sync.aligned.m8n8.x4.shared.b16 {%0,%1,%2,%3}, [%4];"
                 : "=r"(r[0]), "=r"(r[1]), "=r"(r[2]), "=r"(r[3]) : "r"(addr));
}
__device__ __forceinline__ void mma16816(float* d, const uint32_t* a, const uint32_t* b) {
    asm volatile(
        "mma.sync.aligned.m16n8k16.row.col.f32.f16.f16.f32 "
        "{%0,%1,%2,%3}, {%4,%5,%6,%7}, {%8,%9}, {%0,%1,%2,%3};"
        : "+f"(d[0]), "+f"(d[1]), "+f"(d[2]), "+f"(d[3])
        : "r"(a[0]), "r"(a[1]), "r"(a[2]), "r"(a[3]), "r"(b[0]), "r"(b[1]));
}

// ---------------- normalize -> fp16 ----------------
__global__ void normalize_h(const float* __restrict__ in, __half* __restrict__ hi) {
    int row = blockIdx.x;
    const float4* src4 = (const float4*)(in + (size_t)row * CF);
    __half* dh = hi + (size_t)row * CF;
    int tid = threadIdx.x;
    float4 v[2];
    float ss = 0.f;
#pragma unroll
    for (int i = 0; i < 2; i++) {
        int c4 = tid + i * 256;
        if (c4 < 496) {
            v[i] = src4[c4];
            ss += v[i].x * v[i].x + v[i].y * v[i].y + v[i].z * v[i].z + v[i].w * v[i].w;
        } else v[i] = make_float4(0.f, 0.f, 0.f, 0.f);
    }
    __shared__ float red[256];
    red[tid] = ss; __syncthreads();
    for (int s = 128; s > 0; s >>= 1) {
        if (tid < s) red[tid] += red[tid + s];
        __syncthreads();
    }
    float inv = 1.f / (sqrtf(red[0]) + 1e-6f);
#pragma unroll
    for (int i = 0; i < 2; i++) {
        int c4 = tid + i * 256;
        if (c4 < 496) {
            __half2 hh[2] = {
                __halves2half2(__float2half_rn(v[i].x * inv), __float2half_rn(v[i].y * inv)),
                __halves2half2(__float2half_rn(v[i].z * inv), __float2half_rn(v[i].w * inv)) };
            *(uint2*)(dh + c4 * 4) = *(uint2*)hh;
        }
    }
}

// =====================================================================
// gemm_nt_mma: C = Ah*Bh^T  (fp16), KCH=64, PIPE=3, 2 CTAs/SM
// =====================================================================
#define KCHN   64
#define NCHN   (CF / KCHN)       // 31
#define RSTN   144
#define TILEB_N (128 * RSTN)     // 18432
#define STGB_N  (2 * TILEB_N)    // 36864
#define PIPE3  3
#define GEMM_SMEM (PIPE3 * STGB_N)   // 110592

__global__ __launch_bounds__(256, 2) void gemm_nt_mma(
    const __half* __restrict__ Ahi, const __half* __restrict__ Bhi,
    float* __restrict__ Cg)
{
    extern __shared__ __align__(128) char smem[];
    uint32_t sbase = smem_u32(smem);
    int tid = threadIdx.x;
    int wid = tid >> 5, lane = tid & 31;
    int warp_m = wid & 1;
    int warp_n = wid >> 1;

    int b = blockIdx.z;
    int row0 = blockIdx.y * 128;
    int col0 = blockIdx.x * 128;

    const __half* srcs[2] = {
        Ahi + ((size_t)b * NN + row0) * CF,
        Bhi + ((size_t)b * NN + col0) * CF };
    float* C = Cg + (size_t)b * NN * NN;

    float acc[4][4][4];
#pragma unroll
    for (int i = 0; i < 4; i++)
#pragma unroll
        for (int j = 0; j < 4; j++)
#pragma unroll
            for (int k = 0; k < 4; k++) acc[i][j][k] = 0.f;

    auto prefetch = [&](int c) {
        int kk = c * KCHN;
        uint32_t stg = sbase + (c % PIPE3) * STGB_N;
#pragma unroll
        for (int it = 0; it < 8; it++) {
            int idx = it * 256 + tid;
            int t = idx >> 10;
            int w = idx & 1023;
            int r = w >> 3, seg = w & 7;
            cp_async16(stg + (uint32_t)(t * TILEB_N + r * RSTN + seg * 16),
                       srcs[t] + (size_t)r * CF + kk + seg * 8);
        }
    };

    prefetch(0); CP_COMMIT();
    prefetch(1); CP_COMMIT();

    int a_row = (lane & 7) + ((lane >> 3) & 1) * 8;
    int a_k8  = (lane >> 4) * 8;
    int bg    = lane >> 3;
    int b_nat = bg >> 1;
    int b_k8  = (bg & 1) * 8;

    for (int c = 0; c < NCHN; c++) {
        CP_WAIT(1);
        __syncthreads();
        if (c + 2 < NCHN) { prefetch(c + 2); CP_COMMIT(); }

        uint32_t stg = sbase + (c % PIPE3) * STGB_N;
        uint32_t sAh = stg, sBh = stg + TILEB_N;
#pragma unroll
        for (int k16 = 0; k16 < 4; k16++) {
            int kb = k16 * 16;
            uint32_t afh[4][4];
#pragma unroll
            for (int am = 0; am < 4; am++) {
                uint32_t off = (uint32_t)((warp_m * 64 + am * 16 + a_row) * RSTN + (kb + a_k8) * 2);
                ldsm_x4(afh[am], sAh + off);
            }
            uint32_t bfh[4][2];
#pragma unroll
            for (int bp = 0; bp < 2; bp++) {
                uint32_t boff = (uint32_t)((warp_n * 32 + (bp * 2 + b_nat) * 8 + (lane & 7)) * RSTN
                                           + (kb + b_k8) * 2);
                uint32_t r4[4];
                ldsm_x4(r4, sBh + boff);
                bfh[bp * 2 + 0][0] = r4[0]; bfh[bp * 2 + 0][1] = r4[1];
                bfh[bp * 2 + 1][0] = r4[2]; bfh[bp * 2 + 1][1] = r4[3];
            }
#pragma unroll
            for (int am = 0; am < 4; am++)
#pragma unroll
                for (int an = 0; an < 4; an++)
                    mma16816(acc[am][an], afh[am], bfh[an]);
        }
    }

    int tr = lane >> 2, tc = (lane & 3) * 2;
#pragma unroll
    for (int am = 0; am < 4; am++)
#pragma unroll
        for (int an = 0; an < 4; an++) {
            int r = row0 + warp_m * 64 + am * 16 + tr;
            int cc = col0 + warp_n * 32 + an * 8 + tc;
            *(float2*)(C + (size_t)r * NN + cc) = make_float2(acc[am][an][0], acc[am][an][1]);
            *(float2*)(C + (size_t)(r + 8) * NN + cc) = make_float2(acc[am][an][2], acc[am][an][3]);
        }
}

// ---------------- row softmax -> fp16 ----------------
__global__ void softmax_h(const float* __restrict__ Cmat, __half* __restrict__ Ahi) {
    int row = blockIdx.x;
    const float* src = Cmat + (size_t)row * NN;
    __half* dh = Ahi + (size_t)row * NN;
    int tid = threadIdx.x;
    float2 v[2];
    float m = -1e30f;
#pragma unroll
    for (int i = 0; i < 2; i++) {
        int c2 = (tid + i * 256) * 2;
        v[i] = *(const float2*)(src + c2);
        m = fmaxf(m, fmaxf(v[i].x, v[i].y));
    }
    __shared__ float red[256];
    red[tid] = m; __syncthreads();
    for (int s = 128; s > 0; s >>= 1) { if (tid < s) red[tid] = fmaxf(red[tid], red[tid + s]); __syncthreads(); }
    m = red[0]; __syncthreads();
    float ssum = 0.f;
#pragma unroll
    for (int i = 0; i < 2; i++) {
        v[i].x = __expf(v[i].x - m); v[i].y = __expf(v[i].y - m);
        ssum += v[i].x + v[i].y;
    }
    red[tid] = ssum; __syncthreads();
    for (int s = 128; s > 0; s >>= 1) { if (tid < s) red[tid] += red[tid + s]; __syncthreads(); }
    float inv = 1.f / red[0];
#pragma unroll
    for (int i = 0; i < 2; i++) {
        int c2 = (tid + i * 256) * 2;
        *(__half2*)(dh + c2) = __halves2half2(
            __float2half_rn(v[i].x * inv), __float2half_rn(v[i].y * inv));
    }
}

// =====================================================================
// gemm_nn_mma: f_a = Ah @ Bh^T  — KCH=64, PIPE=3, single-sync, 2 CTAs/SM
// CTA 64 rows x 128 cols; 8 warps (32x32 warp tile)
// =====================================================================
#define NKCH2  (NN / KCHN)               // 16
#define A2_BYTES (64 * RSTN)             // 9216
#define B2_BYTES (128 * RSTN)            // 18432
#define STG2_BYTES (A2_BYTES + B2_BYTES) // 27648
#define GEMM2_SMEM (PIPE3 * STG2_BYTES)  // 82944

__global__ __launch_bounds__(256, 2) void gemm_nn_mma(
    const __half* __restrict__ Ahi, const __half* __restrict__ Bhi,
    float* __restrict__ Fg)
{
    extern __shared__ __align__(128) char smem[];
    uint32_t sbase = smem_u32(smem);
    int tid = threadIdx.x;
    int wid = tid >> 5, lane = tid & 31;
    int warp_m = wid & 1;
    int warp_n = wid >> 1;

    int b = blockIdx.y;
    int mrow0 = blockIdx.x * 64;

    const __half* Ah = Ahi + ((size_t)b * NN + mrow0) * NN;
    const __half* Bh = Bhi + (size_t)b * 128 * NN;
    float* F = Fg + (size_t)b * NN * 128;

    float acc[2][4][4];
#pragma unroll
    for (int i = 0; i < 2; i++)
#pragma unroll
        for (int j = 0; j < 4; j++)
#pragma unroll
            for (int k = 0; k < 4; k++) acc[i][j][k] = 0.f;

    auto prefetch = [&](int c) {
        int kk = c * KCHN;
        uint32_t stg = sbase + (c % PIPE3) * STG2_BYTES;
#pragma unroll
        for (int it = 0; it < 6; it++) {
            int idx = it * 256 + tid;          // 0..1535
            if (idx < 512) {                   // A: 64 rows x 8 segs
                int r = idx >> 3, seg = idx & 7;
                cp_async16(stg + (uint32_t)(r * RSTN + seg * 16),
                           Ah + (size_t)r * NN + kk + seg * 8);
            } else {                           // B: 128 rows x 8 segs
                int w = idx - 512;
                int r = w >> 3, seg = w & 7;
                cp_async16(stg + (uint32_t)(A2_BYTES + r * RSTN + seg * 16),
                           Bh + (size_t)r * NN + kk + seg * 8);
            }
        }
    };

    prefetch(0); CP_COMMIT();
    prefetch(1); CP_COMMIT();

    int a_row = (lane & 7) + ((lane >> 3) & 1) * 8;
    int a_k8  = (lane >> 4) * 8;
    int bg    = lane >> 3;
    int b_nat = bg >> 1;
    int b_k8  = (bg & 1) * 8;

    for (int c = 0; c < NKCH2; c++) {
        CP_WAIT(1);
        __syncthreads();
        if (c + 2 < NKCH2) { prefetch(c + 2); CP_COMMIT(); }

        uint32_t stg = sbase + (c % PIPE3) * STG2_BYTES;
        uint32_t sAh = stg, sBh = stg + A2_BYTES;
#pragma unroll
        for (int k16 = 0; k16 < 4; k16++) {
            int kb = k16 * 16;
            uint32_t afh[2][4];
#pragma unroll
            for (int am = 0; am < 2; am++) {
                uint32_t off = (uint32_t)((warp_m * 32 + am * 16 + a_row) * RSTN + (kb + a_k8) * 2);
                ldsm_x4(afh[am], sAh + off);
            }
            uint32_t bfh[4][2];
#pragma unroll
            for (int bp = 0; bp < 2; bp++) {
                uint32_t boff = (uint32_t)((warp_n * 32 + (bp * 2 + b_nat) * 8 + (lane & 7)) * RSTN
                                           + (kb + b_k8) * 2);
                uint32_t r4[4];
                ldsm_x4(r4, sBh + boff);
                bfh[bp * 2 + 0][0] = r4[0]; bfh[bp * 2 + 0][1] = r4[1];
                bfh[bp * 2 + 1][0] = r4[2]; bfh[bp * 2 + 1][1] = r4[3];
            }
#pragma unroll
            for (int am = 0; am < 2; am++)
#pragma unroll
                for (int an = 0; an < 4; an++)
                    mma16816(acc[am][an], afh[am], bfh[an]);
        }
    }

    int tr = lane >> 2, tc = (lane & 3) * 2;
#pragma unroll
    for (int am = 0; am < 2; am++)
#pragma unroll
        for (int an = 0; an < 4; an++) {
            int r = mrow0 + warp_m * 32 + am * 16 + tr;
            int cc = warp_n * 32 + an * 8 + tc;
            *(float2*)(F + (size_t)r * 128 + cc) = make_float2(acc[am][an][0], acc[am][an][1]);
            *(float2*)(F + (size_t)(r + 8) * 128 + cc) = make_float2(acc[am][an][2], acc[am][an][3]);
        }
}

// ------- conv1: Cin=2 (cheap) -------
template <int TILE, int STRIDE, int CIN>
__global__ void conv2d_relu_t(
    const float* __restrict__ in, const float* __restrict__ w,
    const float* __restrict__ bias, float* __restrict__ out,
    int Hin, int Win, int Hout, int Wout, int Cout, int pad)
{
    constexpr int SPANX = (TILE - 1) * STRIDE + 3;
    extern __shared__ float sm[];
    int b = blockIdx.z;
    int oy = blockIdx.y;
    int ox0 = blockIdx.x * TILE;
    int co = threadIdx.x;

    int iy0 = oy * STRIDE - pad;
    int ix0 = ox0 * STRIDE - pad;
    constexpr int TOT = 3 * SPANX * CIN;
    for (int i = threadIdx.x; i < TOT; i += blockDim.x) {
        int ci = i % CIN; int rest = i / CIN;
        int xx = rest % SPANX; int r = rest / SPANX;
        int iy = iy0 + r, ix = ix0 + xx;
        float v = 0.f;
        if (iy >= 0 && iy < Hin && ix >= 0 && ix < Win)
            v = in[(((size_t)b * Hin + iy) * Win + ix) * CIN + ci];
        sm[(r * SPANX + xx) * CIN + ci] = v;
    }
    __syncthreads();

    float acc[TILE];
    float bv = bias[co];
#pragma unroll
    for (int p = 0; p < TILE; p++) acc[p] = bv;

#pragma unroll
    for (int r = 0; r < 3; r++)
#pragma unroll
        for (int kx = 0; kx < 3; kx++) {
#pragma unroll
            for (int ci = 0; ci < CIN; ci++) {
                float wv = w[(size_t)((r * 3 + kx) * CIN + ci) * Cout + co];
                const float* srow = &sm[(r * SPANX + kx) * CIN + ci];
#pragma unroll
                for (int p = 0; p < TILE; p++)
                    acc[p] += srow[(size_t)p * STRIDE * CIN] * wv;
            }
        }
#pragma unroll
    for (int p = 0; p < TILE; p++) {
        int ox = ox0 + p;
        out[(((size_t)b * Hout + oy) * Wout + ox) * Cout + co] = fmaxf(acc[p], 0.f);
    }
}

// ---- conv2: exact R8 config (proven 81us) ----
__global__ void conv2_t_fp16(
    const float* __restrict__ in, const float* __restrict__ w,
    const float* __restrict__ bias, __half* __restrict__ out_hi)
{
    constexpr int TILE = 8, STRIDE = 2, SPANX = 17, CIN = 64, COUT = 128;
    extern __shared__ float sm[];
    int b = blockIdx.z;
    int oy = blockIdx.y;
    int ox0 = blockIdx.x * TILE;
    int co = threadIdx.x;

    int iy0 = oy * STRIDE;
    int ix0 = ox0 * STRIDE;
    constexpr int TOT = 3 * SPANX * CIN;
    for (int i = threadIdx.x; i < TOT; i += COUT) {
        int ci = i % CIN; int rest = i / CIN;
        int xx = rest % SPANX; int r = rest / SPANX;
        int iy = iy0 + r, ix = ix0 + xx;
        float v = 0.f;
        if (iy < 64 && ix < 64)
            v = in[(((size_t)b * 64 + iy) * 64 + ix) * CIN + ci];
        sm[(r * SPANX + xx) * CIN + ci] = v;
    }
    __syncthreads();

    float acc[TILE];
    float bv = bias[co];
#pragma unroll
    for (int p = 0; p < TILE; p++) acc[p] = bv;

#pragma unroll
    for (int r = 0; r < 3; r++)
#pragma unroll
        for (int kx = 0; kx < 3; kx++) {
#pragma unroll 8
            for (int ci = 0; ci < CIN; ci++) {
                float wv = w[(size_t)((r * 3 + kx) * CIN + ci) * COUT + co];
                const float* srow = &sm[(r * SPANX + kx) * CIN + ci];
#pragma unroll
                for (int p = 0; p < TILE; p++)
                    acc[p] += srow[(size_t)p * STRIDE * CIN] * wv;
            }
        }
    __half* dh = out_hi + ((size_t)b * COUT + co) * NN + oy * 32 + ox0;
#pragma unroll
    for (int p = 0; p < TILE; p++)
        dh[p] = __float2half_rn(fmaxf(acc[p], 0.f));
}

// ===================== conv_v4 (pyramid, R14-proven) =====================
template <int TILE, int STRIDE, int CIN, int CICH, int COSPLIT, int OUTMODE>
__global__ __launch_bounds__(128) void conv_v4(
    const float* __restrict__ in, const float* __restrict__ w,
    const float* __restrict__ bias, float* __restrict__ outf,
    __half* __restrict__ outh,
    int Hin, int Win, int Hout, int Wout, int Cout, int pad)
{
    constexpr int SPANX = (TILE - 1) * STRIDE + 3;
    constexpr int COBLK = 128;
    constexpr int NCK = CIN / CICH;
    constexpr int ITOT1 = 3 * SPANX * CICH;
    extern __shared__ float sm[];
    float* smw = sm;
    float* smi = sm + CICH * COBLK;

    int tid = threadIdx.x;
    int l64 = tid & 63;
    int bt2 = tid >> 6;
    int xt = blockIdx.x / COSPLIT;
    int cs = blockIdx.x % COSPLIT;
    int oy = blockIdx.y;
    int bp = blockIdx.z;
    int coA = cs * COBLK + l64;
    int coB = coA + 64;
    int ox0 = xt * TILE;
    int iy0 = oy * STRIDE - pad;
    int ix0 = ox0 * STRIDE - pad;

    float acc0[TILE], acc1[TILE];
    float bv0 = bias[coA], bv1 = bias[coB];
#pragma unroll
    for (int p = 0; p < TILE; p++) { acc0[p] = bv0; acc1[p] = bv1; }

    for (int ck = 0; ck < NCK; ck++) {
        __syncthreads();
        for (int i = tid; i < 2 * ITOT1; i += 128) {
            int bt = i / ITOT1, j = i % ITOT1;
            int ci = j % CICH; int rest = j / CICH;
            int xx = rest % SPANX; int r = rest / SPANX;
            int iy = iy0 + r, ix = ix0 + xx;
            float v = 0.f;
            if (iy >= 0 && iy < Hin && ix >= 0 && ix < Win)
                v = in[(((size_t)(bp * 2 + bt) * Hin + iy) * Win + ix) * CIN + ck * CICH + ci];
            smi[bt * ITOT1 + (r * SPANX + xx) * CICH + ci] = v;
        }
        const float* smin = smi + bt2 * ITOT1;
#pragma unroll
        for (int r = 0; r < 3; r++)
#pragma unroll
            for (int kx = 0; kx < 3; kx++) {
                __syncthreads();
                const float* wsrc = w + ((size_t)((r * 3 + kx) * CIN + ck * CICH)) * Cout
                                      + cs * COBLK;
                for (int i = tid; i < CICH * COBLK / 4; i += 128) {
                    int ci = i / (COBLK / 4), c4 = i % (COBLK / 4);
                    ((float4*)smw)[ci * (COBLK / 4) + c4] =
                        *(const float4*)(wsrc + (size_t)ci * Cout + c4 * 4);
                }
                __syncthreads();
#pragma unroll 4
                for (int c4 = 0; c4 < CICH / 4; c4++) {
                    float4 iv[TILE];
#pragma unroll
                    for (int p = 0; p < TILE; p++)
                        iv[p] = *(const float4*)&smin[(r * SPANX + kx + p * STRIDE) * CICH + c4 * 4];
                    float w0[4], w1[4];
#pragma unroll
                    for (int q = 0; q < 4; q++) {
                        w0[q] = smw[(c4 * 4 + q) * COBLK + l64];
                        w1[q] = smw[(c4 * 4 + q) * COBLK + l64 + 64];
                    }
#pragma unroll
                    for (int p = 0; p < TILE; p++) {
                        acc0[p] += iv[p].x * w0[0] + iv[p].y * w0[1]
                                 + iv[p].z * w0[2] + iv[p].w * w0[3];
                        acc1[p] += iv[p].x * w1[0] + iv[p].y * w1[1]
                                 + iv[p].z * w1[2] + iv[p].w * w1[3];
                    }
                }
            }
    }

    int b = bp * 2 + bt2;
    if (OUTMODE == 0) {
#pragma unroll
        for (int p = 0; p < TILE; p++) {
            size_t base = (((size_t)b * Hout + oy) * Wout + ox0 + p) * Cout;
            outf[base + coA] = fmaxf(acc0[p], 0.f);
            outf[base + coB] = fmaxf(acc1[p], 0.f);
        }
    } else {
        __half* dA = outh + ((size_t)b * Cout + coA) * NN + oy * Wout + ox0;
        __half* dB = outh + ((size_t)b * Cout + coB) * NN + oy * Wout + ox0;
#pragma unroll
        for (int p = 0; p < TILE; p++) {
            dA[p] = __float2half_rn(fmaxf(acc0[p], 0.f));
            dB[p] = __float2half_rn(fmaxf(acc1[p], 0.f));
        }
    }
}

// ---------------- maxpool phase 1 ----------------
__global__ void maxpool_p1(const float* __restrict__ t, float* __restrict__ mpp) {
    int b = blockIdx.z;
    int ns = blockIdx.y;
    int c = blockIdx.x * 256 + threadIdx.x;
    if (c >= CF) return;
    const float* src = t + ((size_t)b * NN + ns * 128) * CF + c;
    float m = -1e30f;
#pragma unroll 8
    for (int n = 0; n < 128; n++) m = fmaxf(m, src[(size_t)n * CF]);
    mpp[((size_t)ns * NB + b) * CF + c] = m;
}

// ---------------- dense1 (fused maxpool reduce) ----------------
__global__ void dense1_p1(const float* __restrict__ mpp, const float* __restrict__ w,
                          float* __restrict__ d1p) {
    int ks = blockIdx.x;
    int b = blockIdx.y;
    int j = threadIdx.x;
    __shared__ float sm[248];
    for (int k = threadIdx.x; k < 248; k += 512) {
        int c = ks * 248 + k;
        float m = -1e30f;
#pragma unroll
        for (int ns = 0; ns < 8; ns++) m = fmaxf(m, mpp[((size_t)ns * NB + b) * CF + c]);
        sm[k] = m;
    }
    __syncthreads();
    float s = 0.f;
#pragma unroll 8
    for (int k = 0; k < 248; k++) s += sm[k] * w[(size_t)(ks * 248 + k) * 512 + j];
    d1p[((size_t)ks * NB + b) * 512 + j] = s;
}

// ---------------- dense2 + logits ----------------
__global__ void dense2_p1(const float* __restrict__ d1p, const float* __restrict__ b1,
                          const float* __restrict__ w, const float* __restrict__ bias,
                          float* __restrict__ logits) {
    int jb = blockIdx.x;
    int b = blockIdx.y;
    int j = jb * 128 + threadIdx.x;
    __shared__ float sg[512];
    for (int k = threadIdx.x; k < 512; k += 128) {
        float s = b1[k];
#pragma unroll
        for (int ks = 0; ks < 8; ks++) s += d1p[((size_t)ks * NB + b) * 512 + k];
        sg[k] = fmaxf(s, 0.f);
    }
    __syncthreads();
    if (j >= NCLS) return;
    float s = bias[j];
#pragma unroll 8
    for (int k = 0; k < 512; k++) s += sg[k] * w[(size_t)k * NCLS + j];
    logits[b * NCLS + j] = s;
}
__global__ void softmax1000(const float* __restrict__ logits, float* __restrict__ out) {
    int b = blockIdx.x;
    const float* src = logits + b * NCLS;
    int tid = threadIdx.x;
    __shared__ float red[256];
    float m = -1e30f;
    for (int j = tid; j < NCLS; j += 256) m = fmaxf(m, src[j]);
    red[tid] = m; __syncthreads();
    for (int s = 128; s > 0; s >>= 1) { if (tid < s) red[tid] = fmaxf(red[tid], red[tid + s]); __syncthreads(); }
    m = red[0]; __syncthreads();
    float ssum = 0.f;
    for (int j = tid; j < NCLS; j += 256) ssum += __expf(src[j] - m);
    red[tid] = ssum; __syncthreads();
    for (int s = 128; s > 0; s >>= 1) { if (tid < s) red[tid] += red[tid + s]; __syncthreads(); }
    float inv = 1.f / red[0];
    for (int j = tid; j < NCLS; j += 256) out[b * NCLS + j] = __expf(src[j] - m) * inv;
}

// ---------------- launcher ----------------
extern "C" void kernel_launch(void* const* d_in, const int* in_sizes, int n_in,
                              void* d_out, int out_size) {
    const float* t_lum  = (const float*)d_in[0];
    const float* r_lum  = (const float*)d_in[1];
    const float* r_ab   = (const float*)d_in[2];
    const float* w_rab1 = (const float*)d_in[3];
    const float* b_rab1 = (const float*)d_in[4];
    const float* w_rab2 = (const float*)d_in[5];
    const float* b_rab2 = (const float*)d_in[6];
    const float* w_fa1  = (const float*)d_in[7];
    const float* b_fa1  = (const float*)d_in[8];
    const float* w_fa2  = (const float*)d_in[9];
    const float* b_fa2  = (const float*)d_in[10];
    const float* w_fa3  = (const float*)d_in[11];
    const float* b_fa3  = (const float*)d_in[12];
    const float* w_d1   = (const float*)d_in[13];
    const float* b_d1   = (const float*)d_in[14];
    const float* w_d2   = (const float*)d_in[15];
    const float* b_d2   = (const float*)d_in[16];

    __half *tnh, *rnh, *Ahi, *fTh;
    float *frab1, *fa, *mpp, *d1p, *logits;
    cudaGetSymbolAddress((void**)&tnh,    g_tn_hi);
    cudaGetSymbolAddress((void**)&rnh,    g_rn_hi);
    cudaGetSymbolAddress((void**)&Ahi,    g_A_hi);
    cudaGetSymbolAddress((void**)&fTh,    g_frabT_hi);
    cudaGetSymbolAddress((void**)&frab1,  g_frab1);
    cudaGetSymbolAddress((void**)&fa,     g_fa);
    cudaGetSymbolAddress((void**)&mpp,    g_mpp);
    cudaGetSymbolAddress((void**)&d1p,    g_d1p);
    cudaGetSymbolAddress((void**)&logits, g_logits);

    cudaFuncSetAttribute(gemm_nt_mma, cudaFuncAttributeMaxDynamicSharedMemorySize, GEMM_SMEM);
    cudaFuncSetAttribute(gemm_nt_mma, cudaFuncAttributePreferredSharedMemoryCarveout, 100);
    cudaFuncSetAttribute(gemm_nn_mma, cudaFuncAttributeMaxDynamicSharedMemorySize, GEMM2_SMEM);
    cudaFuncSetAttribute(gemm_nn_mma, cudaFuncAttributePreferredSharedMemoryCarveout, 100);

    const int SM_FA12 = (64 * 128 + 2 * 3 * 9 * 64) * 4;
    const int SM_FA3  = (64 * 128 + 2 * 3 * 5 * 64) * 4;
    cudaFuncSetAttribute((void*)conv_v4<4, 2, 128, 64, 1, 0>,
                         cudaFuncAttributeMaxDynamicSharedMemorySize, SM_FA12);
    cudaFuncSetAttribute((void*)conv_v4<4, 2, 128, 64, 2, 0>,
                         cudaFuncAttributeMaxDynamicSharedMemorySize, SM_FA12);
    cudaFuncSetAttribute((void*)conv_v4<2, 2, 256, 64, 4, 0>,
                         cudaFuncAttributeMaxDynamicSharedMemorySize, SM_FA3);

    float* out  = (float*)d_out;
    float* Cmat = out + 8000;
    float* s1   = out + 8396608;
    float* s2   = out + 8462144;
    float* s3   = out + 8593216;

    // 1,2: normalize -> fp16
    normalize_h<<<NB * NN, 256>>>(r_lum, rnh);
    normalize_h<<<NB * NN, 256>>>(t_lum, tnh);

    // 3: chroma conv1
    conv2d_relu_t<16, 1, 2><<<dim3(4, 64, NB), 64, 3 * 18 * 2 * 4>>>(
        r_ab, w_rab1, b_rab1, frab1, 64, 64, 64, 64, 64, 1);

    // 4: cost volume (KCH=64)  <- PROFILE SLOT
    gemm_nt_mma<<<dim3(8, 8, NB), 256, GEMM_SMEM>>>(tnh, rnh, Cmat);

    // 5: conv2 (R8-proven)
    conv2_t_fp16<<<dim3(4, 32, NB), 128, 3 * 17 * 64 * 4>>>(
        frab1, w_rab2, b_rab2, fTh);

    // 6: softmax -> fp16
    softmax_h<<<NB * NN, 256>>>(Cmat, Ahi);

    // 7: attention (KCH=64, single-sync, 2 CTA/SM)
    gemm_nn_mma<<<dim3(NN / 64, NB), 256, GEMM2_SMEM>>>(Ahi, fTh, fa);

    // 8-10: pyramid
    conv_v4<4, 2, 128, 64, 1, 0><<<dim3(4, 16, 4), 128, SM_FA12>>>(
        fa, w_fa1, b_fa1, s3, nullptr, 32, 32, 16, 16, 128, 0);
    conv_v4<4, 2, 128, 64, 2, 0><<<dim3(4, 8, 4), 128, SM_FA12>>>(
        s3, w_fa2, b_fa2, s2, nullptr, 16, 16, 8, 8, 256, 0);
    conv_v4<2, 2, 256, 64, 4, 0><<<dim3(8, 4, 4), 128, SM_FA3>>>(
        s2, w_fa3, b_fa3, s1, nullptr, 8, 8, 4, 4, 512, 0);

    // 11: maxpool phase 1
    maxpool_p1<<<dim3(8, 8, NB), 256>>>(t_lum, mpp);

    // 12-14: classifier head
    dense1_p1<<<dim3(8, NB), 512>>>(mpp, w_d1, d1p);
    dense2_p1<<<dim3(8, NB), 128>>>(d1p, b_d1, w_d2, b_d2, logits);
    softmax1000<<<NB, 256>>>(logits, out);
}